// round 1
// baseline (speedup 1.0000x reference)
#include <cuda_runtime.h>

// ---------------------------------------------------------------------------
// DSRAModel forward: embed+causal-context -> QKV -> chunked linear attention
// with delta-rule recurrent state -> Wo -> LayerNorm -> vocab projection.
// Round 1: fp32 SIMT baseline, one tiled-GEMM template with fused epilogues.
// ---------------------------------------------------------------------------

static constexpr int B_  = 2;
static constexpr int S_  = 2048;
static constexpr int D_  = 1024;
static constexpr int K_  = 128;
static constexpr int KR_ = 8;
static constexpr int CH_ = 256;
static constexpr int NC_ = 8;      // S_/CH_
static constexpr int V_  = 32000;
static constexpr int LC_ = 4;      // local context size
static constexpr int R_  = B_ * S_;   // 4096 token rows
static constexpr float LAM_   = 0.9f;
static constexpr float SCALE_ = 0.08838834764831845f;  // 1/sqrt(128)

// ------------------------------ scratch ------------------------------------
__device__ float g_ctx [R_ * D_];
__device__ float g_q   [R_ * K_];
__device__ float g_k   [R_ * K_];
__device__ float g_v   [R_ * D_];
__device__ float g_out [R_ * D_];
__device__ float g_h   [R_ * D_];
__device__ float g_hn  [R_ * D_];
__device__ float g_attn[B_ * NC_ * CH_ * CH_];
__device__ float g_Sst [B_ * K_ * D_];
__device__ float g_U   [B_ * CH_ * D_];
__device__ float g_byp [B_ * KR_];
__device__ float g_St  [B_ * D_];

// ------------------------------ GEMM ---------------------------------------
enum { EPI_STORE = 0, EPI_PHI, EPI_BIAS, EPI_MASK, EPI_INTER, EPI_RESID, EPI_ACC };

// C[M,N] (+=) A[M,Kd] @ B[Kd,N], 128x128x8 tiles, 8x8 microtiles, 256 threads.
// TRA=1: A is stored [Kd,M] row-major (i.e. logical A transposed).
// TRB=1: B is stored [N,Kd] row-major (i.e. logical B transposed).
// blockIdx.z batches with strides sA/sB/sC (elements).
template <int TRA, int TRB, int EPI>
__global__ __launch_bounds__(256) void gemm128(
    const float* __restrict__ A, const float* __restrict__ Bm, float* __restrict__ C,
    const float* __restrict__ x1, const float* __restrict__ x2, const float* __restrict__ x3,
    int M, int N, int Kd, long sA, long sB, long sC, long sAux)
{
    constexpr int BM = 128, BN = 128, BK = 8, TM = 8, TN = 8;
    __shared__ __align__(16) float As[BK][BM];
    __shared__ __align__(16) float Bs[BK][BN];

    const int z = blockIdx.z;
    A  += (long)z * sA;
    Bm += (long)z * sB;
    C  += (long)z * sC;

    const int tid  = threadIdx.x;
    const int row0 = blockIdx.y * BM;
    const int col0 = blockIdx.x * BN;
    const int tRow = tid >> 4;   // 0..15
    const int tCol = tid & 15;   // 0..15

    float acc[TM][TN];
#pragma unroll
    for (int i = 0; i < TM; i++)
#pragma unroll
        for (int j = 0; j < TN; j++) acc[i][j] = 0.f;

    for (int k0 = 0; k0 < Kd; k0 += BK) {
        if (TRA == 0) {
            const int r = tid >> 1, c = (tid & 1) * 4;
            float4 a4 = *reinterpret_cast<const float4*>(A + (long)(row0 + r) * Kd + k0 + c);
            As[c + 0][r] = a4.x; As[c + 1][r] = a4.y;
            As[c + 2][r] = a4.z; As[c + 3][r] = a4.w;
        } else {
            const int r = tid >> 5, c = (tid & 31) * 4;
            *reinterpret_cast<float4*>(&As[r][c]) =
                *reinterpret_cast<const float4*>(A + (long)(k0 + r) * M + row0 + c);
        }
        if (TRB == 0) {
            const int r = tid >> 5, c = (tid & 31) * 4;
            *reinterpret_cast<float4*>(&Bs[r][c]) =
                *reinterpret_cast<const float4*>(Bm + (long)(k0 + r) * N + col0 + c);
        } else {
            const int r = tid >> 1, c = (tid & 1) * 4;
            float4 b4 = *reinterpret_cast<const float4*>(Bm + (long)(col0 + r) * Kd + k0 + c);
            Bs[c + 0][r] = b4.x; Bs[c + 1][r] = b4.y;
            Bs[c + 2][r] = b4.z; Bs[c + 3][r] = b4.w;
        }
        __syncthreads();

#pragma unroll
        for (int kk = 0; kk < BK; kk++) {
            float ra[TM], rb[TN];
            *reinterpret_cast<float4*>(ra)     = *reinterpret_cast<const float4*>(&As[kk][tRow * TM]);
            *reinterpret_cast<float4*>(ra + 4) = *reinterpret_cast<const float4*>(&As[kk][tRow * TM + 4]);
            *reinterpret_cast<float4*>(rb)     = *reinterpret_cast<const float4*>(&Bs[kk][tCol * TN]);
            *reinterpret_cast<float4*>(rb + 4) = *reinterpret_cast<const float4*>(&Bs[kk][tCol * TN + 4]);
#pragma unroll
            for (int i = 0; i < TM; i++)
#pragma unroll
                for (int j = 0; j < TN; j++) acc[i][j] += ra[i] * rb[j];
        }
        __syncthreads();
    }

    // Column-dependent additive term for the inter-chunk epilogue:
    // byp@Vb (low-rank bypass) + St (EMA time state), broadcast over rows.
    float addc[TN];
    if (EPI == EPI_INTER) {
#pragma unroll
        for (int j = 0; j < TN; j++) {
            const int gc = col0 + tCol * TN + j;
            float bv = 0.f;
#pragma unroll
            for (int r = 0; r < KR_; r++) bv += x1[z * KR_ + r] * x2[r * D_ + gc];
            addc[j] = bv + x3[z * D_ + gc];
        }
    }

#pragma unroll
    for (int i = 0; i < TM; i++) {
        const int gr = row0 + tRow * TM + i;
#pragma unroll
        for (int j = 0; j < TN; j++) {
            const int gc = col0 + tCol * TN + j;
            const long idx = (long)gr * N + gc;
            const float vv = acc[i][j];
            if (EPI == EPI_STORE)      C[idx] = vv;
            else if (EPI == EPI_PHI)   C[idx] = (vv > 0.f) ? vv + 1.f : expf(vv);  // elu+1
            else if (EPI == EPI_BIAS)  C[idx] = vv + x1[gc];
            else if (EPI == EPI_MASK)  C[idx] = (gc <= gr) ? vv * SCALE_ : 0.f;
            else if (EPI == EPI_INTER) C[idx] += vv * SCALE_ + addc[j];
            else if (EPI == EPI_RESID) C[idx] = x1[(long)z * sAux + idx] - vv * SCALE_;
            else if (EPI == EPI_ACC)   C[idx] += vv;
        }
    }
}

// --------------------------- small kernels ---------------------------------
__global__ void k_zero(float* __restrict__ p, int n)
{
    const int i = blockIdx.x * blockDim.x + threadIdx.x;
    if (i < n) p[i] = 0.f;
}

// ctx[b,s,:] = sum_{off=0..3, s-off>=0} emb[x[b,s-off], :]
__global__ __launch_bounds__(256) void k_embed(const int* __restrict__ x,
    const float* __restrict__ emb, float* __restrict__ ctx)
{
    const int row = blockIdx.x;         // b*S + s
    const int b = row / S_, s = row % S_;
    const int tid = threadIdx.x;
    float acc[4] = {0.f, 0.f, 0.f, 0.f};
    for (int off = 0; off < LC_; off++) {
        const int sp = s - off;
        if (sp < 0) break;
        const float* er = emb + (long)x[b * S_ + sp] * D_;
#pragma unroll
        for (int j = 0; j < 4; j++) acc[j] += er[tid + j * 256];
    }
    float* cr = ctx + (long)row * D_;
#pragma unroll
    for (int j = 0; j < 4; j++) cr[tid + j * 256] = acc[j];
}

// Per-chunk carry update: xmean, byp = xmean@Ub, St = lam*St + (1-lam)*xmean.
__global__ __launch_bounds__(256) void k_chunk_stats(
    const float* __restrict__ ctx, const float* __restrict__ Ub,
    float* __restrict__ byp, float* __restrict__ St, int c)
{
    const int b = blockIdx.x, tid = threadIdx.x;
    const float* base = ctx + ((long)b * S_ + (long)c * CH_) * D_;
    float xm[4];
#pragma unroll
    for (int j = 0; j < 4; j++) {
        const int d = tid + j * 256;
        float s = 0.f;
        for (int i = 0; i < CH_; i++) s += base[(long)i * D_ + d];
        xm[j] = s * (1.0f / CH_);
    }
    __shared__ float part[KR_ * 256];
    float pr[KR_];
#pragma unroll
    for (int r = 0; r < KR_; r++) pr[r] = 0.f;
#pragma unroll
    for (int j = 0; j < 4; j++) {
        const int d = tid + j * 256;
#pragma unroll
        for (int r = 0; r < KR_; r++) pr[r] += xm[j] * Ub[d * KR_ + r];
    }
#pragma unroll
    for (int r = 0; r < KR_; r++) part[r * 256 + tid] = pr[r];
    __syncthreads();
    for (int st = 128; st > 0; st >>= 1) {
        if (tid < st)
#pragma unroll
            for (int r = 0; r < KR_; r++) part[r * 256 + tid] += part[r * 256 + tid + st];
        __syncthreads();
    }
    if (tid < KR_) byp[b * KR_ + tid] = part[tid * 256];
#pragma unroll
    for (int j = 0; j < 4; j++) {
        const int d = tid + j * 256;
        St[b * D_ + d] = LAM_ * St[b * D_ + d] + (1.f - LAM_) * xm[j];
    }
}

// Row LayerNorm
__global__ __launch_bounds__(256) void k_ln(const float* __restrict__ h,
    const float* __restrict__ g, const float* __restrict__ bta, float* __restrict__ o)
{
    const int row = blockIdx.x, tid = threadIdx.x;
    const float* hr = h + (long)row * D_;
    float v[4]; float s = 0.f;
#pragma unroll
    for (int j = 0; j < 4; j++) { v[j] = hr[tid + j * 256]; s += v[j]; }
    __shared__ float red[256];
    red[tid] = s; __syncthreads();
    for (int st = 128; st > 0; st >>= 1) { if (tid < st) red[tid] += red[tid + st]; __syncthreads(); }
    const float mu = red[0] * (1.f / D_);
    __syncthreads();
    float s2 = 0.f;
#pragma unroll
    for (int j = 0; j < 4; j++) { const float d = v[j] - mu; s2 += d * d; }
    red[tid] = s2; __syncthreads();
    for (int st = 128; st > 0; st >>= 1) { if (tid < st) red[tid] += red[tid + st]; __syncthreads(); }
    const float inv = rsqrtf(red[0] * (1.f / D_) + 1e-5f);
    float* orow = o + (long)row * D_;
#pragma unroll
    for (int j = 0; j < 4; j++) {
        const int c = tid + j * 256;
        orow[c] = (v[j] - mu) * inv * g[c] + bta[c];
    }
}

// ------------------------------- launch ------------------------------------
extern "C" void kernel_launch(void* const* d_in, const int* in_sizes, int n_in,
                              void* d_out, int out_size)
{
    (void)in_sizes; (void)n_in; (void)out_size;
    const int*   x    = (const int*)  d_in[0];
    const float* emb  = (const float*)d_in[1];
    const float* Wq   = (const float*)d_in[2];
    const float* Wk   = (const float*)d_in[3];
    const float* Wv   = (const float*)d_in[4];
    const float* Wo   = (const float*)d_in[5];
    const float* Ub   = (const float*)d_in[6];
    const float* Vb   = (const float*)d_in[7];
    const float* lng  = (const float*)d_in[8];
    const float* lnb  = (const float*)d_in[9];
    const float* Wout = (const float*)d_in[10];
    const float* bout = (const float*)d_in[11];
    float* outp = (float*)d_out;

    float *ctx, *q, *k, *v, *ov, *h, *hn, *at, *Sst, *U, *byp, *St;
    cudaGetSymbolAddress((void**)&ctx, g_ctx);
    cudaGetSymbolAddress((void**)&q,   g_q);
    cudaGetSymbolAddress((void**)&k,   g_k);
    cudaGetSymbolAddress((void**)&v,   g_v);
    cudaGetSymbolAddress((void**)&ov,  g_out);
    cudaGetSymbolAddress((void**)&h,   g_h);
    cudaGetSymbolAddress((void**)&hn,  g_hn);
    cudaGetSymbolAddress((void**)&at,  g_attn);
    cudaGetSymbolAddress((void**)&Sst, g_Sst);
    cudaGetSymbolAddress((void**)&U,   g_U);
    cudaGetSymbolAddress((void**)&byp, g_byp);
    cudaGetSymbolAddress((void**)&St,  g_St);

    // zero the carried state (must be identical every call)
    k_zero<<<(B_ * K_ * D_ + 255) / 256, 256>>>(Sst, B_ * K_ * D_);
    k_zero<<<1, 256>>>(byp, B_ * KR_);
    k_zero<<<(B_ * D_ + 255) / 256, 256>>>(St, B_ * D_);

    // embedding + causal local-context sum
    k_embed<<<R_, 256>>>(x, emb, ctx);

    // QKV projections (phi fused into Q,K)
    gemm128<0,0,EPI_PHI><<<dim3(K_ / 128, R_ / 128, 1), 256>>>(
        ctx, Wq, q, nullptr, nullptr, nullptr, R_, K_, D_, 0, 0, 0, 0);
    gemm128<0,0,EPI_PHI><<<dim3(K_ / 128, R_ / 128, 1), 256>>>(
        ctx, Wk, k, nullptr, nullptr, nullptr, R_, K_, D_, 0, 0, 0, 0);
    gemm128<0,0,EPI_STORE><<<dim3(D_ / 128, R_ / 128, 1), 256>>>(
        ctx, Wv, v, nullptr, nullptr, nullptr, R_, D_, D_, 0, 0, 0, 0);

    // intra-chunk causal linear attention: A = tril(QK^T)*scale ; out = A@V
    gemm128<0,1,EPI_MASK><<<dim3(CH_ / 128, CH_ / 128, B_ * NC_), 256>>>(
        q, k, at, nullptr, nullptr, nullptr,
        CH_, CH_, K_, (long)CH_ * K_, (long)CH_ * K_, (long)CH_ * CH_, 0);
    gemm128<0,0,EPI_STORE><<<dim3(D_ / 128, CH_ / 128, B_ * NC_), 256>>>(
        at, v, ov, nullptr, nullptr, nullptr,
        CH_, D_, CH_, (long)CH_ * CH_, (long)CH_ * D_, (long)CH_ * D_, 0);

    // sequential chunk recurrence (state S, low-rank bypass, EMA time state)
    for (int c = 0; c < NC_; c++) {
        const float* qc = q + (long)c * CH_ * K_;
        const float* kc = k + (long)c * CH_ * K_;
        // out += q@S*scale + byp@Vb + St     (uses carry from chunk c-1)
        gemm128<0,0,EPI_INTER><<<dim3(D_ / 128, CH_ / 128, B_), 256>>>(
            qc, Sst, ov + (long)c * CH_ * D_, byp, Vb, St,
            CH_, D_, K_, (long)S_ * K_, (long)K_ * D_, (long)S_ * D_, 0);
        // U = v - (k@S)*scale                (delta-rule residual)
        gemm128<0,0,EPI_RESID><<<dim3(D_ / 128, CH_ / 128, B_), 256>>>(
            kc, Sst, U, v + (long)c * CH_ * D_, nullptr, nullptr,
            CH_, D_, K_, (long)S_ * K_, (long)K_ * D_, (long)CH_ * D_, (long)S_ * D_);
        // S += k^T @ U
        gemm128<1,0,EPI_ACC><<<dim3(D_ / 128, K_ / 128, B_), 256>>>(
            kc, U, Sst, nullptr, nullptr, nullptr,
            K_, D_, CH_, (long)S_ * K_, (long)CH_ * D_, (long)K_ * D_, 0);
        // carry update for chunk c+1
        k_chunk_stats<<<B_, 256>>>(ctx, Ub, byp, St, c);
    }

    // output projection, layernorm, vocab head
    gemm128<0,0,EPI_STORE><<<dim3(D_ / 128, R_ / 128, 1), 256>>>(
        ov, Wo, h, nullptr, nullptr, nullptr, R_, D_, D_, 0, 0, 0, 0);
    k_ln<<<R_, 256>>>(h, lng, lnb, hn);
    gemm128<0,0,EPI_BIAS><<<dim3(V_ / 128, R_ / 128, 1), 256>>>(
        hn, Wout, outp, bout, nullptr, nullptr, R_, V_, D_, 0, 0, 0, 0);
}

// round 3
// speedup vs baseline: 1.7893x; 1.7893x over previous
#include <cuda_runtime.h>
#include <cuda_bf16.h>
#include <cstdint>

// ---------------------------------------------------------------------------
// DSRAModel forward. Round 3: vocab GEMM via mma.sync bf16 (sm_100-safe; no
// tcgen05 — harness assembles for plain sm_100). Hi/lo split K-concat keeps
// fp32-class accuracy with one bf16 GEMM of K'=3072.
// ---------------------------------------------------------------------------

static constexpr int B_  = 2;
static constexpr int S_  = 2048;
static constexpr int D_  = 1024;
static constexpr int K_  = 128;
static constexpr int KR_ = 8;
static constexpr int CH_ = 256;
static constexpr int NC_ = 8;
static constexpr int V_  = 32000;
static constexpr int LC_ = 4;
static constexpr int R_  = B_ * S_;
static constexpr float LAM_   = 0.9f;
static constexpr float SCALE_ = 0.08838834764831845f;

// ------------------------------ scratch ------------------------------------
__device__ float g_ctx [R_ * D_];
__device__ float g_q   [R_ * K_];
__device__ float g_k   [R_ * K_];
__device__ float g_v   [R_ * D_];
__device__ float g_out [R_ * D_];
__device__ float g_h   [R_ * D_];
__device__ float g_hn  [R_ * D_];
__device__ float g_attn[B_ * NC_ * CH_ * CH_];
__device__ float g_Sst [B_ * K_ * D_];
__device__ float g_U   [B_ * CH_ * D_];
__device__ float g_byp [B_ * KR_];
__device__ float g_St  [B_ * D_];
// hi/lo-split bf16 operands (K' = 3*1024): A'=[Ah,Ah,Al], B'=[Wh,Wl,Wh] K-major
static constexpr int KP_ = 3 * D_;
__device__ unsigned short g_Abf[R_ * KP_];
__device__ unsigned short g_Bbf[V_ * KP_];

// ------------------------ PTX helpers (sm_100-safe) ------------------------
__device__ __forceinline__ uint32_t smem_u32(const void* p) {
    uint32_t a;
    asm("{ .reg .u64 t; cvta.to.shared.u64 t, %1; cvt.u32.u64 %0, t; }" : "=r"(a) : "l"(p));
    return a;
}
#define CP16(dst, src)   asm volatile("cp.async.cg.shared.global [%0], [%1], 16;" :: "r"(dst), "l"(src))
#define CP_COMMIT()      asm volatile("cp.async.commit_group;" ::: "memory")
#define CP_WAIT(n)       asm volatile("cp.async.wait_group %0;" :: "n"(n) : "memory")
#define LDSM4(r, addr)                                                          \
    asm volatile("ldmatrix.sync.aligned.m8n8.x4.shared.b16 {%0,%1,%2,%3}, [%4];" \
        : "=r"((r)[0]), "=r"((r)[1]), "=r"((r)[2]), "=r"((r)[3]) : "r"(addr))
#define MMA16816(c, a, b0, b1)                                                  \
    asm volatile("mma.sync.aligned.m16n8k16.row.col.f32.bf16.bf16.f32 "         \
        "{%0,%1,%2,%3},{%4,%5,%6,%7},{%8,%9},{%0,%1,%2,%3};"                    \
        : "+f"((c)[0]), "+f"((c)[1]), "+f"((c)[2]), "+f"((c)[3])                \
        : "r"((a)[0]), "r"((a)[1]), "r"((a)[2]), "r"((a)[3]), "r"(b0), "r"(b1))

// ---------------------- vocab GEMM (mma.sync bf16) -------------------------
// C[4096,32000] = A'[4096,3072] @ B'[32000,3072]^T + bias
static constexpr int GBM = 128, GBN = 128, GBK = 32, NSTG = 3;
static constexpr int KIT  = KP_ / GBK;           // 96
static constexpr int ROWB = 80;                  // padded row stride bytes (40 bf16)
static constexpr int ABYT = GBM * ROWB;          // 10240
static constexpr int STG  = 2 * ABYT;            // 20480 (A then B)
static constexpr int GSM  = NSTG * STG;          // 61440

__global__ __launch_bounds__(256, 2)
void vocab_mma(const unsigned short* __restrict__ Abf,
               const unsigned short* __restrict__ Bbf,
               const float* __restrict__ bias, float* __restrict__ C)
{
    extern __shared__ char smem[];
    const uint32_t sb = smem_u32(smem);
    const int tid = threadIdx.x, wid = tid >> 5, lane = tid & 31;
    const int wm = wid >> 2, wn = wid & 3;            // 2 x 4 warp grid
    const int m0 = blockIdx.x * GBM;                  // m fastest => B strip reuse
    const int n0 = blockIdx.y * GBN;

    const unsigned short* Arow = Abf + (long)m0 * KP_;
    const unsigned short* Brow = Bbf + (long)n0 * KP_;

    // per-thread cp.async assignment: row = tid/2, two 16B chunks
    const int ldr = tid >> 1, ldc = (tid & 1) * 2;

    auto load_stage = [&](int it, int slot) {
        const int k0 = it * GBK;
        const uint32_t ab = sb + slot * STG;
        const uint32_t bb = ab + ABYT;
        const unsigned short* ga = Arow + (long)ldr * KP_ + k0 + ldc * 8;
        CP16(ab + ldr * ROWB + ldc * 16, ga);
        CP16(ab + ldr * ROWB + (ldc + 1) * 16, ga + 8);
        const unsigned short* gb = Brow + (long)ldr * KP_ + k0 + ldc * 8;
        CP16(bb + ldr * ROWB + ldc * 16, gb);
        CP16(bb + ldr * ROWB + (ldc + 1) * 16, gb + 8);
    };

    // ldmatrix lane offsets (byte), excluding ks/slot terms
    uint32_t aoff[4], boff[2];
#pragma unroll
    for (int mt = 0; mt < 4; mt++)
        aoff[mt] = (wm * 64 + mt * 16 + (lane & 15)) * ROWB + (lane >> 4) * 16;
#pragma unroll
    for (int nt2 = 0; nt2 < 2; nt2++)
        boff[nt2] = (wn * 32 + nt2 * 16 + (lane & 7) + ((lane >> 4) << 3)) * ROWB
                  + ((lane >> 3) & 1) * 16;

    float acc[4][4][4];
#pragma unroll
    for (int mt = 0; mt < 4; mt++)
#pragma unroll
        for (int nt = 0; nt < 4; nt++)
#pragma unroll
            for (int e = 0; e < 4; e++) acc[mt][nt][e] = 0.f;

    // prologue
#pragma unroll
    for (int s = 0; s < NSTG - 1; s++) { load_stage(s, s); CP_COMMIT(); }

    for (int i = 0; i < KIT; i++) {
        CP_WAIT(NSTG - 2);
        __syncthreads();
        const int slot = i % NSTG;
        const uint32_t ab = sb + slot * STG;
        const uint32_t bb = ab + ABYT;
#pragma unroll
        for (int ks = 0; ks < 2; ks++) {
            uint32_t af[4][4], bf[2][4];
#pragma unroll
            for (int mt = 0; mt < 4; mt++) LDSM4(af[mt], ab + aoff[mt] + ks * 32);
#pragma unroll
            for (int nt2 = 0; nt2 < 2; nt2++) LDSM4(bf[nt2], bb + boff[nt2] + ks * 32);
#pragma unroll
            for (int mt = 0; mt < 4; mt++)
#pragma unroll
                for (int nt = 0; nt < 4; nt++)
                    MMA16816(acc[mt][nt], af[mt], bf[nt >> 1][(nt & 1) * 2],
                             bf[nt >> 1][(nt & 1) * 2 + 1]);
        }
        __syncthreads();
        if (i + NSTG - 1 < KIT) load_stage(i + NSTG - 1, (i + NSTG - 1) % NSTG);
        CP_COMMIT();   // empty groups at tail keep wait-count arithmetic uniform
    }

    // epilogue: direct float2 stores + bias
    const int r0 = lane >> 2, c2 = (lane & 3) * 2;
#pragma unroll
    for (int nt = 0; nt < 4; nt++) {
        const int gc = n0 + wn * 32 + nt * 8 + c2;
        const float2 bv = *reinterpret_cast<const float2*>(bias + gc);
#pragma unroll
        for (int mt = 0; mt < 4; mt++) {
            const int gr = m0 + wm * 64 + mt * 16 + r0;
            float2 lo = { acc[mt][nt][0] + bv.x, acc[mt][nt][1] + bv.y };
            float2 hi = { acc[mt][nt][2] + bv.x, acc[mt][nt][3] + bv.y };
            *reinterpret_cast<float2*>(C + (long)gr * V_ + gc) = lo;
            *reinterpret_cast<float2*>(C + (long)(gr + 8) * V_ + gc) = hi;
        }
    }
}

// -------------------- hi/lo split conversion kernels -----------------------
__global__ __launch_bounds__(256) void k_convA(const float* __restrict__ hn,
                                               unsigned short* __restrict__ A)
{
    const int i = blockIdx.x * 256 + threadIdx.x;
    const float x = hn[i];
    const __nv_bfloat16 h = __float2bfloat16_rn(x);
    const __nv_bfloat16 l = __float2bfloat16_rn(x - __bfloat162float(h));
    const int m = i >> 10, k = i & 1023;
    const long base = (long)m * KP_ + k;
    const unsigned short hb = __bfloat16_as_ushort(h);
    A[base] = hb; A[base + D_] = hb; A[base + 2 * D_] = __bfloat16_as_ushort(l);
}

__global__ __launch_bounds__(256) void k_convB(const float* __restrict__ W,
                                               unsigned short* __restrict__ Bt)
{
    __shared__ float t[32][33];
    const int n0 = blockIdx.x * 32, k0 = blockIdx.y * 32;
    const int tx = threadIdx.x & 31, ty = threadIdx.x >> 5;
#pragma unroll
    for (int j = 0; j < 32; j += 8)
        t[ty + j][tx] = W[(long)(k0 + ty + j) * V_ + n0 + tx];
    __syncthreads();
#pragma unroll
    for (int j = 0; j < 32; j += 8) {
        const int n = ty + j;
        const float x = t[tx][n];
        const __nv_bfloat16 h = __float2bfloat16_rn(x);
        const __nv_bfloat16 l = __float2bfloat16_rn(x - __bfloat162float(h));
        const long base = (long)(n0 + n) * KP_ + k0 + tx;
        const unsigned short hb = __bfloat16_as_ushort(h);
        Bt[base] = hb; Bt[base + D_] = __bfloat16_as_ushort(l); Bt[base + 2 * D_] = hb;
    }
}

// ------------------------------ SIMT GEMM ----------------------------------
enum { EPI_STORE = 0, EPI_PHI, EPI_MASK, EPI_INTER, EPI_RESID, EPI_ACC };

template <int TRA, int TRB, int EPI>
__global__ __launch_bounds__(256) void gemm128(
    const float* __restrict__ A, const float* __restrict__ Bm, float* __restrict__ C,
    const float* __restrict__ x1, const float* __restrict__ x2, const float* __restrict__ x3,
    int M, int N, int Kd, long sA, long sB, long sC, long sAux)
{
    constexpr int BM = 128, BN = 128, BK = 8, TM = 8, TN = 8;
    __shared__ __align__(16) float As[BK][BM];
    __shared__ __align__(16) float Bs[BK][BN];

    const int z = blockIdx.z;
    A  += (long)z * sA;
    Bm += (long)z * sB;
    C  += (long)z * sC;

    const int tid  = threadIdx.x;
    const int row0 = blockIdx.y * BM;
    const int col0 = blockIdx.x * BN;
    const int tRow = tid >> 4;
    const int tCol = tid & 15;

    float acc[TM][TN];
#pragma unroll
    for (int i = 0; i < TM; i++)
#pragma unroll
        for (int j = 0; j < TN; j++) acc[i][j] = 0.f;

    for (int k0 = 0; k0 < Kd; k0 += BK) {
        if (TRA == 0) {
            const int r = tid >> 1, c = (tid & 1) * 4;
            float4 a4 = *reinterpret_cast<const float4*>(A + (long)(row0 + r) * Kd + k0 + c);
            As[c + 0][r] = a4.x; As[c + 1][r] = a4.y;
            As[c + 2][r] = a4.z; As[c + 3][r] = a4.w;
        } else {
            const int r = tid >> 5, c = (tid & 31) * 4;
            *reinterpret_cast<float4*>(&As[r][c]) =
                *reinterpret_cast<const float4*>(A + (long)(k0 + r) * M + row0 + c);
        }
        if (TRB == 0) {
            const int r = tid >> 5, c = (tid & 31) * 4;
            *reinterpret_cast<float4*>(&Bs[r][c]) =
                *reinterpret_cast<const float4*>(Bm + (long)(k0 + r) * N + col0 + c);
        } else {
            const int r = tid >> 1, c = (tid & 1) * 4;
            float4 b4 = *reinterpret_cast<const float4*>(Bm + (long)(col0 + r) * Kd + k0 + c);
            Bs[c + 0][r] = b4.x; Bs[c + 1][r] = b4.y;
            Bs[c + 2][r] = b4.z; Bs[c + 3][r] = b4.w;
        }
        __syncthreads();

#pragma unroll
        for (int kk = 0; kk < BK; kk++) {
            float ra[TM], rb[TN];
            *reinterpret_cast<float4*>(ra)     = *reinterpret_cast<const float4*>(&As[kk][tRow * TM]);
            *reinterpret_cast<float4*>(ra + 4) = *reinterpret_cast<const float4*>(&As[kk][tRow * TM + 4]);
            *reinterpret_cast<float4*>(rb)     = *reinterpret_cast<const float4*>(&Bs[kk][tCol * TN]);
            *reinterpret_cast<float4*>(rb + 4) = *reinterpret_cast<const float4*>(&Bs[kk][tCol * TN + 4]);
#pragma unroll
            for (int i = 0; i < TM; i++)
#pragma unroll
                for (int j = 0; j < TN; j++) acc[i][j] += ra[i] * rb[j];
        }
        __syncthreads();
    }

    float addc[TN];
    if (EPI == EPI_INTER) {
#pragma unroll
        for (int j = 0; j < TN; j++) {
            const int gc = col0 + tCol * TN + j;
            float bv = 0.f;
#pragma unroll
            for (int r = 0; r < KR_; r++) bv += x1[z * KR_ + r] * x2[r * D_ + gc];
            addc[j] = bv + x3[z * D_ + gc];
        }
    }

#pragma unroll
    for (int i = 0; i < TM; i++) {
        const int gr = row0 + tRow * TM + i;
#pragma unroll
        for (int j = 0; j < TN; j++) {
            const int gc = col0 + tCol * TN + j;
            const long idx = (long)gr * N + gc;
            const float vv = acc[i][j];
            if (EPI == EPI_STORE)      C[idx] = vv;
            else if (EPI == EPI_PHI)   C[idx] = (vv > 0.f) ? vv + 1.f : expf(vv);
            else if (EPI == EPI_MASK)  C[idx] = (gc <= gr) ? vv * SCALE_ : 0.f;
            else if (EPI == EPI_INTER) C[idx] += vv * SCALE_ + addc[j];
            else if (EPI == EPI_RESID) C[idx] = x1[(long)z * sAux + idx] - vv * SCALE_;
            else if (EPI == EPI_ACC)   C[idx] += vv;
        }
    }
}

// --------------------------- small kernels ---------------------------------
__global__ void k_zero(float* __restrict__ p, int n)
{
    const int i = blockIdx.x * blockDim.x + threadIdx.x;
    if (i < n) p[i] = 0.f;
}

__global__ __launch_bounds__(256) void k_embed(const int* __restrict__ x,
    const float* __restrict__ emb, float* __restrict__ ctx)
{
    const int row = blockIdx.x;
    const int b = row / S_, s = row % S_;
    const int tid = threadIdx.x;
    float acc[4] = {0.f, 0.f, 0.f, 0.f};
    for (int off = 0; off < LC_; off++) {
        const int sp = s - off;
        if (sp < 0) break;
        const float* er = emb + (long)x[b * S_ + sp] * D_;
#pragma unroll
        for (int j = 0; j < 4; j++) acc[j] += er[tid + j * 256];
    }
    float* cr = ctx + (long)row * D_;
#pragma unroll
    for (int j = 0; j < 4; j++) cr[tid + j * 256] = acc[j];
}

__global__ __launch_bounds__(256) void k_chunk_stats(
    const float* __restrict__ ctx, const float* __restrict__ Ub,
    float* __restrict__ byp, float* __restrict__ St, int c)
{
    const int b = blockIdx.x, tid = threadIdx.x;
    const float* base = ctx + ((long)b * S_ + (long)c * CH_) * D_;
    float xm[4];
#pragma unroll
    for (int j = 0; j < 4; j++) {
        const int d = tid + j * 256;
        float s = 0.f;
        for (int i = 0; i < CH_; i++) s += base[(long)i * D_ + d];
        xm[j] = s * (1.0f / CH_);
    }
    __shared__ float part[KR_ * 256];
    float pr[KR_];
#pragma unroll
    for (int r = 0; r < KR_; r++) pr[r] = 0.f;
#pragma unroll
    for (int j = 0; j < 4; j++) {
        const int d = tid + j * 256;
#pragma unroll
        for (int r = 0; r < KR_; r++) pr[r] += xm[j] * Ub[d * KR_ + r];
    }
#pragma unroll
    for (int r = 0; r < KR_; r++) part[r * 256 + tid] = pr[r];
    __syncthreads();
    for (int st = 128; st > 0; st >>= 1) {
        if (tid < st)
#pragma unroll
            for (int r = 0; r < KR_; r++) part[r * 256 + tid] += part[r * 256 + tid + st];
        __syncthreads();
    }
    if (tid < KR_) byp[b * KR_ + tid] = part[tid * 256];
#pragma unroll
    for (int j = 0; j < 4; j++) {
        const int d = tid + j * 256;
        St[b * D_ + d] = LAM_ * St[b * D_ + d] + (1.f - LAM_) * xm[j];
    }
}

__global__ __launch_bounds__(256) void k_ln(const float* __restrict__ h,
    const float* __restrict__ g, const float* __restrict__ bta, float* __restrict__ o)
{
    const int row = blockIdx.x, tid = threadIdx.x;
    const float* hr = h + (long)row * D_;
    float v[4]; float s = 0.f;
#pragma unroll
    for (int j = 0; j < 4; j++) { v[j] = hr[tid + j * 256]; s += v[j]; }
    __shared__ float red[256];
    red[tid] = s; __syncthreads();
    for (int st = 128; st > 0; st >>= 1) { if (tid < st) red[tid] += red[tid + st]; __syncthreads(); }
    const float mu = red[0] * (1.f / D_);
    __syncthreads();
    float s2 = 0.f;
#pragma unroll
    for (int j = 0; j < 4; j++) { const float d = v[j] - mu; s2 += d * d; }
    red[tid] = s2; __syncthreads();
    for (int st = 128; st > 0; st >>= 1) { if (tid < st) red[tid] += red[tid + st]; __syncthreads(); }
    const float inv = rsqrtf(red[0] * (1.f / D_) + 1e-5f);
    float* orow = o + (long)row * D_;
#pragma unroll
    for (int j = 0; j < 4; j++) {
        const int c = tid + j * 256;
        orow[c] = (v[j] - mu) * inv * g[c] + bta[c];
    }
}

// ------------------------------- launch ------------------------------------
extern "C" void kernel_launch(void* const* d_in, const int* in_sizes, int n_in,
                              void* d_out, int out_size)
{
    (void)in_sizes; (void)n_in; (void)out_size;
    const int*   x    = (const int*)  d_in[0];
    const float* emb  = (const float*)d_in[1];
    const float* Wq   = (const float*)d_in[2];
    const float* Wk   = (const float*)d_in[3];
    const float* Wv   = (const float*)d_in[4];
    const float* Wo   = (const float*)d_in[5];
    const float* Ub   = (const float*)d_in[6];
    const float* Vb   = (const float*)d_in[7];
    const float* lng  = (const float*)d_in[8];
    const float* lnb  = (const float*)d_in[9];
    const float* Wout = (const float*)d_in[10];
    const float* bout = (const float*)d_in[11];
    float* outp = (float*)d_out;

    float *ctx, *q, *k, *v, *ov, *h, *hn, *at, *Sst, *U, *byp, *St;
    unsigned short *Abf, *Bbf;
    cudaGetSymbolAddress((void**)&ctx, g_ctx);
    cudaGetSymbolAddress((void**)&q,   g_q);
    cudaGetSymbolAddress((void**)&k,   g_k);
    cudaGetSymbolAddress((void**)&v,   g_v);
    cudaGetSymbolAddress((void**)&ov,  g_out);
    cudaGetSymbolAddress((void**)&h,   g_h);
    cudaGetSymbolAddress((void**)&hn,  g_hn);
    cudaGetSymbolAddress((void**)&at,  g_attn);
    cudaGetSymbolAddress((void**)&Sst, g_Sst);
    cudaGetSymbolAddress((void**)&U,   g_U);
    cudaGetSymbolAddress((void**)&byp, g_byp);
    cudaGetSymbolAddress((void**)&St,  g_St);
    cudaGetSymbolAddress((void**)&Abf, g_Abf);
    cudaGetSymbolAddress((void**)&Bbf, g_Bbf);

    cudaFuncSetAttribute(vocab_mma, cudaFuncAttributeMaxDynamicSharedMemorySize, GSM);

    // weight split+transpose (independent of the model chain)
    k_convB<<<dim3(V_ / 32, D_ / 32), 256>>>(Wout, Bbf);

    k_zero<<<(B_ * K_ * D_ + 255) / 256, 256>>>(Sst, B_ * K_ * D_);
    k_zero<<<1, 256>>>(byp, B_ * KR_);
    k_zero<<<(B_ * D_ + 255) / 256, 256>>>(St, B_ * D_);

    k_embed<<<R_, 256>>>(x, emb, ctx);

    gemm128<0,0,EPI_PHI><<<dim3(K_ / 128, R_ / 128, 1), 256>>>(
        ctx, Wq, q, nullptr, nullptr, nullptr, R_, K_, D_, 0, 0, 0, 0);
    gemm128<0,0,EPI_PHI><<<dim3(K_ / 128, R_ / 128, 1), 256>>>(
        ctx, Wk, k, nullptr, nullptr, nullptr, R_, K_, D_, 0, 0, 0, 0);
    gemm128<0,0,EPI_STORE><<<dim3(D_ / 128, R_ / 128, 1), 256>>>(
        ctx, Wv, v, nullptr, nullptr, nullptr, R_, D_, D_, 0, 0, 0, 0);

    gemm128<0,1,EPI_MASK><<<dim3(CH_ / 128, CH_ / 128, B_ * NC_), 256>>>(
        q, k, at, nullptr, nullptr, nullptr,
        CH_, CH_, K_, (long)CH_ * K_, (long)CH_ * K_, (long)CH_ * CH_, 0);
    gemm128<0,0,EPI_STORE><<<dim3(D_ / 128, CH_ / 128, B_ * NC_), 256>>>(
        at, v, ov, nullptr, nullptr, nullptr,
        CH_, D_, CH_, (long)CH_ * CH_, (long)CH_ * D_, (long)CH_ * D_, 0);

    for (int c = 0; c < NC_; c++) {
        const float* qc = q + (long)c * CH_ * K_;
        const float* kc = k + (long)c * CH_ * K_;
        gemm128<0,0,EPI_INTER><<<dim3(D_ / 128, CH_ / 128, B_), 256>>>(
            qc, Sst, ov + (long)c * CH_ * D_, byp, Vb, St,
            CH_, D_, K_, (long)S_ * K_, (long)K_ * D_, (long)S_ * D_, 0);
        gemm128<0,0,EPI_RESID><<<dim3(D_ / 128, CH_ / 128, B_), 256>>>(
            kc, Sst, U, v + (long)c * CH_ * D_, nullptr, nullptr,
            CH_, D_, K_, (long)S_ * K_, (long)K_ * D_, (long)CH_ * D_, (long)S_ * D_);
        gemm128<1,0,EPI_ACC><<<dim3(D_ / 128, K_ / 128, B_), 256>>>(
            kc, U, Sst, nullptr, nullptr, nullptr,
            K_, D_, CH_, (long)S_ * K_, (long)CH_ * D_, (long)K_ * D_, 0);
        k_chunk_stats<<<B_, 256>>>(ctx, Ub, byp, St, c);
    }

    gemm128<0,0,EPI_STORE><<<dim3(D_ / 128, R_ / 128, 1), 256>>>(
        ov, Wo, h, nullptr, nullptr, nullptr, R_, D_, D_, 0, 0, 0, 0);
    k_ln<<<R_, 256>>>(h, lng, lnb, hn);

    k_convA<<<R_ * D_ / 256, 256>>>(hn, Abf);
    vocab_mma<<<dim3(R_ / GBM, V_ / GBN), 256, GSM>>>(Abf, Bbf, bout, outp);
}

// round 5
// speedup vs baseline: 2.1741x; 1.2151x over previous
#include <cuda_runtime.h>
#include <cuda_bf16.h>
#include <cuda_fp16.h>
#include <cstdint>

// ---------------------------------------------------------------------------
// DSRAModel forward. Round 5 (= Round 4 resubmit after infra failure):
// vocab GEMM = fp16 2-term split (K'=2048), A' = [Ah, Al] exact to 22 bits,
// W' = [Wh, Wh] dedup'd in the loader. Split fused into LayerNorm.
// mma.sync m16n8k16 fp16 (sm_100-safe).
// ---------------------------------------------------------------------------

static constexpr int B_  = 2;
static constexpr int S_  = 2048;
static constexpr int D_  = 1024;
static constexpr int K_  = 128;
static constexpr int KR_ = 8;
static constexpr int CH_ = 256;
static constexpr int NC_ = 8;
static constexpr int V_  = 32000;
static constexpr int LC_ = 4;
static constexpr int R_  = B_ * S_;
static constexpr float LAM_   = 0.9f;
static constexpr float SCALE_ = 0.08838834764831845f;

// ------------------------------ scratch ------------------------------------
__device__ float g_ctx [R_ * D_];
__device__ float g_q   [R_ * K_];
__device__ float g_k   [R_ * K_];
__device__ float g_v   [R_ * D_];
__device__ float g_out [R_ * D_];
__device__ float g_h   [R_ * D_];
__device__ float g_attn[B_ * NC_ * CH_ * CH_];
__device__ float g_Sst [B_ * K_ * D_];
__device__ float g_U   [B_ * CH_ * D_];
__device__ float g_byp [B_ * KR_];
__device__ float g_St  [B_ * D_];
// fp16 split operands: A' = [Ah, Al] (K'=2048), Bh = fp16(W^T) (K=1024, dedup)
static constexpr int KPA_ = 2 * D_;   // 2048
static constexpr int KB_  = D_;       // 1024
__device__ unsigned short g_Ahf[R_ * KPA_];
__device__ unsigned short g_Bhf[V_ * KB_];

// ------------------------ PTX helpers (sm_100-safe) ------------------------
__device__ __forceinline__ uint32_t smem_u32(const void* p) {
    uint32_t a;
    asm("{ .reg .u64 t; cvta.to.shared.u64 t, %1; cvt.u32.u64 %0, t; }" : "=r"(a) : "l"(p));
    return a;
}
#define CP16(dst, src)   asm volatile("cp.async.cg.shared.global [%0], [%1], 16;" :: "r"(dst), "l"(src))
#define CP_COMMIT()      asm volatile("cp.async.commit_group;" ::: "memory")
#define CP_WAIT(n)       asm volatile("cp.async.wait_group %0;" :: "n"(n) : "memory")
#define LDSM4(r, addr)                                                          \
    asm volatile("ldmatrix.sync.aligned.m8n8.x4.shared.b16 {%0,%1,%2,%3}, [%4];" \
        : "=r"((r)[0]), "=r"((r)[1]), "=r"((r)[2]), "=r"((r)[3]) : "r"(addr))
#define MMA16816(c, a, b0, b1)                                                  \
    asm volatile("mma.sync.aligned.m16n8k16.row.col.f32.f16.f16.f32 "           \
        "{%0,%1,%2,%3},{%4,%5,%6,%7},{%8,%9},{%0,%1,%2,%3};"                    \
        : "+f"((c)[0]), "+f"((c)[1]), "+f"((c)[2]), "+f"((c)[3])                \
        : "r"((a)[0]), "r"((a)[1]), "r"((a)[2]), "r"((a)[3]), "r"(b0), "r"(b1))

// ---------------------- vocab GEMM (mma.sync fp16) -------------------------
// C[4096,32000] = [Ah,Al] @ [Wh;Wh]^T + bias  (B tile index wraps mod 1024)
static constexpr int GBM = 128, GBN = 128, GBK = 32, NSTG = 3;
static constexpr int KIT  = KPA_ / GBK;          // 64
static constexpr int ROWB = 80;                  // padded row stride bytes
static constexpr int ABYT = GBM * ROWB;          // 10240
static constexpr int STG  = 2 * ABYT;            // 20480
static constexpr int GSM  = NSTG * STG;          // 61440

__global__ __launch_bounds__(256, 2)
void vocab_mma(const unsigned short* __restrict__ Ahf,
               const unsigned short* __restrict__ Bhf,
               const float* __restrict__ bias, float* __restrict__ C)
{
    extern __shared__ char smem[];
    const uint32_t sb = smem_u32(smem);
    const int tid = threadIdx.x, wid = tid >> 5, lane = tid & 31;
    const int wm = wid >> 2, wn = wid & 3;            // 2 x 4 warp grid
    const int m0 = blockIdx.x * GBM;                  // m fastest => B strip reuse
    const int n0 = blockIdx.y * GBN;

    const unsigned short* Arow = Ahf + (long)m0 * KPA_;
    const unsigned short* Brow = Bhf + (long)n0 * KB_;

    const int ldr = tid >> 1, ldc = (tid & 1) * 2;    // row, 2x16B chunks

    auto load_stage = [&](int it, int slot) {
        const int ka = it * GBK;                       // A index 0..2047
        const int kb = ka & (KB_ - 1);                 // B dedup: wrap at 1024
        const uint32_t ab = sb + slot * STG;
        const uint32_t bb = ab + ABYT;
        const unsigned short* ga = Arow + (long)ldr * KPA_ + ka + ldc * 8;
        CP16(ab + ldr * ROWB + ldc * 16, ga);
        CP16(ab + ldr * ROWB + (ldc + 1) * 16, ga + 8);
        const unsigned short* gb = Brow + (long)ldr * KB_ + kb + ldc * 8;
        CP16(bb + ldr * ROWB + ldc * 16, gb);
        CP16(bb + ldr * ROWB + (ldc + 1) * 16, gb + 8);
    };

    uint32_t aoff[4], boff[2];
#pragma unroll
    for (int mt = 0; mt < 4; mt++)
        aoff[mt] = (wm * 64 + mt * 16 + (lane & 15)) * ROWB + (lane >> 4) * 16;
#pragma unroll
    for (int nt2 = 0; nt2 < 2; nt2++)
        boff[nt2] = (wn * 32 + nt2 * 16 + (lane & 7) + ((lane >> 4) << 3)) * ROWB
                  + ((lane >> 3) & 1) * 16;

    float acc[4][4][4];
#pragma unroll
    for (int mt = 0; mt < 4; mt++)
#pragma unroll
        for (int nt = 0; nt < 4; nt++)
#pragma unroll
            for (int e = 0; e < 4; e++) acc[mt][nt][e] = 0.f;

#pragma unroll
    for (int s = 0; s < NSTG - 1; s++) { load_stage(s, s); CP_COMMIT(); }

    for (int i = 0; i < KIT; i++) {
        CP_WAIT(NSTG - 2);
        __syncthreads();
        const int slot = i % NSTG;
        const uint32_t ab = sb + slot * STG;
        const uint32_t bb = ab + ABYT;
#pragma unroll
        for (int ks = 0; ks < 2; ks++) {
            uint32_t af[4][4], bf[2][4];
#pragma unroll
            for (int mt = 0; mt < 4; mt++) LDSM4(af[mt], ab + aoff[mt] + ks * 32);
#pragma unroll
            for (int nt2 = 0; nt2 < 2; nt2++) LDSM4(bf[nt2], bb + boff[nt2] + ks * 32);
#pragma unroll
            for (int mt = 0; mt < 4; mt++)
#pragma unroll
                for (int nt = 0; nt < 4; nt++)
                    MMA16816(acc[mt][nt], af[mt], bf[nt >> 1][(nt & 1) * 2],
                             bf[nt >> 1][(nt & 1) * 2 + 1]);
        }
        __syncthreads();
        if (i + NSTG - 1 < KIT) load_stage(i + NSTG - 1, (i + NSTG - 1) % NSTG);
        CP_COMMIT();
    }

    const int r0 = lane >> 2, c2 = (lane & 3) * 2;
#pragma unroll
    for (int nt = 0; nt < 4; nt++) {
        const int gc = n0 + wn * 32 + nt * 8 + c2;
        const float2 bv = *reinterpret_cast<const float2*>(bias + gc);
#pragma unroll
        for (int mt = 0; mt < 4; mt++) {
            const int gr = m0 + wm * 64 + mt * 16 + r0;
            float2 lo = { acc[mt][nt][0] + bv.x, acc[mt][nt][1] + bv.y };
            float2 hi = { acc[mt][nt][2] + bv.x, acc[mt][nt][3] + bv.y };
            *reinterpret_cast<float2*>(C + (long)gr * V_ + gc) = lo;
            *reinterpret_cast<float2*>(C + (long)(gr + 8) * V_ + gc) = hi;
        }
    }
}

// ----------------- weight transpose + fp16 convert -------------------------
__global__ __launch_bounds__(256) void k_convB(const float* __restrict__ W,
                                               unsigned short* __restrict__ Bt)
{
    __shared__ float t[32][33];
    const int n0 = blockIdx.x * 32, k0 = blockIdx.y * 32;
    const int tx = threadIdx.x & 31, ty = threadIdx.x >> 5;
#pragma unroll
    for (int j = 0; j < 32; j += 8)
        t[ty + j][tx] = W[(long)(k0 + ty + j) * V_ + n0 + tx];
    __syncthreads();
#pragma unroll
    for (int j = 0; j < 32; j += 8) {
        const int n = ty + j;
        Bt[(long)(n0 + n) * KB_ + k0 + tx] =
            __half_as_ushort(__float2half_rn(t[tx][n]));
    }
}

// ------------------------------ SIMT GEMM ----------------------------------
enum { EPI_STORE = 0, EPI_PHI, EPI_MASK, EPI_INTER, EPI_RESID, EPI_ACC };

template <int TRA, int TRB, int EPI>
__global__ __launch_bounds__(256) void gemm128(
    const float* __restrict__ A, const float* __restrict__ Bm, float* __restrict__ C,
    const float* __restrict__ x1, const float* __restrict__ x2, const float* __restrict__ x3,
    int M, int N, int Kd, long sA, long sB, long sC, long sAux)
{
    constexpr int BM = 128, BN = 128, BK = 8, TM = 8, TN = 8;
    __shared__ __align__(16) float As[BK][BM];
    __shared__ __align__(16) float Bs[BK][BN];

    const int z = blockIdx.z;
    A  += (long)z * sA;
    Bm += (long)z * sB;
    C  += (long)z * sC;

    const int tid  = threadIdx.x;
    const int row0 = blockIdx.y * BM;
    const int col0 = blockIdx.x * BN;
    const int tRow = tid >> 4;
    const int tCol = tid & 15;

    float acc[TM][TN];
#pragma unroll
    for (int i = 0; i < TM; i++)
#pragma unroll
        for (int j = 0; j < TN; j++) acc[i][j] = 0.f;

    for (int k0 = 0; k0 < Kd; k0 += BK) {
        if (TRA == 0) {
            const int r = tid >> 1, c = (tid & 1) * 4;
            float4 a4 = *reinterpret_cast<const float4*>(A + (long)(row0 + r) * Kd + k0 + c);
            As[c + 0][r] = a4.x; As[c + 1][r] = a4.y;
            As[c + 2][r] = a4.z; As[c + 3][r] = a4.w;
        } else {
            const int r = tid >> 5, c = (tid & 31) * 4;
            *reinterpret_cast<float4*>(&As[r][c]) =
                *reinterpret_cast<const float4*>(A + (long)(k0 + r) * M + row0 + c);
        }
        if (TRB == 0) {
            const int r = tid >> 5, c = (tid & 31) * 4;
            *reinterpret_cast<float4*>(&Bs[r][c]) =
                *reinterpret_cast<const float4*>(Bm + (long)(k0 + r) * N + col0 + c);
        } else {
            const int r = tid >> 1, c = (tid & 1) * 4;
            float4 b4 = *reinterpret_cast<const float4*>(Bm + (long)(col0 + r) * Kd + k0 + c);
            Bs[c + 0][r] = b4.x; Bs[c + 1][r] = b4.y;
            Bs[c + 2][r] = b4.z; Bs[c + 3][r] = b4.w;
        }
        __syncthreads();

#pragma unroll
        for (int kk = 0; kk < BK; kk++) {
            float ra[TM], rb[TN];
            *reinterpret_cast<float4*>(ra)     = *reinterpret_cast<const float4*>(&As[kk][tRow * TM]);
            *reinterpret_cast<float4*>(ra + 4) = *reinterpret_cast<const float4*>(&As[kk][tRow * TM + 4]);
            *reinterpret_cast<float4*>(rb)     = *reinterpret_cast<const float4*>(&Bs[kk][tCol * TN]);
            *reinterpret_cast<float4*>(rb + 4) = *reinterpret_cast<const float4*>(&Bs[kk][tCol * TN + 4]);
#pragma unroll
            for (int i = 0; i < TM; i++)
#pragma unroll
                for (int j = 0; j < TN; j++) acc[i][j] += ra[i] * rb[j];
        }
        __syncthreads();
    }

    float addc[TN];
    if (EPI == EPI_INTER) {
#pragma unroll
        for (int j = 0; j < TN; j++) {
            const int gc = col0 + tCol * TN + j;
            float bv = 0.f;
#pragma unroll
            for (int r = 0; r < KR_; r++) bv += x1[z * KR_ + r] * x2[r * D_ + gc];
            addc[j] = bv + x3[z * D_ + gc];
        }
    }

#pragma unroll
    for (int i = 0; i < TM; i++) {
        const int gr = row0 + tRow * TM + i;
#pragma unroll
        for (int j = 0; j < TN; j++) {
            const int gc = col0 + tCol * TN + j;
            const long idx = (long)gr * N + gc;
            const float vv = acc[i][j];
            if (EPI == EPI_STORE)      C[idx] = vv;
            else if (EPI == EPI_PHI)   C[idx] = (vv > 0.f) ? vv + 1.f : expf(vv);
            else if (EPI == EPI_MASK)  C[idx] = (gc <= gr) ? vv * SCALE_ : 0.f;
            else if (EPI == EPI_INTER) C[idx] += vv * SCALE_ + addc[j];
            else if (EPI == EPI_RESID) C[idx] = x1[(long)z * sAux + idx] - vv * SCALE_;
            else if (EPI == EPI_ACC)   C[idx] += vv;
        }
    }
}

// --------------------------- small kernels ---------------------------------
__global__ void k_zero(float* __restrict__ p, int n)
{
    const int i = blockIdx.x * blockDim.x + threadIdx.x;
    if (i < n) p[i] = 0.f;
}

__global__ __launch_bounds__(256) void k_embed(const int* __restrict__ x,
    const float* __restrict__ emb, float* __restrict__ ctx)
{
    const int row = blockIdx.x;
    const int b = row / S_, s = row % S_;
    const int tid = threadIdx.x;
    float acc[4] = {0.f, 0.f, 0.f, 0.f};
    for (int off = 0; off < LC_; off++) {
        const int sp = s - off;
        if (sp < 0) break;
        const float* er = emb + (long)x[b * S_ + sp] * D_;
#pragma unroll
        for (int j = 0; j < 4; j++) acc[j] += er[tid + j * 256];
    }
    float* cr = ctx + (long)row * D_;
#pragma unroll
    for (int j = 0; j < 4; j++) cr[tid + j * 256] = acc[j];
}

__global__ __launch_bounds__(256) void k_chunk_stats(
    const float* __restrict__ ctx, const float* __restrict__ Ub,
    float* __restrict__ byp, float* __restrict__ St, int c)
{
    const int b = blockIdx.x, tid = threadIdx.x;
    const float* base = ctx + ((long)b * S_ + (long)c * CH_) * D_;
    float xm[4];
#pragma unroll
    for (int j = 0; j < 4; j++) {
        const int d = tid + j * 256;
        float s = 0.f;
        for (int i = 0; i < CH_; i++) s += base[(long)i * D_ + d];
        xm[j] = s * (1.0f / CH_);
    }
    __shared__ float part[KR_ * 256];
    float pr[KR_];
#pragma unroll
    for (int r = 0; r < KR_; r++) pr[r] = 0.f;
#pragma unroll
    for (int j = 0; j < 4; j++) {
        const int d = tid + j * 256;
#pragma unroll
        for (int r = 0; r < KR_; r++) pr[r] += xm[j] * Ub[d * KR_ + r];
    }
#pragma unroll
    for (int r = 0; r < KR_; r++) part[r * 256 + tid] = pr[r];
    __syncthreads();
    for (int st = 128; st > 0; st >>= 1) {
        if (tid < st)
#pragma unroll
            for (int r = 0; r < KR_; r++) part[r * 256 + tid] += part[r * 256 + tid + st];
        __syncthreads();
    }
    if (tid < KR_) byp[b * KR_ + tid] = part[tid * 256];
#pragma unroll
    for (int j = 0; j < 4; j++) {
        const int d = tid + j * 256;
        St[b * D_ + d] = LAM_ * St[b * D_ + d] + (1.f - LAM_) * xm[j];
    }
}

// LayerNorm fused with fp16 hi/lo split: A'[row] = [h2(y), h2(y - h2(y))]
__global__ __launch_bounds__(256) void k_ln_split(const float* __restrict__ h,
    const float* __restrict__ g, const float* __restrict__ bta,
    unsigned short* __restrict__ Aout)
{
    const int row = blockIdx.x, tid = threadIdx.x;
    const float* hr = h + (long)row * D_;
    float v[4]; float s = 0.f;
#pragma unroll
    for (int j = 0; j < 4; j++) { v[j] = hr[tid + j * 256]; s += v[j]; }
    __shared__ float red[256];
    red[tid] = s; __syncthreads();
    for (int st = 128; st > 0; st >>= 1) { if (tid < st) red[tid] += red[tid + st]; __syncthreads(); }
    const float mu = red[0] * (1.f / D_);
    __syncthreads();
    float s2 = 0.f;
#pragma unroll
    for (int j = 0; j < 4; j++) { const float d = v[j] - mu; s2 += d * d; }
    red[tid] = s2; __syncthreads();
    for (int st = 128; st > 0; st >>= 1) { if (tid < st) red[tid] += red[tid + st]; __syncthreads(); }
    const float inv = rsqrtf(red[0] * (1.f / D_) + 1e-5f);
    unsigned short* ar = Aout + (long)row * KPA_;
#pragma unroll
    for (int j = 0; j < 4; j++) {
        const int c = tid + j * 256;
        const float y = (v[j] - mu) * inv * g[c] + bta[c];
        const __half hi = __float2half_rn(y);
        const __half lo = __float2half_rn(y - __half2float(hi));
        ar[c]      = __half_as_ushort(hi);
        ar[c + D_] = __half_as_ushort(lo);
    }
}

// ------------------------------- launch ------------------------------------
extern "C" void kernel_launch(void* const* d_in, const int* in_sizes, int n_in,
                              void* d_out, int out_size)
{
    (void)in_sizes; (void)n_in; (void)out_size;
    const int*   x    = (const int*)  d_in[0];
    const float* emb  = (const float*)d_in[1];
    const float* Wq   = (const float*)d_in[2];
    const float* Wk   = (const float*)d_in[3];
    const float* Wv   = (const float*)d_in[4];
    const float* Wo   = (const float*)d_in[5];
    const float* Ub   = (const float*)d_in[6];
    const float* Vb   = (const float*)d_in[7];
    const float* lng  = (const float*)d_in[8];
    const float* lnb  = (const float*)d_in[9];
    const float* Wout = (const float*)d_in[10];
    const float* bout = (const float*)d_in[11];
    float* outp = (float*)d_out;

    float *ctx, *q, *k, *v, *ov, *h, *at, *Sst, *U, *byp, *St;
    unsigned short *Ahf, *Bhf;
    cudaGetSymbolAddress((void**)&ctx, g_ctx);
    cudaGetSymbolAddress((void**)&q,   g_q);
    cudaGetSymbolAddress((void**)&k,   g_k);
    cudaGetSymbolAddress((void**)&v,   g_v);
    cudaGetSymbolAddress((void**)&ov,  g_out);
    cudaGetSymbolAddress((void**)&h,   g_h);
    cudaGetSymbolAddress((void**)&at,  g_attn);
    cudaGetSymbolAddress((void**)&Sst, g_Sst);
    cudaGetSymbolAddress((void**)&U,   g_U);
    cudaGetSymbolAddress((void**)&byp, g_byp);
    cudaGetSymbolAddress((void**)&St,  g_St);
    cudaGetSymbolAddress((void**)&Ahf, g_Ahf);
    cudaGetSymbolAddress((void**)&Bhf, g_Bhf);

    cudaFuncSetAttribute(vocab_mma, cudaFuncAttributeMaxDynamicSharedMemorySize, GSM);

    // weight transpose+convert (independent of the model chain)
    k_convB<<<dim3(V_ / 32, D_ / 32), 256>>>(Wout, Bhf);

    k_zero<<<(B_ * K_ * D_ + 255) / 256, 256>>>(Sst, B_ * K_ * D_);
    k_zero<<<1, 256>>>(byp, B_ * KR_);
    k_zero<<<(B_ * D_ + 255) / 256, 256>>>(St, B_ * D_);

    k_embed<<<R_, 256>>>(x, emb, ctx);

    gemm128<0,0,EPI_PHI><<<dim3(K_ / 128, R_ / 128, 1), 256>>>(
        ctx, Wq, q, nullptr, nullptr, nullptr, R_, K_, D_, 0, 0, 0, 0);
    gemm128<0,0,EPI_PHI><<<dim3(K_ / 128, R_ / 128, 1), 256>>>(
        ctx, Wk, k, nullptr, nullptr, nullptr, R_, K_, D_, 0, 0, 0, 0);
    gemm128<0,0,EPI_STORE><<<dim3(D_ / 128, R_ / 128, 1), 256>>>(
        ctx, Wv, v, nullptr, nullptr, nullptr, R_, D_, D_, 0, 0, 0, 0);

    gemm128<0,1,EPI_MASK><<<dim3(CH_ / 128, CH_ / 128, B_ * NC_), 256>>>(
        q, k, at, nullptr, nullptr, nullptr,
        CH_, CH_, K_, (long)CH_ * K_, (long)CH_ * K_, (long)CH_ * CH_, 0);
    gemm128<0,0,EPI_STORE><<<dim3(D_ / 128, CH_ / 128, B_ * NC_), 256>>>(
        at, v, ov, nullptr, nullptr, nullptr,
        CH_, D_, CH_, (long)CH_ * CH_, (long)CH_ * D_, (long)CH_ * D_, 0);

    for (int c = 0; c < NC_; c++) {
        const float* qc = q + (long)c * CH_ * K_;
        const float* kc = k + (long)c * CH_ * K_;
        gemm128<0,0,EPI_INTER><<<dim3(D_ / 128, CH_ / 128, B_), 256>>>(
            qc, Sst, ov + (long)c * CH_ * D_, byp, Vb, St,
            CH_, D_, K_, (long)S_ * K_, (long)K_ * D_, (long)S_ * D_, 0);
        gemm128<0,0,EPI_RESID><<<dim3(D_ / 128, CH_ / 128, B_), 256>>>(
            kc, Sst, U, v + (long)c * CH_ * D_, nullptr, nullptr,
            CH_, D_, K_, (long)S_ * K_, (long)K_ * D_, (long)CH_ * D_, (long)S_ * D_);
        gemm128<1,0,EPI_ACC><<<dim3(D_ / 128, K_ / 128, B_), 256>>>(
            kc, U, Sst, nullptr, nullptr, nullptr,
            K_, D_, CH_, (long)S_ * K_, (long)CH_ * D_, (long)K_ * D_, 0);
        k_chunk_stats<<<B_, 256>>>(ctx, Ub, byp, St, c);
    }

    gemm128<0,0,EPI_STORE><<<dim3(D_ / 128, R_ / 128, 1), 256>>>(
        ov, Wo, h, nullptr, nullptr, nullptr, R_, D_, D_, 0, 0, 0, 0);
    k_ln_split<<<R_, 256>>>(h, lng, lnb, Ahf);

    vocab_mma<<<dim3(R_ / GBM, V_ / GBN), 256, GSM>>>(Ahf, Bhf, bout, outp);
}

// round 6
// speedup vs baseline: 2.9264x; 1.3460x over previous
#include <cuda_runtime.h>
#include <cuda_bf16.h>
#include <cuda_fp16.h>
#include <cstdint>

// ---------------------------------------------------------------------------
// DSRAModel forward. Round 6: single fp16 vocab GEMM (K=1024, no split).
// Measured error budget: fp16-W rounding alone gave 2.08e-4; adding fp16-A
// rounding predicts ~2.9e-4 (gate 1e-3). Halves the dominant GEMM work again.
// ---------------------------------------------------------------------------

static constexpr int B_  = 2;
static constexpr int S_  = 2048;
static constexpr int D_  = 1024;
static constexpr int K_  = 128;
static constexpr int KR_ = 8;
static constexpr int CH_ = 256;
static constexpr int NC_ = 8;
static constexpr int V_  = 32000;
static constexpr int LC_ = 4;
static constexpr int R_  = B_ * S_;
static constexpr float LAM_   = 0.9f;
static constexpr float SCALE_ = 0.08838834764831845f;

// ------------------------------ scratch ------------------------------------
__device__ float g_ctx [R_ * D_];
__device__ float g_q   [R_ * K_];
__device__ float g_k   [R_ * K_];
__device__ float g_v   [R_ * D_];
__device__ float g_out [R_ * D_];
__device__ float g_h   [R_ * D_];
__device__ float g_attn[B_ * NC_ * CH_ * CH_];
__device__ float g_Sst [B_ * K_ * D_];
__device__ float g_U   [B_ * CH_ * D_];
__device__ float g_byp [B_ * KR_];
__device__ float g_St  [B_ * D_];
// fp16 operands for the vocab GEMM: A = fp16(LN out), B = fp16(W^T), K=1024
static constexpr int KB_ = D_;       // 1024
__device__ unsigned short g_Ahf[R_ * KB_];
__device__ unsigned short g_Bhf[V_ * KB_];

// ------------------------ PTX helpers (sm_100-safe) ------------------------
__device__ __forceinline__ uint32_t smem_u32(const void* p) {
    uint32_t a;
    asm("{ .reg .u64 t; cvta.to.shared.u64 t, %1; cvt.u32.u64 %0, t; }" : "=r"(a) : "l"(p));
    return a;
}
#define CP16(dst, src)   asm volatile("cp.async.cg.shared.global [%0], [%1], 16;" :: "r"(dst), "l"(src))
#define CP_COMMIT()      asm volatile("cp.async.commit_group;" ::: "memory")
#define CP_WAIT(n)       asm volatile("cp.async.wait_group %0;" :: "n"(n) : "memory")
#define LDSM4(r, addr)                                                          \
    asm volatile("ldmatrix.sync.aligned.m8n8.x4.shared.b16 {%0,%1,%2,%3}, [%4];" \
        : "=r"((r)[0]), "=r"((r)[1]), "=r"((r)[2]), "=r"((r)[3]) : "r"(addr))
#define MMA16816(c, a, b0, b1)                                                  \
    asm volatile("mma.sync.aligned.m16n8k16.row.col.f32.f16.f16.f32 "           \
        "{%0,%1,%2,%3},{%4,%5,%6,%7},{%8,%9},{%0,%1,%2,%3};"                    \
        : "+f"((c)[0]), "+f"((c)[1]), "+f"((c)[2]), "+f"((c)[3])                \
        : "r"((a)[0]), "r"((a)[1]), "r"((a)[2]), "r"((a)[3]), "r"(b0), "r"(b1))

// ---------------------- vocab GEMM (mma.sync fp16) -------------------------
// C[4096,32000] = Ah[4096,1024] @ Bh[32000,1024]^T + bias
static constexpr int GBM = 128, GBN = 128, GBK = 32, NSTG = 3;
static constexpr int KIT  = KB_ / GBK;           // 32
static constexpr int ROWB = 80;                  // padded row stride bytes
static constexpr int ABYT = GBM * ROWB;          // 10240
static constexpr int STG  = 2 * ABYT;            // 20480
static constexpr int GSM  = NSTG * STG;          // 61440

__global__ __launch_bounds__(256, 2)
void vocab_mma(const unsigned short* __restrict__ Ahf,
               const unsigned short* __restrict__ Bhf,
               const float* __restrict__ bias, float* __restrict__ C)
{
    extern __shared__ char smem[];
    const uint32_t sb = smem_u32(smem);
    const int tid = threadIdx.x, wid = tid >> 5, lane = tid & 31;
    const int wm = wid >> 2, wn = wid & 3;            // 2 x 4 warp grid
    const int m0 = blockIdx.x * GBM;                  // m fastest => B strip reuse
    const int n0 = blockIdx.y * GBN;

    const unsigned short* Arow = Ahf + (long)m0 * KB_;
    const unsigned short* Brow = Bhf + (long)n0 * KB_;

    const int ldr = tid >> 1, ldc = (tid & 1) * 2;    // row, 2x16B chunks

    auto load_stage = [&](int it, int slot) {
        const int k0 = it * GBK;
        const uint32_t ab = sb + slot * STG;
        const uint32_t bb = ab + ABYT;
        const unsigned short* ga = Arow + (long)ldr * KB_ + k0 + ldc * 8;
        CP16(ab + ldr * ROWB + ldc * 16, ga);
        CP16(ab + ldr * ROWB + (ldc + 1) * 16, ga + 8);
        const unsigned short* gb = Brow + (long)ldr * KB_ + k0 + ldc * 8;
        CP16(bb + ldr * ROWB + ldc * 16, gb);
        CP16(bb + ldr * ROWB + (ldc + 1) * 16, gb + 8);
    };

    uint32_t aoff[4], boff[2];
#pragma unroll
    for (int mt = 0; mt < 4; mt++)
        aoff[mt] = (wm * 64 + mt * 16 + (lane & 15)) * ROWB + (lane >> 4) * 16;
#pragma unroll
    for (int nt2 = 0; nt2 < 2; nt2++)
        boff[nt2] = (wn * 32 + nt2 * 16 + (lane & 7) + ((lane >> 4) << 3)) * ROWB
                  + ((lane >> 3) & 1) * 16;

    float acc[4][4][4];
#pragma unroll
    for (int mt = 0; mt < 4; mt++)
#pragma unroll
        for (int nt = 0; nt < 4; nt++)
#pragma unroll
            for (int e = 0; e < 4; e++) acc[mt][nt][e] = 0.f;

#pragma unroll
    for (int s = 0; s < NSTG - 1; s++) { load_stage(s, s); CP_COMMIT(); }

    for (int i = 0; i < KIT; i++) {
        CP_WAIT(NSTG - 2);
        __syncthreads();
        const int slot = i % NSTG;
        const uint32_t ab = sb + slot * STG;
        const uint32_t bb = ab + ABYT;
#pragma unroll
        for (int ks = 0; ks < 2; ks++) {
            uint32_t af[4][4], bf[2][4];
#pragma unroll
            for (int mt = 0; mt < 4; mt++) LDSM4(af[mt], ab + aoff[mt] + ks * 32);
#pragma unroll
            for (int nt2 = 0; nt2 < 2; nt2++) LDSM4(bf[nt2], bb + boff[nt2] + ks * 32);
#pragma unroll
            for (int mt = 0; mt < 4; mt++)
#pragma unroll
                for (int nt = 0; nt < 4; nt++)
                    MMA16816(acc[mt][nt], af[mt], bf[nt >> 1][(nt & 1) * 2],
                             bf[nt >> 1][(nt & 1) * 2 + 1]);
        }
        __syncthreads();
        if (i + NSTG - 1 < KIT) load_stage(i + NSTG - 1, (i + NSTG - 1) % NSTG);
        CP_COMMIT();
    }

    const int r0 = lane >> 2, c2 = (lane & 3) * 2;
#pragma unroll
    for (int nt = 0; nt < 4; nt++) {
        const int gc = n0 + wn * 32 + nt * 8 + c2;
        const float2 bv = *reinterpret_cast<const float2*>(bias + gc);
#pragma unroll
        for (int mt = 0; mt < 4; mt++) {
            const int gr = m0 + wm * 64 + mt * 16 + r0;
            float2 lo = { acc[mt][nt][0] + bv.x, acc[mt][nt][1] + bv.y };
            float2 hi = { acc[mt][nt][2] + bv.x, acc[mt][nt][3] + bv.y };
            *reinterpret_cast<float2*>(C + (long)gr * V_ + gc) = lo;
            *reinterpret_cast<float2*>(C + (long)(gr + 8) * V_ + gc) = hi;
        }
    }
}

// ----------------- weight transpose + fp16 convert -------------------------
__global__ __launch_bounds__(256) void k_convB(const float* __restrict__ W,
                                               unsigned short* __restrict__ Bt)
{
    __shared__ float t[32][33];
    const int n0 = blockIdx.x * 32, k0 = blockIdx.y * 32;
    const int tx = threadIdx.x & 31, ty = threadIdx.x >> 5;
#pragma unroll
    for (int j = 0; j < 32; j += 8)
        t[ty + j][tx] = W[(long)(k0 + ty + j) * V_ + n0 + tx];
    __syncthreads();
#pragma unroll
    for (int j = 0; j < 32; j += 8) {
        const int n = ty + j;
        Bt[(long)(n0 + n) * KB_ + k0 + tx] =
            __half_as_ushort(__float2half_rn(t[tx][n]));
    }
}

// ------------------------------ SIMT GEMM ----------------------------------
enum { EPI_STORE = 0, EPI_PHI, EPI_MASK, EPI_INTER, EPI_RESID, EPI_ACC };

template <int TRA, int TRB, int EPI>
__global__ __launch_bounds__(256) void gemm128(
    const float* __restrict__ A, const float* __restrict__ Bm, float* __restrict__ C,
    const float* __restrict__ x1, const float* __restrict__ x2, const float* __restrict__ x3,
    int M, int N, int Kd, long sA, long sB, long sC, long sAux)
{
    constexpr int BM = 128, BN = 128, BK = 8, TM = 8, TN = 8;
    __shared__ __align__(16) float As[BK][BM];
    __shared__ __align__(16) float Bs[BK][BN];

    const int z = blockIdx.z;
    A  += (long)z * sA;
    Bm += (long)z * sB;
    C  += (long)z * sC;

    const int tid  = threadIdx.x;
    const int row0 = blockIdx.y * BM;
    const int col0 = blockIdx.x * BN;
    const int tRow = tid >> 4;
    const int tCol = tid & 15;

    float acc[TM][TN];
#pragma unroll
    for (int i = 0; i < TM; i++)
#pragma unroll
        for (int j = 0; j < TN; j++) acc[i][j] = 0.f;

    for (int k0 = 0; k0 < Kd; k0 += BK) {
        if (TRA == 0) {
            const int r = tid >> 1, c = (tid & 1) * 4;
            float4 a4 = *reinterpret_cast<const float4*>(A + (long)(row0 + r) * Kd + k0 + c);
            As[c + 0][r] = a4.x; As[c + 1][r] = a4.y;
            As[c + 2][r] = a4.z; As[c + 3][r] = a4.w;
        } else {
            const int r = tid >> 5, c = (tid & 31) * 4;
            *reinterpret_cast<float4*>(&As[r][c]) =
                *reinterpret_cast<const float4*>(A + (long)(k0 + r) * M + row0 + c);
        }
        if (TRB == 0) {
            const int r = tid >> 5, c = (tid & 31) * 4;
            *reinterpret_cast<float4*>(&Bs[r][c]) =
                *reinterpret_cast<const float4*>(Bm + (long)(k0 + r) * N + col0 + c);
        } else {
            const int r = tid >> 1, c = (tid & 1) * 4;
            float4 b4 = *reinterpret_cast<const float4*>(Bm + (long)(col0 + r) * Kd + k0 + c);
            Bs[c + 0][r] = b4.x; Bs[c + 1][r] = b4.y;
            Bs[c + 2][r] = b4.z; Bs[c + 3][r] = b4.w;
        }
        __syncthreads();

#pragma unroll
        for (int kk = 0; kk < BK; kk++) {
            float ra[TM], rb[TN];
            *reinterpret_cast<float4*>(ra)     = *reinterpret_cast<const float4*>(&As[kk][tRow * TM]);
            *reinterpret_cast<float4*>(ra + 4) = *reinterpret_cast<const float4*>(&As[kk][tRow * TM + 4]);
            *reinterpret_cast<float4*>(rb)     = *reinterpret_cast<const float4*>(&Bs[kk][tCol * TN]);
            *reinterpret_cast<float4*>(rb + 4) = *reinterpret_cast<const float4*>(&Bs[kk][tCol * TN + 4]);
#pragma unroll
            for (int i = 0; i < TM; i++)
#pragma unroll
                for (int j = 0; j < TN; j++) acc[i][j] += ra[i] * rb[j];
        }
        __syncthreads();
    }

    float addc[TN];
    if (EPI == EPI_INTER) {
#pragma unroll
        for (int j = 0; j < TN; j++) {
            const int gc = col0 + tCol * TN + j;
            float bv = 0.f;
#pragma unroll
            for (int r = 0; r < KR_; r++) bv += x1[z * KR_ + r] * x2[r * D_ + gc];
            addc[j] = bv + x3[z * D_ + gc];
        }
    }

#pragma unroll
    for (int i = 0; i < TM; i++) {
        const int gr = row0 + tRow * TM + i;
#pragma unroll
        for (int j = 0; j < TN; j++) {
            const int gc = col0 + tCol * TN + j;
            const long idx = (long)gr * N + gc;
            const float vv = acc[i][j];
            if (EPI == EPI_STORE)      C[idx] = vv;
            else if (EPI == EPI_PHI)   C[idx] = (vv > 0.f) ? vv + 1.f : expf(vv);
            else if (EPI == EPI_MASK)  C[idx] = (gc <= gr) ? vv * SCALE_ : 0.f;
            else if (EPI == EPI_INTER) C[idx] += vv * SCALE_ + addc[j];
            else if (EPI == EPI_RESID) C[idx] = x1[(long)z * sAux + idx] - vv * SCALE_;
            else if (EPI == EPI_ACC)   C[idx] += vv;
        }
    }
}

// --------------------------- small kernels ---------------------------------
__global__ void k_zero(float* __restrict__ p, int n)
{
    const int i = blockIdx.x * blockDim.x + threadIdx.x;
    if (i < n) p[i] = 0.f;
}

__global__ __launch_bounds__(256) void k_embed(const int* __restrict__ x,
    const float* __restrict__ emb, float* __restrict__ ctx)
{
    const int row = blockIdx.x;
    const int b = row / S_, s = row % S_;
    const int tid = threadIdx.x;
    float acc[4] = {0.f, 0.f, 0.f, 0.f};
    for (int off = 0; off < LC_; off++) {
        const int sp = s - off;
        if (sp < 0) break;
        const float* er = emb + (long)x[b * S_ + sp] * D_;
#pragma unroll
        for (int j = 0; j < 4; j++) acc[j] += er[tid + j * 256];
    }
    float* cr = ctx + (long)row * D_;
#pragma unroll
    for (int j = 0; j < 4; j++) cr[tid + j * 256] = acc[j];
}

__global__ __launch_bounds__(256) void k_chunk_stats(
    const float* __restrict__ ctx, const float* __restrict__ Ub,
    float* __restrict__ byp, float* __restrict__ St, int c)
{
    const int b = blockIdx.x, tid = threadIdx.x;
    const float* base = ctx + ((long)b * S_ + (long)c * CH_) * D_;
    float xm[4];
#pragma unroll
    for (int j = 0; j < 4; j++) {
        const int d = tid + j * 256;
        float s = 0.f;
        for (int i = 0; i < CH_; i++) s += base[(long)i * D_ + d];
        xm[j] = s * (1.0f / CH_);
    }
    __shared__ float part[KR_ * 256];
    float pr[KR_];
#pragma unroll
    for (int r = 0; r < KR_; r++) pr[r] = 0.f;
#pragma unroll
    for (int j = 0; j < 4; j++) {
        const int d = tid + j * 256;
#pragma unroll
        for (int r = 0; r < KR_; r++) pr[r] += xm[j] * Ub[d * KR_ + r];
    }
#pragma unroll
    for (int r = 0; r < KR_; r++) part[r * 256 + tid] = pr[r];
    __syncthreads();
    for (int st = 128; st > 0; st >>= 1) {
        if (tid < st)
#pragma unroll
            for (int r = 0; r < KR_; r++) part[r * 256 + tid] += part[r * 256 + tid + st];
        __syncthreads();
    }
    if (tid < KR_) byp[b * KR_ + tid] = part[tid * 256];
#pragma unroll
    for (int j = 0; j < 4; j++) {
        const int d = tid + j * 256;
        St[b * D_ + d] = LAM_ * St[b * D_ + d] + (1.f - LAM_) * xm[j];
    }
}

// LayerNorm fused with fp16 convert: A[row] = fp16(y)
__global__ __launch_bounds__(256) void k_ln_h16(const float* __restrict__ h,
    const float* __restrict__ g, const float* __restrict__ bta,
    unsigned short* __restrict__ Aout)
{
    const int row = blockIdx.x, tid = threadIdx.x;
    const float* hr = h + (long)row * D_;
    float v[4]; float s = 0.f;
#pragma unroll
    for (int j = 0; j < 4; j++) { v[j] = hr[tid + j * 256]; s += v[j]; }
    __shared__ float red[256];
    red[tid] = s; __syncthreads();
    for (int st = 128; st > 0; st >>= 1) { if (tid < st) red[tid] += red[tid + st]; __syncthreads(); }
    const float mu = red[0] * (1.f / D_);
    __syncthreads();
    float s2 = 0.f;
#pragma unroll
    for (int j = 0; j < 4; j++) { const float d = v[j] - mu; s2 += d * d; }
    red[tid] = s2; __syncthreads();
    for (int st = 128; st > 0; st >>= 1) { if (tid < st) red[tid] += red[tid + st]; __syncthreads(); }
    const float inv = rsqrtf(red[0] * (1.f / D_) + 1e-5f);
    unsigned short* ar = Aout + (long)row * KB_;
#pragma unroll
    for (int j = 0; j < 4; j++) {
        const int c = tid + j * 256;
        const float y = (v[j] - mu) * inv * g[c] + bta[c];
        ar[c] = __half_as_ushort(__float2half_rn(y));
    }
}

// ------------------------------- launch ------------------------------------
extern "C" void kernel_launch(void* const* d_in, const int* in_sizes, int n_in,
                              void* d_out, int out_size)
{
    (void)in_sizes; (void)n_in; (void)out_size;
    const int*   x    = (const int*)  d_in[0];
    const float* emb  = (const float*)d_in[1];
    const float* Wq   = (const float*)d_in[2];
    const float* Wk   = (const float*)d_in[3];
    const float* Wv   = (const float*)d_in[4];
    const float* Wo   = (const float*)d_in[5];
    const float* Ub   = (const float*)d_in[6];
    const float* Vb   = (const float*)d_in[7];
    const float* lng  = (const float*)d_in[8];
    const float* lnb  = (const float*)d_in[9];
    const float* Wout = (const float*)d_in[10];
    const float* bout = (const float*)d_in[11];
    float* outp = (float*)d_out;

    float *ctx, *q, *k, *v, *ov, *h, *at, *Sst, *U, *byp, *St;
    unsigned short *Ahf, *Bhf;
    cudaGetSymbolAddress((void**)&ctx, g_ctx);
    cudaGetSymbolAddress((void**)&q,   g_q);
    cudaGetSymbolAddress((void**)&k,   g_k);
    cudaGetSymbolAddress((void**)&v,   g_v);
    cudaGetSymbolAddress((void**)&ov,  g_out);
    cudaGetSymbolAddress((void**)&h,   g_h);
    cudaGetSymbolAddress((void**)&at,  g_attn);
    cudaGetSymbolAddress((void**)&Sst, g_Sst);
    cudaGetSymbolAddress((void**)&U,   g_U);
    cudaGetSymbolAddress((void**)&byp, g_byp);
    cudaGetSymbolAddress((void**)&St,  g_St);
    cudaGetSymbolAddress((void**)&Ahf, g_Ahf);
    cudaGetSymbolAddress((void**)&Bhf, g_Bhf);

    cudaFuncSetAttribute(vocab_mma, cudaFuncAttributeMaxDynamicSharedMemorySize, GSM);

    // weight transpose+convert (independent of the model chain)
    k_convB<<<dim3(V_ / 32, D_ / 32), 256>>>(Wout, Bhf);

    k_zero<<<(B_ * K_ * D_ + 255) / 256, 256>>>(Sst, B_ * K_ * D_);
    k_zero<<<1, 256>>>(byp, B_ * KR_);
    k_zero<<<(B_ * D_ + 255) / 256, 256>>>(St, B_ * D_);

    k_embed<<<R_, 256>>>(x, emb, ctx);

    gemm128<0,0,EPI_PHI><<<dim3(K_ / 128, R_ / 128, 1), 256>>>(
        ctx, Wq, q, nullptr, nullptr, nullptr, R_, K_, D_, 0, 0, 0, 0);
    gemm128<0,0,EPI_PHI><<<dim3(K_ / 128, R_ / 128, 1), 256>>>(
        ctx, Wk, k, nullptr, nullptr, nullptr, R_, K_, D_, 0, 0, 0, 0);
    gemm128<0,0,EPI_STORE><<<dim3(D_ / 128, R_ / 128, 1), 256>>>(
        ctx, Wv, v, nullptr, nullptr, nullptr, R_, D_, D_, 0, 0, 0, 0);

    gemm128<0,1,EPI_MASK><<<dim3(CH_ / 128, CH_ / 128, B_ * NC_), 256>>>(
        q, k, at, nullptr, nullptr, nullptr,
        CH_, CH_, K_, (long)CH_ * K_, (long)CH_ * K_, (long)CH_ * CH_, 0);
    gemm128<0,0,EPI_STORE><<<dim3(D_ / 128, CH_ / 128, B_ * NC_), 256>>>(
        at, v, ov, nullptr, nullptr, nullptr,
        CH_, D_, CH_, (long)CH_ * CH_, (long)CH_ * D_, (long)CH_ * D_, 0);

    for (int c = 0; c < NC_; c++) {
        const float* qc = q + (long)c * CH_ * K_;
        const float* kc = k + (long)c * CH_ * K_;
        gemm128<0,0,EPI_INTER><<<dim3(D_ / 128, CH_ / 128, B_), 256>>>(
            qc, Sst, ov + (long)c * CH_ * D_, byp, Vb, St,
            CH_, D_, K_, (long)S_ * K_, (long)K_ * D_, (long)S_ * D_, 0);
        gemm128<0,0,EPI_RESID><<<dim3(D_ / 128, CH_ / 128, B_), 256>>>(
            kc, Sst, U, v + (long)c * CH_ * D_, nullptr, nullptr,
            CH_, D_, K_, (long)S_ * K_, (long)K_ * D_, (long)CH_ * D_, (long)S_ * D_);
        gemm128<1,0,EPI_ACC><<<dim3(D_ / 128, K_ / 128, B_), 256>>>(
            kc, U, Sst, nullptr, nullptr, nullptr,
            K_, D_, CH_, (long)S_ * K_, (long)CH_ * D_, (long)K_ * D_, 0);
        k_chunk_stats<<<B_, 256>>>(ctx, Ub, byp, St, c);
    }

    gemm128<0,0,EPI_STORE><<<dim3(D_ / 128, R_ / 128, 1), 256>>>(
        ov, Wo, h, nullptr, nullptr, nullptr, R_, D_, D_, 0, 0, 0, 0);
    k_ln_h16<<<R_, 256>>>(h, lng, lnb, Ahf);

    vocab_mma<<<dim3(R_ / GBM, V_ / GBN), 256, GSM>>>(Ahf, Bhf, bout, outp);
}

// round 9
// speedup vs baseline: 3.2878x; 1.1235x over previous
#include <cuda_runtime.h>
#include <cuda_bf16.h>
#include <cuda_fp16.h>
#include <cstdint>

// ---------------------------------------------------------------------------
// DSRAModel forward. Round 9 (bisect): R6 numerics (fp32 v, fp32 Wo, fp16
// vocab GEMM) + the recurrence restructure only (fused INTER+RESID kernel,
// hoisted carry-stat scan). Isolates the restructure from the fp16 paths.
// ---------------------------------------------------------------------------

static constexpr int B_  = 2;
static constexpr int S_  = 2048;
static constexpr int D_  = 1024;
static constexpr int K_  = 128;
static constexpr int KR_ = 8;
static constexpr int CH_ = 256;
static constexpr int NC_ = 8;
static constexpr int V_  = 32000;
static constexpr int LC_ = 4;
static constexpr int R_  = B_ * S_;
static constexpr float LAM_   = 0.9f;
static constexpr float SCALE_ = 0.08838834764831845f;

// ------------------------------ scratch ------------------------------------
__device__ float g_ctx [R_ * D_];
__device__ float g_q   [R_ * K_];
__device__ float g_k   [R_ * K_];
__device__ float g_v   [R_ * D_];
__device__ float g_out [R_ * D_];
__device__ float g_h   [R_ * D_];
__device__ float g_attn[B_ * NC_ * CH_ * CH_];
__device__ float g_Sst [B_ * K_ * D_];
__device__ float g_U   [B_ * CH_ * D_];
__device__ float g_xm     [B_ * NC_ * D_];
__device__ float g_bypArr [NC_ * B_ * KR_];
__device__ float g_StArr  [NC_ * B_ * D_];
// fp16 operands for the vocab GEMM only
static constexpr int KB_ = D_;       // 1024
__device__ unsigned short g_Ahf[R_ * KB_];
__device__ unsigned short g_Bhf[V_ * KB_];

// ------------------------ PTX helpers (sm_100-safe) ------------------------
__device__ __forceinline__ uint32_t smem_u32(const void* p) {
    uint32_t a;
    asm("{ .reg .u64 t; cvta.to.shared.u64 t, %1; cvt.u32.u64 %0, t; }" : "=r"(a) : "l"(p));
    return a;
}
#define CP16(dst, src)   asm volatile("cp.async.cg.shared.global [%0], [%1], 16;" :: "r"(dst), "l"(src))
#define CP_COMMIT()      asm volatile("cp.async.commit_group;" ::: "memory")
#define CP_WAIT(n)       asm volatile("cp.async.wait_group %0;" :: "n"(n) : "memory")
#define LDSM4(r, addr)                                                          \
    asm volatile("ldmatrix.sync.aligned.m8n8.x4.shared.b16 {%0,%1,%2,%3}, [%4];" \
        : "=r"((r)[0]), "=r"((r)[1]), "=r"((r)[2]), "=r"((r)[3]) : "r"(addr))
#define MMA16816(c, a, b0, b1)                                                  \
    asm volatile("mma.sync.aligned.m16n8k16.row.col.f32.f16.f16.f32 "           \
        "{%0,%1,%2,%3},{%4,%5,%6,%7},{%8,%9},{%0,%1,%2,%3};"                    \
        : "+f"((c)[0]), "+f"((c)[1]), "+f"((c)[2]), "+f"((c)[3])                \
        : "r"((a)[0]), "r"((a)[1]), "r"((a)[2]), "r"((a)[3]), "r"(b0), "r"(b1))

// ---------------------- vocab GEMM (mma.sync fp16) -------------------------
static constexpr int GBM = 128, GBN = 128, GBK = 32, NSTG = 3;
static constexpr int KIT  = KB_ / GBK;           // 32
static constexpr int ROWB = 80;
static constexpr int ABYT = GBM * ROWB;
static constexpr int STG  = 2 * ABYT;
static constexpr int GSM  = NSTG * STG;          // 61440

__global__ __launch_bounds__(256, 2)
void vocab_mma(const unsigned short* __restrict__ Ahf,
               const unsigned short* __restrict__ Bhf,
               const float* __restrict__ bias, float* __restrict__ C)
{
    extern __shared__ char smem[];
    const uint32_t sb = smem_u32(smem);
    const int tid = threadIdx.x, wid = tid >> 5, lane = tid & 31;
    const int wm = wid >> 2, wn = wid & 3;
    const int m0 = blockIdx.x * GBM;
    const int n0 = blockIdx.y * GBN;

    const unsigned short* Arow = Ahf + (long)m0 * KB_;
    const unsigned short* Brow = Bhf + (long)n0 * KB_;

    const int ldr = tid >> 1, ldc = (tid & 1) * 2;

    auto load_stage = [&](int it, int slot) {
        const int k0 = it * GBK;
        const uint32_t ab = sb + slot * STG;
        const uint32_t bb = ab + ABYT;
        const unsigned short* ga = Arow + (long)ldr * KB_ + k0 + ldc * 8;
        CP16(ab + ldr * ROWB + ldc * 16, ga);
        CP16(ab + ldr * ROWB + (ldc + 1) * 16, ga + 8);
        const unsigned short* gb = Brow + (long)ldr * KB_ + k0 + ldc * 8;
        CP16(bb + ldr * ROWB + ldc * 16, gb);
        CP16(bb + ldr * ROWB + (ldc + 1) * 16, gb + 8);
    };

    uint32_t aoff[4], boff[2];
#pragma unroll
    for (int mt = 0; mt < 4; mt++)
        aoff[mt] = (wm * 64 + mt * 16 + (lane & 15)) * ROWB + (lane >> 4) * 16;
#pragma unroll
    for (int nt2 = 0; nt2 < 2; nt2++)
        boff[nt2] = (wn * 32 + nt2 * 16 + (lane & 7) + ((lane >> 4) << 3)) * ROWB
                  + ((lane >> 3) & 1) * 16;

    float acc[4][4][4];
#pragma unroll
    for (int mt = 0; mt < 4; mt++)
#pragma unroll
        for (int nt = 0; nt < 4; nt++)
#pragma unroll
            for (int e = 0; e < 4; e++) acc[mt][nt][e] = 0.f;

#pragma unroll
    for (int s = 0; s < NSTG - 1; s++) { load_stage(s, s); CP_COMMIT(); }

    for (int i = 0; i < KIT; i++) {
        CP_WAIT(NSTG - 2);
        __syncthreads();
        const int slot = i % NSTG;
        const uint32_t ab = sb + slot * STG;
        const uint32_t bb = ab + ABYT;
#pragma unroll
        for (int ks = 0; ks < 2; ks++) {
            uint32_t af[4][4], bf[2][4];
#pragma unroll
            for (int mt = 0; mt < 4; mt++) LDSM4(af[mt], ab + aoff[mt] + ks * 32);
#pragma unroll
            for (int nt2 = 0; nt2 < 2; nt2++) LDSM4(bf[nt2], bb + boff[nt2] + ks * 32);
#pragma unroll
            for (int mt = 0; mt < 4; mt++)
#pragma unroll
                for (int nt = 0; nt < 4; nt++)
                    MMA16816(acc[mt][nt], af[mt], bf[nt >> 1][(nt & 1) * 2],
                             bf[nt >> 1][(nt & 1) * 2 + 1]);
        }
        __syncthreads();
        if (i + NSTG - 1 < KIT) load_stage(i + NSTG - 1, (i + NSTG - 1) % NSTG);
        CP_COMMIT();
    }

    const int r0 = lane >> 2, c2 = (lane & 3) * 2;
#pragma unroll
    for (int nt = 0; nt < 4; nt++) {
        const int gc = n0 + wn * 32 + nt * 8 + c2;
        const float2 bv = *reinterpret_cast<const float2*>(bias + gc);
#pragma unroll
        for (int mt = 0; mt < 4; mt++) {
            const int gr = m0 + wm * 64 + mt * 16 + r0;
            float2 lo = { acc[mt][nt][0] + bv.x, acc[mt][nt][1] + bv.y };
            float2 hi = { acc[mt][nt][2] + bv.x, acc[mt][nt][3] + bv.y };
            *reinterpret_cast<float2*>(C + (long)gr * V_ + gc) = lo;
            *reinterpret_cast<float2*>(C + (long)(gr + 8) * V_ + gc) = hi;
        }
    }
}

// ----------------- weight transpose + fp16 convert -------------------------
__global__ __launch_bounds__(256) void k_convB(const float* __restrict__ W,
                                               unsigned short* __restrict__ Bt)
{
    __shared__ float t[32][33];
    const int n0 = blockIdx.x * 32, k0 = blockIdx.y * 32;
    const int tx = threadIdx.x & 31, ty = threadIdx.x >> 5;
#pragma unroll
    for (int j = 0; j < 32; j += 8)
        t[ty + j][tx] = W[(long)(k0 + ty + j) * V_ + n0 + tx];
    __syncthreads();
#pragma unroll
    for (int j = 0; j < 32; j += 8) {
        const int n = ty + j;
        Bt[(long)(n0 + n) * KB_ + k0 + tx] =
            __half_as_ushort(__float2half_rn(t[tx][n]));
    }
}

// ------------------------------ SIMT GEMM ----------------------------------
enum { EPI_STORE = 0, EPI_PHI, EPI_MASK, EPI_ACC };

template <int TRA, int TRB, int EPI>
__global__ __launch_bounds__(256) void gemm128(
    const float* __restrict__ A, const float* __restrict__ Bm, float* __restrict__ C,
    int M, int N, int Kd, long sA, long sB, long sC)
{
    constexpr int BM = 128, BN = 128, BK = 8, TM = 8, TN = 8;
    __shared__ __align__(16) float As[BK][BM];
    __shared__ __align__(16) float Bs[BK][BN];

    const int z = blockIdx.z;
    A  += (long)z * sA;
    Bm += (long)z * sB;
    C  += (long)z * sC;

    const int tid  = threadIdx.x;
    const int row0 = blockIdx.y * BM;
    const int col0 = blockIdx.x * BN;
    const int tRow = tid >> 4;
    const int tCol = tid & 15;

    float acc[TM][TN];
#pragma unroll
    for (int i = 0; i < TM; i++)
#pragma unroll
        for (int j = 0; j < TN; j++) acc[i][j] = 0.f;

    for (int k0 = 0; k0 < Kd; k0 += BK) {
        if (TRA == 0) {
            const int r = tid >> 1, c = (tid & 1) * 4;
            float4 a4 = *reinterpret_cast<const float4*>(A + (long)(row0 + r) * Kd + k0 + c);
            As[c + 0][r] = a4.x; As[c + 1][r] = a4.y;
            As[c + 2][r] = a4.z; As[c + 3][r] = a4.w;
        } else {
            const int r = tid >> 5, c = (tid & 31) * 4;
            *reinterpret_cast<float4*>(&As[r][c]) =
                *reinterpret_cast<const float4*>(A + (long)(k0 + r) * M + row0 + c);
        }
        if (TRB == 0) {
            const int r = tid >> 5, c = (tid & 31) * 4;
            *reinterpret_cast<float4*>(&Bs[r][c]) =
                *reinterpret_cast<const float4*>(Bm + (long)(k0 + r) * N + col0 + c);
        } else {
            const int r = tid >> 1, c = (tid & 1) * 4;
            float4 b4 = *reinterpret_cast<const float4*>(Bm + (long)(col0 + r) * Kd + k0 + c);
            Bs[c + 0][r] = b4.x; Bs[c + 1][r] = b4.y;
            Bs[c + 2][r] = b4.z; Bs[c + 3][r] = b4.w;
        }
        __syncthreads();

#pragma unroll
        for (int kk = 0; kk < BK; kk++) {
            float ra[TM], rb[TN];
            *reinterpret_cast<float4*>(ra)     = *reinterpret_cast<const float4*>(&As[kk][tRow * TM]);
            *reinterpret_cast<float4*>(ra + 4) = *reinterpret_cast<const float4*>(&As[kk][tRow * TM + 4]);
            *reinterpret_cast<float4*>(rb)     = *reinterpret_cast<const float4*>(&Bs[kk][tCol * TN]);
            *reinterpret_cast<float4*>(rb + 4) = *reinterpret_cast<const float4*>(&Bs[kk][tCol * TN + 4]);
#pragma unroll
            for (int i = 0; i < TM; i++)
#pragma unroll
                for (int j = 0; j < TN; j++) acc[i][j] += ra[i] * rb[j];
        }
        __syncthreads();
    }

#pragma unroll
    for (int i = 0; i < TM; i++) {
        const int gr = row0 + tRow * TM + i;
#pragma unroll
        for (int j = 0; j < TN; j++) {
            const int gc = col0 + tCol * TN + j;
            const long idx = (long)gr * N + gc;
            const float vv = acc[i][j];
            if (EPI == EPI_STORE)      C[idx] = vv;
            else if (EPI == EPI_PHI)   C[idx] = (vv > 0.f) ? vv + 1.f : expf(vv);
            else if (EPI == EPI_MASK)  C[idx] = (gc <= gr) ? vv * SCALE_ : 0.f;
            else if (EPI == EPI_ACC)   C[idx] += vv;
        }
    }
}

// -------------- fused INTER+RESID recurrence kernel (per chunk) -------------
// role 0 (INTER): ov += (q@S)*scale + byp@Vb + St   (all fp32)
// role 1 (RESID): U = v - (k@S)*scale
__global__ __launch_bounds__(256) void k_ir(
    const float* __restrict__ qc, const float* __restrict__ kc,
    const float* __restrict__ Sst,
    float* __restrict__ ovc,
    const float* __restrict__ vc, float* __restrict__ U,
    const float* __restrict__ bypc, const float* __restrict__ Vb,
    const float* __restrict__ Stc)
{
    constexpr int BM = 128, BN = 128, BK = 8, TM = 8, TN = 8;
    __shared__ __align__(16) float As[BK][BM];
    __shared__ __align__(16) float Bs[BK][BN];

    const int zb   = blockIdx.z & 1;
    const int role = blockIdx.z >> 1;
    const float* A  = (role ? kc : qc) + (long)zb * S_ * K_;
    const float* Bm = Sst + (long)zb * K_ * D_;

    const int tid  = threadIdx.x;
    const int row0 = blockIdx.y * BM;
    const int col0 = blockIdx.x * BN;
    const int tRow = tid >> 4;
    const int tCol = tid & 15;

    float acc[TM][TN];
#pragma unroll
    for (int i = 0; i < TM; i++)
#pragma unroll
        for (int j = 0; j < TN; j++) acc[i][j] = 0.f;

    for (int k0 = 0; k0 < K_; k0 += BK) {
        {
            const int r = tid >> 1, c = (tid & 1) * 4;
            float4 a4 = *reinterpret_cast<const float4*>(A + (long)(row0 + r) * K_ + k0 + c);
            As[c + 0][r] = a4.x; As[c + 1][r] = a4.y;
            As[c + 2][r] = a4.z; As[c + 3][r] = a4.w;
        }
        {
            const int r = tid >> 5, c = (tid & 31) * 4;
            *reinterpret_cast<float4*>(&Bs[r][c]) =
                *reinterpret_cast<const float4*>(Bm + (long)(k0 + r) * D_ + col0 + c);
        }
        __syncthreads();
#pragma unroll
        for (int kk = 0; kk < BK; kk++) {
            float ra[TM], rb[TN];
            *reinterpret_cast<float4*>(ra)     = *reinterpret_cast<const float4*>(&As[kk][tRow * TM]);
            *reinterpret_cast<float4*>(ra + 4) = *reinterpret_cast<const float4*>(&As[kk][tRow * TM + 4]);
            *reinterpret_cast<float4*>(rb)     = *reinterpret_cast<const float4*>(&Bs[kk][tCol * TN]);
            *reinterpret_cast<float4*>(rb + 4) = *reinterpret_cast<const float4*>(&Bs[kk][tCol * TN + 4]);
#pragma unroll
            for (int i = 0; i < TM; i++)
#pragma unroll
                for (int j = 0; j < TN; j++) acc[i][j] += ra[i] * rb[j];
        }
        __syncthreads();
    }

    if (role == 0) {
        float addc[TN];
#pragma unroll
        for (int j = 0; j < TN; j++) {
            const int gc = col0 + tCol * TN + j;
            float bv = 0.f;
#pragma unroll
            for (int r = 0; r < KR_; r++) bv += bypc[zb * KR_ + r] * Vb[r * D_ + gc];
            addc[j] = bv + Stc[zb * D_ + gc];
        }
#pragma unroll
        for (int i = 0; i < TM; i++) {
            const int gr = row0 + tRow * TM + i;
#pragma unroll
            for (int j = 0; j < TN; j++) {
                const int gc = col0 + tCol * TN + j;
                const long o = (long)zb * S_ * D_ + (long)gr * D_ + gc;
                ovc[o] += acc[i][j] * SCALE_ + addc[j];
            }
        }
    } else {
#pragma unroll
        for (int i = 0; i < TM; i++) {
            const int gr = row0 + tRow * TM + i;
#pragma unroll
            for (int j = 0; j < TN; j++) {
                const int gc = col0 + tCol * TN + j;
                U[(long)zb * CH_ * D_ + (long)gr * D_ + gc] =
                    vc[(long)zb * S_ * D_ + (long)gr * D_ + gc] - acc[i][j] * SCALE_;
            }
        }
    }
}

// --------------------------- small kernels ---------------------------------
__global__ void k_zero(float* __restrict__ p, int n)
{
    const int i = blockIdx.x * blockDim.x + threadIdx.x;
    if (i < n) p[i] = 0.f;
}

__global__ __launch_bounds__(256) void k_embed(const int* __restrict__ x,
    const float* __restrict__ emb, float* __restrict__ ctx)
{
    const int row = blockIdx.x;
    const int b = row / S_, s = row % S_;
    const int tid = threadIdx.x;
    float acc[4] = {0.f, 0.f, 0.f, 0.f};
    for (int off = 0; off < LC_; off++) {
        const int sp = s - off;
        if (sp < 0) break;
        const float* er = emb + (long)x[b * S_ + sp] * D_;
#pragma unroll
        for (int j = 0; j < 4; j++) acc[j] += er[tid + j * 256];
    }
    float* cr = ctx + (long)row * D_;
#pragma unroll
    for (int j = 0; j < 4; j++) cr[tid + j * 256] = acc[j];
}

__global__ __launch_bounds__(256) void k_xmean(const float* __restrict__ ctx,
                                               float* __restrict__ xm)
{
    const int b = blockIdx.x, c = blockIdx.y, tid = threadIdx.x;
    const float* base = ctx + ((long)b * S_ + (long)c * CH_) * D_;
#pragma unroll
    for (int j = 0; j < 4; j++) {
        const int d = tid + j * 256;
        float s = 0.f;
        for (int i = 0; i < CH_; i++) s += base[(long)i * D_ + d];
        xm[((long)b * NC_ + c) * D_ + d] = s * (1.0f / CH_);
    }
}

__global__ __launch_bounds__(256) void k_scan(const float* __restrict__ xm,
    const float* __restrict__ Ub, float* __restrict__ bypArr, float* __restrict__ StArr)
{
    const int b = blockIdx.x, tid = threadIdx.x;
    __shared__ float part[KR_ * 256];
    float stp[4] = {0.f, 0.f, 0.f, 0.f};
#pragma unroll
    for (int j = 0; j < 4; j++) StArr[(long)(0 * B_ + b) * D_ + tid + j * 256] = 0.f;
    if (tid < KR_) bypArr[(0 * B_ + b) * KR_ + tid] = 0.f;

    for (int c = 1; c < NC_; c++) {
        const float* xp = xm + ((long)b * NC_ + (c - 1)) * D_;
        float pr[KR_];
#pragma unroll
        for (int r = 0; r < KR_; r++) pr[r] = 0.f;
#pragma unroll
        for (int j = 0; j < 4; j++) {
            const int d = tid + j * 256;
            const float xv = xp[d];
            stp[j] = LAM_ * stp[j] + (1.f - LAM_) * xv;
            StArr[(long)(c * B_ + b) * D_ + d] = stp[j];
#pragma unroll
            for (int r = 0; r < KR_; r++) pr[r] += xv * Ub[d * KR_ + r];
        }
#pragma unroll
        for (int r = 0; r < KR_; r++) part[r * 256 + tid] = pr[r];
        __syncthreads();
        for (int st = 128; st > 0; st >>= 1) {
            if (tid < st)
#pragma unroll
                for (int r = 0; r < KR_; r++) part[r * 256 + tid] += part[r * 256 + tid + st];
            __syncthreads();
        }
        if (tid < KR_) bypArr[(c * B_ + b) * KR_ + tid] = part[tid * 256];
        __syncthreads();
    }
}

// LayerNorm fused with fp16 convert: A[row] = fp16(LN(h))
__global__ __launch_bounds__(256) void k_ln_h16(const float* __restrict__ h,
    const float* __restrict__ g, const float* __restrict__ bta,
    unsigned short* __restrict__ Aout)
{
    const int row = blockIdx.x, tid = threadIdx.x;
    const float* hr = h + (long)row * D_;
    float v[4]; float s = 0.f;
#pragma unroll
    for (int j = 0; j < 4; j++) { v[j] = hr[tid + j * 256]; s += v[j]; }
    __shared__ float red[256];
    red[tid] = s; __syncthreads();
    for (int st = 128; st > 0; st >>= 1) { if (tid < st) red[tid] += red[tid + st]; __syncthreads(); }
    const float mu = red[0] * (1.f / D_);
    __syncthreads();
    float s2 = 0.f;
#pragma unroll
    for (int j = 0; j < 4; j++) { const float d = v[j] - mu; s2 += d * d; }
    red[tid] = s2; __syncthreads();
    for (int st = 128; st > 0; st >>= 1) { if (tid < st) red[tid] += red[tid + st]; __syncthreads(); }
    const float inv = rsqrtf(red[0] * (1.f / D_) + 1e-5f);
    unsigned short* ar = Aout + (long)row * KB_;
#pragma unroll
    for (int j = 0; j < 4; j++) {
        const int c = tid + j * 256;
        const float y = (v[j] - mu) * inv * g[c] + bta[c];
        ar[c] = __half_as_ushort(__float2half_rn(y));
    }
}

// ------------------------------- launch ------------------------------------
extern "C" void kernel_launch(void* const* d_in, const int* in_sizes, int n_in,
                              void* d_out, int out_size)
{
    (void)in_sizes; (void)n_in; (void)out_size;
    const int*   x    = (const int*)  d_in[0];
    const float* emb  = (const float*)d_in[1];
    const float* Wq   = (const float*)d_in[2];
    const float* Wk   = (const float*)d_in[3];
    const float* Wv   = (const float*)d_in[4];
    const float* Wo   = (const float*)d_in[5];
    const float* Ub   = (const float*)d_in[6];
    const float* Vb   = (const float*)d_in[7];
    const float* lng  = (const float*)d_in[8];
    const float* lnb  = (const float*)d_in[9];
    const float* Wout = (const float*)d_in[10];
    const float* bout = (const float*)d_in[11];
    float* outp = (float*)d_out;

    float *ctx, *q, *k, *v, *ov, *h, *at, *Sst, *U, *xm, *bypArr, *StArr;
    unsigned short *Ahf, *Bhf;
    cudaGetSymbolAddress((void**)&ctx,    g_ctx);
    cudaGetSymbolAddress((void**)&q,      g_q);
    cudaGetSymbolAddress((void**)&k,      g_k);
    cudaGetSymbolAddress((void**)&v,      g_v);
    cudaGetSymbolAddress((void**)&ov,     g_out);
    cudaGetSymbolAddress((void**)&h,      g_h);
    cudaGetSymbolAddress((void**)&at,     g_attn);
    cudaGetSymbolAddress((void**)&Sst,    g_Sst);
    cudaGetSymbolAddress((void**)&U,      g_U);
    cudaGetSymbolAddress((void**)&xm,     g_xm);
    cudaGetSymbolAddress((void**)&bypArr, g_bypArr);
    cudaGetSymbolAddress((void**)&StArr,  g_StArr);
    cudaGetSymbolAddress((void**)&Ahf,    g_Ahf);
    cudaGetSymbolAddress((void**)&Bhf,    g_Bhf);

    cudaFuncSetAttribute(vocab_mma, cudaFuncAttributeMaxDynamicSharedMemorySize, GSM);

    // weight transpose+convert (independent of the model chain)
    k_convB<<<dim3(V_ / 32, D_ / 32), 256>>>(Wout, Bhf);

    k_zero<<<(B_ * K_ * D_ + 255) / 256, 256>>>(Sst, B_ * K_ * D_);

    // embedding + causal local-context sum
    k_embed<<<R_, 256>>>(x, emb, ctx);

    // carry stats for all chunks (hoisted out of the serial loop)
    k_xmean<<<dim3(B_, NC_), 256>>>(ctx, xm);
    k_scan<<<B_, 256>>>(xm, Ub, bypArr, StArr);

    // projections (all fp32 SIMT this round)
    gemm128<0,0,EPI_PHI><<<dim3(K_ / 128, R_ / 128, 1), 256>>>(
        ctx, Wq, q, R_, K_, D_, 0, 0, 0);
    gemm128<0,0,EPI_PHI><<<dim3(K_ / 128, R_ / 128, 1), 256>>>(
        ctx, Wk, k, R_, K_, D_, 0, 0, 0);
    gemm128<0,0,EPI_STORE><<<dim3(D_ / 128, R_ / 128, 1), 256>>>(
        ctx, Wv, v, R_, D_, D_, 0, 0, 0);

    // intra-chunk causal linear attention
    gemm128<0,1,EPI_MASK><<<dim3(CH_ / 128, CH_ / 128, B_ * NC_), 256>>>(
        q, k, at, CH_, CH_, K_, (long)CH_ * K_, (long)CH_ * K_, (long)CH_ * CH_);
    gemm128<0,0,EPI_STORE><<<dim3(D_ / 128, CH_ / 128, B_ * NC_), 256>>>(
        at, v, ov, CH_, D_, CH_, (long)CH_ * CH_, (long)CH_ * D_, (long)CH_ * D_);

    // sequential chunk recurrence: 2 launches per chunk
    for (int c = 0; c < NC_; c++) {
        const float* qc = q + (long)c * CH_ * K_;
        const float* kc = k + (long)c * CH_ * K_;
        k_ir<<<dim3(D_ / 128, CH_ / 128, 2 * B_), 256>>>(
            qc, kc, Sst,
            ov + (long)c * CH_ * D_,
            v + (long)c * CH_ * D_, U,
            bypArr + (long)c * B_ * KR_, Vb, StArr + (long)c * B_ * D_);
        gemm128<1,0,EPI_ACC><<<dim3(D_ / 128, K_ / 128, B_), 256>>>(
            kc, U, Sst, K_, D_, CH_, (long)S_ * K_, (long)CH_ * D_, (long)K_ * D_);
    }

    // output projection (fp32), layernorm+fp16, vocab head (fp16 tensor)
    gemm128<0,0,EPI_STORE><<<dim3(D_ / 128, R_ / 128, 1), 256>>>(
        ov, Wo, h, R_, D_, D_, 0, 0, 0);
    k_ln_h16<<<R_, 256>>>(h, lng, lnb, Ahf);
    vocab_mma<<<dim3(R_ / GBM, V_ / GBN), 256, GSM>>>(Ahf, Bhf, bout, outp);
}

// round 11
// speedup vs baseline: 3.8814x; 1.1805x over previous
#include <cuda_runtime.h>
#include <cuda_bf16.h>
#include <cuda_fp16.h>
#include <cstdint>

// ---------------------------------------------------------------------------
// DSRAModel forward. Round 11: fp16 tensor GEMMs for Wv, Wo (row-scaled), and
// vocab. KEY FIX: the fp32 reference's LayerNorm variance OVERFLOWS to inf for
// late chunks (state gain ~2.9e3/chunk -> h ~ 1e19..1e22), zeroing those rows.
// Our LN reconstructs d_ref = alpha*(h_s - mu_s) and squares it in fp32 so we
// saturate exactly where the reference does (R10's 0.5774 = sqrt(1/3) bug).
// ---------------------------------------------------------------------------

static constexpr int B_  = 2;
static constexpr int S_  = 2048;
static constexpr int D_  = 1024;
static constexpr int K_  = 128;
static constexpr int KR_ = 8;
static constexpr int CH_ = 256;
static constexpr int NC_ = 8;
static constexpr int V_  = 32000;
static constexpr int LC_ = 4;
static constexpr int R_  = B_ * S_;
static constexpr float LAM_   = 0.9f;
static constexpr float SCALE_ = 0.08838834764831845f;

// ------------------------------ scratch ------------------------------------
__device__ float g_ctx [R_ * D_];
__device__ float g_q   [R_ * K_];
__device__ float g_k   [R_ * K_];
__device__ float g_v   [R_ * D_];
__device__ float g_out [R_ * D_];
__device__ float g_h   [R_ * D_];
__device__ float g_attn[B_ * NC_ * CH_ * CH_];
__device__ float g_Sst [B_ * K_ * D_];
__device__ float g_U   [B_ * CH_ * D_];
__device__ float g_xm     [B_ * NC_ * D_];
__device__ float g_bypArr [NC_ * B_ * KR_];
__device__ float g_StArr  [NC_ * B_ * D_];
__device__ float g_alpha  [R_];              // per-row max|ov| (LN reconstruction)
// fp16 operands
static constexpr int KB_ = D_;       // 1024
__device__ unsigned short g_ctxh[R_ * D_];   // fp16 ctx (A of Wv gemm)
__device__ unsigned short g_ovh [R_ * D_];   // fp16 row-scaled ov (A of Wo gemm)
__device__ unsigned short g_Ahf [R_ * KB_];  // fp16 LN out (A of vocab gemm)
__device__ unsigned short g_Wvt [D_ * D_];   // fp16 Wv^T
__device__ unsigned short g_Wot [D_ * D_];   // fp16 Wo^T
__device__ unsigned short g_Bhf [V_ * KB_];  // fp16 Wout^T

// ------------------------ PTX helpers (sm_100-safe) ------------------------
__device__ __forceinline__ uint32_t smem_u32(const void* p) {
    uint32_t a;
    asm("{ .reg .u64 t; cvta.to.shared.u64 t, %1; cvt.u32.u64 %0, t; }" : "=r"(a) : "l"(p));
    return a;
}
#define CP16(dst, src)   asm volatile("cp.async.cg.shared.global [%0], [%1], 16;" :: "r"(dst), "l"(src))
#define CP_COMMIT()      asm volatile("cp.async.commit_group;" ::: "memory")
#define CP_WAIT(n)       asm volatile("cp.async.wait_group %0;" :: "n"(n) : "memory")
#define LDSM4(r, addr)                                                          \
    asm volatile("ldmatrix.sync.aligned.m8n8.x4.shared.b16 {%0,%1,%2,%3}, [%4];" \
        : "=r"((r)[0]), "=r"((r)[1]), "=r"((r)[2]), "=r"((r)[3]) : "r"(addr))
#define MMA16816(c, a, b0, b1)                                                  \
    asm volatile("mma.sync.aligned.m16n8k16.row.col.f32.f16.f16.f32 "           \
        "{%0,%1,%2,%3},{%4,%5,%6,%7},{%8,%9},{%0,%1,%2,%3};"                    \
        : "+f"((c)[0]), "+f"((c)[1]), "+f"((c)[2]), "+f"((c)[3])                \
        : "r"((a)[0]), "r"((a)[1]), "r"((a)[2]), "r"((a)[3]), "r"(b0), "r"(b1))

// -------------------- generic fp16 GEMM (mma.sync) -------------------------
static constexpr int GBM = 128, GBN = 128, GBK = 32, NSTG = 3;
static constexpr int KIT  = KB_ / GBK;           // 32
static constexpr int ROWB = 80;
static constexpr int ABYT = GBM * ROWB;
static constexpr int STG  = 2 * ABYT;
static constexpr int GSM  = NSTG * STG;          // 61440

template <bool BIAS>
__global__ __launch_bounds__(256, 2)
void hgemm(const unsigned short* __restrict__ Ahf,
           const unsigned short* __restrict__ Bhf,
           const float* __restrict__ bias, float* __restrict__ C, int Ncols)
{
    extern __shared__ char smem[];
    const uint32_t sb = smem_u32(smem);
    const int tid = threadIdx.x, wid = tid >> 5, lane = tid & 31;
    const int wm = wid >> 2, wn = wid & 3;
    const int m0 = blockIdx.x * GBM;
    const int n0 = blockIdx.y * GBN;

    const unsigned short* Arow = Ahf + (long)m0 * KB_;
    const unsigned short* Brow = Bhf + (long)n0 * KB_;

    const int ldr = tid >> 1, ldc = (tid & 1) * 2;

    auto load_stage = [&](int it, int slot) {
        const int k0 = it * GBK;
        const uint32_t ab = sb + slot * STG;
        const uint32_t bb = ab + ABYT;
        const unsigned short* ga = Arow + (long)ldr * KB_ + k0 + ldc * 8;
        CP16(ab + ldr * ROWB + ldc * 16, ga);
        CP16(ab + ldr * ROWB + (ldc + 1) * 16, ga + 8);
        const unsigned short* gb = Brow + (long)ldr * KB_ + k0 + ldc * 8;
        CP16(bb + ldr * ROWB + ldc * 16, gb);
        CP16(bb + ldr * ROWB + (ldc + 1) * 16, gb + 8);
    };

    uint32_t aoff[4], boff[2];
#pragma unroll
    for (int mt = 0; mt < 4; mt++)
        aoff[mt] = (wm * 64 + mt * 16 + (lane & 15)) * ROWB + (lane >> 4) * 16;
#pragma unroll
    for (int nt2 = 0; nt2 < 2; nt2++)
        boff[nt2] = (wn * 32 + nt2 * 16 + (lane & 7) + ((lane >> 4) << 3)) * ROWB
                  + ((lane >> 3) & 1) * 16;

    float acc[4][4][4];
#pragma unroll
    for (int mt = 0; mt < 4; mt++)
#pragma unroll
        for (int nt = 0; nt < 4; nt++)
#pragma unroll
            for (int e = 0; e < 4; e++) acc[mt][nt][e] = 0.f;

#pragma unroll
    for (int s = 0; s < NSTG - 1; s++) { load_stage(s, s); CP_COMMIT(); }

    for (int i = 0; i < KIT; i++) {
        CP_WAIT(NSTG - 2);
        __syncthreads();
        const int slot = i % NSTG;
        const uint32_t ab = sb + slot * STG;
        const uint32_t bb = ab + ABYT;
#pragma unroll
        for (int ks = 0; ks < 2; ks++) {
            uint32_t af[4][4], bf[2][4];
#pragma unroll
            for (int mt = 0; mt < 4; mt++) LDSM4(af[mt], ab + aoff[mt] + ks * 32);
#pragma unroll
            for (int nt2 = 0; nt2 < 2; nt2++) LDSM4(bf[nt2], bb + boff[nt2] + ks * 32);
#pragma unroll
            for (int mt = 0; mt < 4; mt++)
#pragma unroll
                for (int nt = 0; nt < 4; nt++)
                    MMA16816(acc[mt][nt], af[mt], bf[nt >> 1][(nt & 1) * 2],
                             bf[nt >> 1][(nt & 1) * 2 + 1]);
        }
        __syncthreads();
        if (i + NSTG - 1 < KIT) load_stage(i + NSTG - 1, (i + NSTG - 1) % NSTG);
        CP_COMMIT();
    }

    const int r0 = lane >> 2, c2 = (lane & 3) * 2;
#pragma unroll
    for (int nt = 0; nt < 4; nt++) {
        const int gc = n0 + wn * 32 + nt * 8 + c2;
        float2 bv = {0.f, 0.f};
        if (BIAS) bv = *reinterpret_cast<const float2*>(bias + gc);
#pragma unroll
        for (int mt = 0; mt < 4; mt++) {
            const int gr = m0 + wm * 64 + mt * 16 + r0;
            float2 lo = { acc[mt][nt][0] + bv.x, acc[mt][nt][1] + bv.y };
            float2 hi = { acc[mt][nt][2] + bv.x, acc[mt][nt][3] + bv.y };
            *reinterpret_cast<float2*>(C + (long)gr * Ncols + gc) = lo;
            *reinterpret_cast<float2*>(C + (long)(gr + 8) * Ncols + gc) = hi;
        }
    }
}

// ----------------- weight transpose + fp16 convert -------------------------
__global__ __launch_bounds__(256) void k_convB(const float* __restrict__ W,
                                               unsigned short* __restrict__ Bt, int ncols)
{
    __shared__ float t[32][33];
    const int n0 = blockIdx.x * 32, k0 = blockIdx.y * 32;
    const int tx = threadIdx.x & 31, ty = threadIdx.x >> 5;
#pragma unroll
    for (int j = 0; j < 32; j += 8)
        t[ty + j][tx] = W[(long)(k0 + ty + j) * ncols + n0 + tx];
    __syncthreads();
#pragma unroll
    for (int j = 0; j < 32; j += 8) {
        const int n = ty + j;
        Bt[(long)(n0 + n) * KB_ + k0 + tx] =
            __half_as_ushort(__float2half_rn(t[tx][n]));
    }
}

// ------------------------------ SIMT GEMM ----------------------------------
enum { EPI_STORE = 0, EPI_PHI, EPI_MASK, EPI_ACC };

template <int TRA, int TRB, int EPI>
__global__ __launch_bounds__(256) void gemm128(
    const float* __restrict__ A, const float* __restrict__ Bm, float* __restrict__ C,
    int M, int N, int Kd, long sA, long sB, long sC)
{
    constexpr int BM = 128, BN = 128, BK = 8, TM = 8, TN = 8;
    __shared__ __align__(16) float As[BK][BM];
    __shared__ __align__(16) float Bs[BK][BN];

    const int z = blockIdx.z;
    A  += (long)z * sA;
    Bm += (long)z * sB;
    C  += (long)z * sC;

    const int tid  = threadIdx.x;
    const int row0 = blockIdx.y * BM;
    const int col0 = blockIdx.x * BN;
    const int tRow = tid >> 4;
    const int tCol = tid & 15;

    float acc[TM][TN];
#pragma unroll
    for (int i = 0; i < TM; i++)
#pragma unroll
        for (int j = 0; j < TN; j++) acc[i][j] = 0.f;

    for (int k0 = 0; k0 < Kd; k0 += BK) {
        if (TRA == 0) {
            const int r = tid >> 1, c = (tid & 1) * 4;
            float4 a4 = *reinterpret_cast<const float4*>(A + (long)(row0 + r) * Kd + k0 + c);
            As[c + 0][r] = a4.x; As[c + 1][r] = a4.y;
            As[c + 2][r] = a4.z; As[c + 3][r] = a4.w;
        } else {
            const int r = tid >> 5, c = (tid & 31) * 4;
            *reinterpret_cast<float4*>(&As[r][c]) =
                *reinterpret_cast<const float4*>(A + (long)(k0 + r) * M + row0 + c);
        }
        if (TRB == 0) {
            const int r = tid >> 5, c = (tid & 31) * 4;
            *reinterpret_cast<float4*>(&Bs[r][c]) =
                *reinterpret_cast<const float4*>(Bm + (long)(k0 + r) * N + col0 + c);
        } else {
            const int r = tid >> 1, c = (tid & 1) * 4;
            float4 b4 = *reinterpret_cast<const float4*>(Bm + (long)(col0 + r) * Kd + k0 + c);
            Bs[c + 0][r] = b4.x; Bs[c + 1][r] = b4.y;
            Bs[c + 2][r] = b4.z; Bs[c + 3][r] = b4.w;
        }
        __syncthreads();

#pragma unroll
        for (int kk = 0; kk < BK; kk++) {
            float ra[TM], rb[TN];
            *reinterpret_cast<float4*>(ra)     = *reinterpret_cast<const float4*>(&As[kk][tRow * TM]);
            *reinterpret_cast<float4*>(ra + 4) = *reinterpret_cast<const float4*>(&As[kk][tRow * TM + 4]);
            *reinterpret_cast<float4*>(rb)     = *reinterpret_cast<const float4*>(&Bs[kk][tCol * TN]);
            *reinterpret_cast<float4*>(rb + 4) = *reinterpret_cast<const float4*>(&Bs[kk][tCol * TN + 4]);
#pragma unroll
            for (int i = 0; i < TM; i++)
#pragma unroll
                for (int j = 0; j < TN; j++) acc[i][j] += ra[i] * rb[j];
        }
        __syncthreads();
    }

#pragma unroll
    for (int i = 0; i < TM; i++) {
        const int gr = row0 + tRow * TM + i;
#pragma unroll
        for (int j = 0; j < TN; j++) {
            const int gc = col0 + tCol * TN + j;
            const long idx = (long)gr * N + gc;
            const float vv = acc[i][j];
            if (EPI == EPI_STORE)      C[idx] = vv;
            else if (EPI == EPI_PHI)   C[idx] = (vv > 0.f) ? vv + 1.f : expf(vv);
            else if (EPI == EPI_MASK)  C[idx] = (gc <= gr) ? vv * SCALE_ : 0.f;
            else if (EPI == EPI_ACC)   C[idx] += vv;
        }
    }
}

// -------------- fused INTER+RESID recurrence kernel (per chunk) -------------
__global__ __launch_bounds__(256) void k_ir(
    const float* __restrict__ qc, const float* __restrict__ kc,
    const float* __restrict__ Sst,
    float* __restrict__ ovc,
    const float* __restrict__ vc, float* __restrict__ U,
    const float* __restrict__ bypc, const float* __restrict__ Vb,
    const float* __restrict__ Stc)
{
    constexpr int BM = 128, BN = 128, BK = 8, TM = 8, TN = 8;
    __shared__ __align__(16) float As[BK][BM];
    __shared__ __align__(16) float Bs[BK][BN];

    const int zb   = blockIdx.z & 1;
    const int role = blockIdx.z >> 1;
    const float* A  = (role ? kc : qc) + (long)zb * S_ * K_;
    const float* Bm = Sst + (long)zb * K_ * D_;

    const int tid  = threadIdx.x;
    const int row0 = blockIdx.y * BM;
    const int col0 = blockIdx.x * BN;
    const int tRow = tid >> 4;
    const int tCol = tid & 15;

    float acc[TM][TN];
#pragma unroll
    for (int i = 0; i < TM; i++)
#pragma unroll
        for (int j = 0; j < TN; j++) acc[i][j] = 0.f;

    for (int k0 = 0; k0 < K_; k0 += BK) {
        {
            const int r = tid >> 1, c = (tid & 1) * 4;
            float4 a4 = *reinterpret_cast<const float4*>(A + (long)(row0 + r) * K_ + k0 + c);
            As[c + 0][r] = a4.x; As[c + 1][r] = a4.y;
            As[c + 2][r] = a4.z; As[c + 3][r] = a4.w;
        }
        {
            const int r = tid >> 5, c = (tid & 31) * 4;
            *reinterpret_cast<float4*>(&Bs[r][c]) =
                *reinterpret_cast<const float4*>(Bm + (long)(k0 + r) * D_ + col0 + c);
        }
        __syncthreads();
#pragma unroll
        for (int kk = 0; kk < BK; kk++) {
            float ra[TM], rb[TN];
            *reinterpret_cast<float4*>(ra)     = *reinterpret_cast<const float4*>(&As[kk][tRow * TM]);
            *reinterpret_cast<float4*>(ra + 4) = *reinterpret_cast<const float4*>(&As[kk][tRow * TM + 4]);
            *reinterpret_cast<float4*>(rb)     = *reinterpret_cast<const float4*>(&Bs[kk][tCol * TN]);
            *reinterpret_cast<float4*>(rb + 4) = *reinterpret_cast<const float4*>(&Bs[kk][tCol * TN + 4]);
#pragma unroll
            for (int i = 0; i < TM; i++)
#pragma unroll
                for (int j = 0; j < TN; j++) acc[i][j] += ra[i] * rb[j];
        }
        __syncthreads();
    }

    if (role == 0) {
        float addc[TN];
#pragma unroll
        for (int j = 0; j < TN; j++) {
            const int gc = col0 + tCol * TN + j;
            float bv = 0.f;
#pragma unroll
            for (int r = 0; r < KR_; r++) bv += bypc[zb * KR_ + r] * Vb[r * D_ + gc];
            addc[j] = bv + Stc[zb * D_ + gc];
        }
#pragma unroll
        for (int i = 0; i < TM; i++) {
            const int gr = row0 + tRow * TM + i;
#pragma unroll
            for (int j = 0; j < TN; j++) {
                const int gc = col0 + tCol * TN + j;
                const long o = (long)zb * S_ * D_ + (long)gr * D_ + gc;
                ovc[o] += acc[i][j] * SCALE_ + addc[j];
            }
        }
    } else {
#pragma unroll
        for (int i = 0; i < TM; i++) {
            const int gr = row0 + tRow * TM + i;
#pragma unroll
            for (int j = 0; j < TN; j++) {
                const int gc = col0 + tCol * TN + j;
                U[(long)zb * CH_ * D_ + (long)gr * D_ + gc] =
                    vc[(long)zb * S_ * D_ + (long)gr * D_ + gc] - acc[i][j] * SCALE_;
            }
        }
    }
}

// --------------------------- small kernels ---------------------------------
__global__ void k_zero(float* __restrict__ p, int n)
{
    const int i = blockIdx.x * blockDim.x + threadIdx.x;
    if (i < n) p[i] = 0.f;
}

__global__ __launch_bounds__(256) void k_embed(const int* __restrict__ x,
    const float* __restrict__ emb, float* __restrict__ ctx,
    unsigned short* __restrict__ ctxh)
{
    const int row = blockIdx.x;
    const int b = row / S_, s = row % S_;
    const int tid = threadIdx.x;
    float acc[4] = {0.f, 0.f, 0.f, 0.f};
    for (int off = 0; off < LC_; off++) {
        const int sp = s - off;
        if (sp < 0) break;
        const float* er = emb + (long)x[b * S_ + sp] * D_;
#pragma unroll
        for (int j = 0; j < 4; j++) acc[j] += er[tid + j * 256];
    }
    float* cr = ctx + (long)row * D_;
    unsigned short* ch = ctxh + (long)row * D_;
#pragma unroll
    for (int j = 0; j < 4; j++) {
        cr[tid + j * 256] = acc[j];
        ch[tid + j * 256] = __half_as_ushort(__float2half_rn(acc[j]));
    }
}

// per-chunk mean, tiled: grid (B, NC, 8)
__global__ __launch_bounds__(256) void k_xmean(const float* __restrict__ ctx,
                                               float* __restrict__ xm)
{
    const int b = blockIdx.x, c = blockIdx.y, seg = blockIdx.z;
    const int tid = threadIdx.x;
    const int d = seg * 128 + (tid & 127);
    const int half = tid >> 7;
    const float* base = ctx + ((long)b * S_ + (long)c * CH_ + half * 128) * D_;
    float s = 0.f;
    for (int i = 0; i < 128; i++) s += base[(long)i * D_ + d];
    __shared__ float red[256];
    red[tid] = s;
    __syncthreads();
    if (half == 0)
        xm[((long)b * NC_ + c) * D_ + d] = (red[tid] + red[tid + 128]) * (1.0f / CH_);
}

__global__ __launch_bounds__(256) void k_scan(const float* __restrict__ xm,
    const float* __restrict__ Ub, float* __restrict__ bypArr, float* __restrict__ StArr)
{
    const int b = blockIdx.x, tid = threadIdx.x;
    __shared__ float part[KR_ * 256];
    float stp[4] = {0.f, 0.f, 0.f, 0.f};
#pragma unroll
    for (int j = 0; j < 4; j++) StArr[(long)(0 * B_ + b) * D_ + tid + j * 256] = 0.f;
    if (tid < KR_) bypArr[(0 * B_ + b) * KR_ + tid] = 0.f;

    for (int c = 1; c < NC_; c++) {
        const float* xp = xm + ((long)b * NC_ + (c - 1)) * D_;
        float pr[KR_];
#pragma unroll
        for (int r = 0; r < KR_; r++) pr[r] = 0.f;
#pragma unroll
        for (int j = 0; j < 4; j++) {
            const int d = tid + j * 256;
            const float xv = xp[d];
            stp[j] = LAM_ * stp[j] + (1.f - LAM_) * xv;
            StArr[(long)(c * B_ + b) * D_ + d] = stp[j];
#pragma unroll
            for (int r = 0; r < KR_; r++) pr[r] += xv * Ub[d * KR_ + r];
        }
#pragma unroll
        for (int r = 0; r < KR_; r++) part[r * 256 + tid] = pr[r];
        __syncthreads();
        for (int st = 128; st > 0; st >>= 1) {
            if (tid < st)
#pragma unroll
                for (int r = 0; r < KR_; r++) part[r * 256 + tid] += part[r * 256 + tid + st];
            __syncthreads();
        }
        if (tid < KR_) bypArr[(c * B_ + b) * KR_ + tid] = part[tid * 256];
        __syncthreads();
    }
}

// per-row max-abs normalization + fp16 convert; also stores alpha = rowmax
__global__ __launch_bounds__(256) void k_rowscale_h16(const float* __restrict__ ov,
    unsigned short* __restrict__ ovh, float* __restrict__ alpha)
{
    const int row = blockIdx.x, tid = threadIdx.x;
    const float* r = ov + (long)row * D_;
    float v[4]; float mx = 0.f;
#pragma unroll
    for (int j = 0; j < 4; j++) { v[j] = r[tid + j * 256]; mx = fmaxf(mx, fabsf(v[j])); }
    __shared__ float red[256];
    red[tid] = mx; __syncthreads();
    for (int st = 128; st > 0; st >>= 1) {
        if (tid < st) red[tid] = fmaxf(red[tid], red[tid + st]);
        __syncthreads();
    }
    const float a = fmaxf(red[0], 1e-30f);
    if (tid == 0) alpha[row] = a;
    const float inv = 1.0f / a;
    unsigned short* o = ovh + (long)row * D_;
#pragma unroll
    for (int j = 0; j < 4; j++)
        o[tid + j * 256] = __half_as_ushort(__float2half_rn(v[j] * inv));
}

// LayerNorm on scaled h, reconstructing REFERENCE arithmetic:
// d_ref = alpha*(h_s - mu_s); var_ref = mean(d_ref^2)  (overflows to inf
// exactly where fp32 reference does -> hn = 0, matching jax saturation);
// hn = d_ref * rsqrt(var_ref + 1e-5) * g + b; store fp16.
__global__ __launch_bounds__(256) void k_ln_alpha(const float* __restrict__ h,
    const float* __restrict__ alpha,
    const float* __restrict__ g, const float* __restrict__ bta,
    unsigned short* __restrict__ Aout)
{
    const int row = blockIdx.x, tid = threadIdx.x;
    const float a = alpha[row];
    const float* hr = h + (long)row * D_;
    float v[4]; float s = 0.f;
#pragma unroll
    for (int j = 0; j < 4; j++) { v[j] = hr[tid + j * 256]; s += v[j]; }
    __shared__ float red[256];
    red[tid] = s; __syncthreads();
    for (int st = 128; st > 0; st >>= 1) { if (tid < st) red[tid] += red[tid + st]; __syncthreads(); }
    const float mu = red[0] * (1.f / D_);
    __syncthreads();
    float dref[4]; float s2 = 0.f;
#pragma unroll
    for (int j = 0; j < 4; j++) {
        dref[j] = a * (v[j] - mu);          // = h_ref - mu_ref (finite)
        s2 += dref[j] * dref[j];            // may overflow to inf like the reference
    }
    red[tid] = s2; __syncthreads();
    for (int st = 128; st > 0; st >>= 1) { if (tid < st) red[tid] += red[tid + st]; __syncthreads(); }
    const float inv = rsqrtf(red[0] * (1.f / D_) + 1e-5f);   // inf -> 0 (saturation)
    unsigned short* ar = Aout + (long)row * KB_;
#pragma unroll
    for (int j = 0; j < 4; j++) {
        const int c = tid + j * 256;
        const float y = dref[j] * inv * g[c] + bta[c];
        ar[c] = __half_as_ushort(__float2half_rn(y));
    }
}

// ------------------------------- launch ------------------------------------
extern "C" void kernel_launch(void* const* d_in, const int* in_sizes, int n_in,
                              void* d_out, int out_size)
{
    (void)in_sizes; (void)n_in; (void)out_size;
    const int*   x    = (const int*)  d_in[0];
    const float* emb  = (const float*)d_in[1];
    const float* Wq   = (const float*)d_in[2];
    const float* Wk   = (const float*)d_in[3];
    const float* Wv   = (const float*)d_in[4];
    const float* Wo   = (const float*)d_in[5];
    const float* Ub   = (const float*)d_in[6];
    const float* Vb   = (const float*)d_in[7];
    const float* lng  = (const float*)d_in[8];
    const float* lnb  = (const float*)d_in[9];
    const float* Wout = (const float*)d_in[10];
    const float* bout = (const float*)d_in[11];
    float* outp = (float*)d_out;

    float *ctx, *q, *k, *v, *ov, *h, *at, *Sst, *U, *xm, *bypArr, *StArr, *alpha;
    unsigned short *ctxh, *ovh, *Ahf, *Wvt, *Wot, *Bhf;
    cudaGetSymbolAddress((void**)&ctx,    g_ctx);
    cudaGetSymbolAddress((void**)&q,      g_q);
    cudaGetSymbolAddress((void**)&k,      g_k);
    cudaGetSymbolAddress((void**)&v,      g_v);
    cudaGetSymbolAddress((void**)&ov,     g_out);
    cudaGetSymbolAddress((void**)&h,      g_h);
    cudaGetSymbolAddress((void**)&at,     g_attn);
    cudaGetSymbolAddress((void**)&Sst,    g_Sst);
    cudaGetSymbolAddress((void**)&U,      g_U);
    cudaGetSymbolAddress((void**)&xm,     g_xm);
    cudaGetSymbolAddress((void**)&bypArr, g_bypArr);
    cudaGetSymbolAddress((void**)&StArr,  g_StArr);
    cudaGetSymbolAddress((void**)&alpha,  g_alpha);
    cudaGetSymbolAddress((void**)&ctxh,   g_ctxh);
    cudaGetSymbolAddress((void**)&ovh,    g_ovh);
    cudaGetSymbolAddress((void**)&Ahf,    g_Ahf);
    cudaGetSymbolAddress((void**)&Wvt,    g_Wvt);
    cudaGetSymbolAddress((void**)&Wot,    g_Wot);
    cudaGetSymbolAddress((void**)&Bhf,    g_Bhf);

    cudaFuncSetAttribute(hgemm<true>,  cudaFuncAttributeMaxDynamicSharedMemorySize, GSM);
    cudaFuncSetAttribute(hgemm<false>, cudaFuncAttributeMaxDynamicSharedMemorySize, GSM);

    // weight conversions (independent of the model chain)
    k_convB<<<dim3(V_ / 32, D_ / 32), 256>>>(Wout, Bhf, V_);
    k_convB<<<dim3(D_ / 32, D_ / 32), 256>>>(Wv, Wvt, D_);
    k_convB<<<dim3(D_ / 32, D_ / 32), 256>>>(Wo, Wot, D_);

    k_zero<<<(B_ * K_ * D_ + 255) / 256, 256>>>(Sst, B_ * K_ * D_);

    // embedding + causal local-context sum (fp32 + fp16)
    k_embed<<<R_, 256>>>(x, emb, ctx, ctxh);

    // carry stats for all chunks (hoisted out of the serial loop)
    k_xmean<<<dim3(B_, NC_, 8), 256>>>(ctx, xm);
    k_scan<<<B_, 256>>>(xm, Ub, bypArr, StArr);

    // projections: Q,K fp32 SIMT; V fp16 tensor
    gemm128<0,0,EPI_PHI><<<dim3(K_ / 128, R_ / 128, 1), 256>>>(
        ctx, Wq, q, R_, K_, D_, 0, 0, 0);
    gemm128<0,0,EPI_PHI><<<dim3(K_ / 128, R_ / 128, 1), 256>>>(
        ctx, Wk, k, R_, K_, D_, 0, 0, 0);
    hgemm<false><<<dim3(R_ / GBM, D_ / GBN), 256, GSM>>>(ctxh, Wvt, nullptr, v, D_);

    // intra-chunk causal linear attention
    gemm128<0,1,EPI_MASK><<<dim3(CH_ / 128, CH_ / 128, B_ * NC_), 256>>>(
        q, k, at, CH_, CH_, K_, (long)CH_ * K_, (long)CH_ * K_, (long)CH_ * CH_);
    gemm128<0,0,EPI_STORE><<<dim3(D_ / 128, CH_ / 128, B_ * NC_), 256>>>(
        at, v, ov, CH_, D_, CH_, (long)CH_ * CH_, (long)CH_ * D_, (long)CH_ * D_);

    // sequential chunk recurrence: 2 launches per chunk
    for (int c = 0; c < NC_; c++) {
        const float* qc = q + (long)c * CH_ * K_;
        const float* kc = k + (long)c * CH_ * K_;
        k_ir<<<dim3(D_ / 128, CH_ / 128, 2 * B_), 256>>>(
            qc, kc, Sst,
            ov + (long)c * CH_ * D_,
            v + (long)c * CH_ * D_, U,
            bypArr + (long)c * B_ * KR_, Vb, StArr + (long)c * B_ * D_);
        gemm128<1,0,EPI_ACC><<<dim3(D_ / 128, K_ / 128, B_), 256>>>(
            kc, U, Sst, K_, D_, CH_, (long)S_ * K_, (long)CH_ * D_, (long)K_ * D_);
    }

    // row-scale ov -> fp16 (+alpha), Wo (fp16 tensor), LN w/ saturation, vocab
    k_rowscale_h16<<<R_, 256>>>(ov, ovh, alpha);
    hgemm<false><<<dim3(R_ / GBM, D_ / GBN), 256, GSM>>>(ovh, Wot, nullptr, h, D_);
    k_ln_alpha<<<R_, 256>>>(h, alpha, lng, lnb, Ahf);
    hgemm<true><<<dim3(R_ / GBM, V_ / GBN), 256, GSM>>>(Ahf, Bhf, bout, outp, V_);
}

// round 12
// speedup vs baseline: 4.4833x; 1.1551x over previous
#include <cuda_runtime.h>
#include <cuda_bf16.h>
#include <cuda_fp16.h>
#include <cstdint>

// ---------------------------------------------------------------------------
// DSRAModel forward. Round 12: R11 + (a) merged Q/K projection launch,
// (b) chunk-0 recurrence skip (S=0 => U=v, INTER adds 0), (c) fp16 tensor
// intra-chunk at@v (generalized hgemm<KDIM>, fp16 'at' from MASK epilogue,
// fp16 v^T via smem transpose). LN saturation reconstruction retained.
// ---------------------------------------------------------------------------

static constexpr int B_  = 2;
static constexpr int S_  = 2048;
static constexpr int D_  = 1024;
static constexpr int K_  = 128;
static constexpr int KR_ = 8;
static constexpr int CH_ = 256;
static constexpr int NC_ = 8;
static constexpr int V_  = 32000;
static constexpr int LC_ = 4;
static constexpr int R_  = B_ * S_;
static constexpr float LAM_   = 0.9f;
static constexpr float SCALE_ = 0.08838834764831845f;

// ------------------------------ scratch ------------------------------------
__device__ float g_ctx [R_ * D_];
__device__ float g_qk  [2 * R_ * K_];        // q then k, contiguous
__device__ float g_v   [R_ * D_];
__device__ float g_out [R_ * D_];
__device__ float g_h   [R_ * D_];
__device__ float g_Sst [B_ * K_ * D_];
__device__ float g_U   [B_ * CH_ * D_];
__device__ float g_xm     [B_ * NC_ * D_];
__device__ float g_bypArr [NC_ * B_ * KR_];
__device__ float g_StArr  [NC_ * B_ * D_];
__device__ float g_alpha  [R_];
__device__ float g_Wqk [2 * D_ * K_];        // [Wq ; Wk]
// fp16 operands
static constexpr int KB_ = D_;
__device__ unsigned short g_ctxh[R_ * D_];
__device__ unsigned short g_ovh [R_ * D_];
__device__ unsigned short g_Ahf [R_ * KB_];
__device__ unsigned short g_Wvt [D_ * D_];
__device__ unsigned short g_Wot [D_ * D_];
__device__ unsigned short g_Bhf [V_ * KB_];
__device__ unsigned short g_ath [B_ * NC_ * CH_ * CH_];  // fp16 masked attn
__device__ unsigned short g_vhT [B_ * NC_ * D_ * CH_];   // fp16 v^T per chunk

// ------------------------ PTX helpers (sm_100-safe) ------------------------
__device__ __forceinline__ uint32_t smem_u32(const void* p) {
    uint32_t a;
    asm("{ .reg .u64 t; cvta.to.shared.u64 t, %1; cvt.u32.u64 %0, t; }" : "=r"(a) : "l"(p));
    return a;
}
#define CP16(dst, src)   asm volatile("cp.async.cg.shared.global [%0], [%1], 16;" :: "r"(dst), "l"(src))
#define CP_COMMIT()      asm volatile("cp.async.commit_group;" ::: "memory")
#define CP_WAIT(n)       asm volatile("cp.async.wait_group %0;" :: "n"(n) : "memory")
#define LDSM4(r, addr)                                                          \
    asm volatile("ldmatrix.sync.aligned.m8n8.x4.shared.b16 {%0,%1,%2,%3}, [%4];" \
        : "=r"((r)[0]), "=r"((r)[1]), "=r"((r)[2]), "=r"((r)[3]) : "r"(addr))
#define MMA16816(c, a, b0, b1)                                                  \
    asm volatile("mma.sync.aligned.m16n8k16.row.col.f32.f16.f16.f32 "           \
        "{%0,%1,%2,%3},{%4,%5,%6,%7},{%8,%9},{%0,%1,%2,%3};"                    \
        : "+f"((c)[0]), "+f"((c)[1]), "+f"((c)[2]), "+f"((c)[3])                \
        : "r"((a)[0]), "r"((a)[1]), "r"((a)[2]), "r"((a)[3]), "r"(b0), "r"(b1))

// ---------------- generalized fp16 GEMM (mma.sync, z-batched) ---------------
// C[M,Ncols] = A[M,KDIM] @ B[Ncols,KDIM]^T (+bias), fp16 K-major operands.
static constexpr int GBM = 128, GBN = 128, GBK = 32, NSTG = 3;
static constexpr int ROWB = 80;
static constexpr int ABYT = GBM * ROWB;
static constexpr int STG  = 2 * ABYT;
static constexpr int GSM  = NSTG * STG;          // 61440

template <int KDIM, bool BIAS>
__global__ __launch_bounds__(256, 2)
void hgemm(const unsigned short* __restrict__ A,
           const unsigned short* __restrict__ B,
           const float* __restrict__ bias, float* __restrict__ C, int Ncols,
           long sA, long sB, long sC)
{
    constexpr int KIT = KDIM / GBK;
    extern __shared__ char smem[];
    const uint32_t sb = smem_u32(smem);
    const int tid = threadIdx.x, wid = tid >> 5, lane = tid & 31;
    const int wm = wid >> 2, wn = wid & 3;
    const int z  = blockIdx.z;
    const int m0 = blockIdx.x * GBM;
    const int n0 = blockIdx.y * GBN;
    A += (long)z * sA; B += (long)z * sB; C += (long)z * sC;

    const unsigned short* Arow = A + (long)m0 * KDIM;
    const unsigned short* Brow = B + (long)n0 * KDIM;

    const int ldr = tid >> 1, ldc = (tid & 1) * 2;

    auto load_stage = [&](int it, int slot) {
        const int k0 = it * GBK;
        const uint32_t ab = sb + slot * STG;
        const uint32_t bb = ab + ABYT;
        const unsigned short* ga = Arow + (long)ldr * KDIM + k0 + ldc * 8;
        CP16(ab + ldr * ROWB + ldc * 16, ga);
        CP16(ab + ldr * ROWB + (ldc + 1) * 16, ga + 8);
        const unsigned short* gb = Brow + (long)ldr * KDIM + k0 + ldc * 8;
        CP16(bb + ldr * ROWB + ldc * 16, gb);
        CP16(bb + ldr * ROWB + (ldc + 1) * 16, gb + 8);
    };

    uint32_t aoff[4], boff[2];
#pragma unroll
    for (int mt = 0; mt < 4; mt++)
        aoff[mt] = (wm * 64 + mt * 16 + (lane & 15)) * ROWB + (lane >> 4) * 16;
#pragma unroll
    for (int nt2 = 0; nt2 < 2; nt2++)
        boff[nt2] = (wn * 32 + nt2 * 16 + (lane & 7) + ((lane >> 4) << 3)) * ROWB
                  + ((lane >> 3) & 1) * 16;

    float acc[4][4][4];
#pragma unroll
    for (int mt = 0; mt < 4; mt++)
#pragma unroll
        for (int nt = 0; nt < 4; nt++)
#pragma unroll
            for (int e = 0; e < 4; e++) acc[mt][nt][e] = 0.f;

#pragma unroll
    for (int s = 0; s < NSTG - 1; s++) { load_stage(s, s); CP_COMMIT(); }

    for (int i = 0; i < KIT; i++) {
        CP_WAIT(NSTG - 2);
        __syncthreads();
        const int slot = i % NSTG;
        const uint32_t ab = sb + slot * STG;
        const uint32_t bb = ab + ABYT;
#pragma unroll
        for (int ks = 0; ks < 2; ks++) {
            uint32_t af[4][4], bf[2][4];
#pragma unroll
            for (int mt = 0; mt < 4; mt++) LDSM4(af[mt], ab + aoff[mt] + ks * 32);
#pragma unroll
            for (int nt2 = 0; nt2 < 2; nt2++) LDSM4(bf[nt2], bb + boff[nt2] + ks * 32);
#pragma unroll
            for (int mt = 0; mt < 4; mt++)
#pragma unroll
                for (int nt = 0; nt < 4; nt++)
                    MMA16816(acc[mt][nt], af[mt], bf[nt >> 1][(nt & 1) * 2],
                             bf[nt >> 1][(nt & 1) * 2 + 1]);
        }
        __syncthreads();
        if (i + NSTG - 1 < KIT) load_stage(i + NSTG - 1, (i + NSTG - 1) % NSTG);
        CP_COMMIT();
    }

    const int r0 = lane >> 2, c2 = (lane & 3) * 2;
#pragma unroll
    for (int nt = 0; nt < 4; nt++) {
        const int gc = n0 + wn * 32 + nt * 8 + c2;
        float2 bv = {0.f, 0.f};
        if (BIAS) bv = *reinterpret_cast<const float2*>(bias + gc);
#pragma unroll
        for (int mt = 0; mt < 4; mt++) {
            const int gr = m0 + wm * 64 + mt * 16 + r0;
            float2 lo = { acc[mt][nt][0] + bv.x, acc[mt][nt][1] + bv.y };
            float2 hi = { acc[mt][nt][2] + bv.x, acc[mt][nt][3] + bv.y };
            *reinterpret_cast<float2*>(C + (long)gr * Ncols + gc) = lo;
            *reinterpret_cast<float2*>(C + (long)(gr + 8) * Ncols + gc) = hi;
        }
    }
}

// ----------------- weight transpose + fp16 convert -------------------------
__global__ __launch_bounds__(256) void k_convB(const float* __restrict__ W,
                                               unsigned short* __restrict__ Bt, int ncols)
{
    __shared__ float t[32][33];
    const int n0 = blockIdx.x * 32, k0 = blockIdx.y * 32;
    const int tx = threadIdx.x & 31, ty = threadIdx.x >> 5;
#pragma unroll
    for (int j = 0; j < 32; j += 8)
        t[ty + j][tx] = W[(long)(k0 + ty + j) * ncols + n0 + tx];
    __syncthreads();
#pragma unroll
    for (int j = 0; j < 32; j += 8) {
        const int n = ty + j;
        Bt[(long)(n0 + n) * KB_ + k0 + tx] =
            __half_as_ushort(__float2half_rn(t[tx][n]));
    }
}

// v [R,D] fp32 -> vhT [16][D][CH] fp16 (per-chunk transpose)
__global__ __launch_bounds__(256) void k_convVT(const float* __restrict__ v,
                                                unsigned short* __restrict__ vhT)
{
    __shared__ float sm[32][33];
    const int d0 = blockIdx.x * 32, t0 = blockIdx.y * 32, z = blockIdx.z;
    const int tx = threadIdx.x & 31, ty = threadIdx.x >> 5;
#pragma unroll
    for (int j = 0; j < 32; j += 8)
        sm[ty + j][tx] = v[((long)z * CH_ + t0 + ty + j) * D_ + d0 + tx];
    __syncthreads();
#pragma unroll
    for (int j = 0; j < 32; j += 8)
        vhT[((long)z * D_ + d0 + ty + j) * CH_ + t0 + tx] =
            __half_as_ushort(__float2half_rn(sm[tx][ty + j]));
}

// ------------------------------ SIMT GEMM ----------------------------------
enum { EPI_STORE = 0, EPI_PHI, EPI_MASKH, EPI_ACC };

template <int TRA, int TRB, int EPI>
__global__ __launch_bounds__(256) void gemm128(
    const float* __restrict__ A, const float* __restrict__ Bm, float* __restrict__ C,
    int M, int N, int Kd, long sA, long sB, long sC)
{
    constexpr int BM = 128, BN = 128, BK = 8, TM = 8, TN = 8;
    __shared__ __align__(16) float As[BK][BM];
    __shared__ __align__(16) float Bs[BK][BN];

    const int z = blockIdx.z;
    A  += (long)z * sA;
    Bm += (long)z * sB;
    C  += (long)z * sC;      // for EPI_MASKH, sC is given in FLOAT units

    const int tid  = threadIdx.x;
    const int row0 = blockIdx.y * BM;
    const int col0 = blockIdx.x * BN;
    const int tRow = tid >> 4;
    const int tCol = tid & 15;

    float acc[TM][TN];
#pragma unroll
    for (int i = 0; i < TM; i++)
#pragma unroll
        for (int j = 0; j < TN; j++) acc[i][j] = 0.f;

    for (int k0 = 0; k0 < Kd; k0 += BK) {
        if (TRA == 0) {
            const int r = tid >> 1, c = (tid & 1) * 4;
            float4 a4 = *reinterpret_cast<const float4*>(A + (long)(row0 + r) * Kd + k0 + c);
            As[c + 0][r] = a4.x; As[c + 1][r] = a4.y;
            As[c + 2][r] = a4.z; As[c + 3][r] = a4.w;
        } else {
            const int r = tid >> 5, c = (tid & 31) * 4;
            *reinterpret_cast<float4*>(&As[r][c]) =
                *reinterpret_cast<const float4*>(A + (long)(k0 + r) * M + row0 + c);
        }
        if (TRB == 0) {
            const int r = tid >> 5, c = (tid & 31) * 4;
            *reinterpret_cast<float4*>(&Bs[r][c]) =
                *reinterpret_cast<const float4*>(Bm + (long)(k0 + r) * N + col0 + c);
        } else {
            const int r = tid >> 1, c = (tid & 1) * 4;
            float4 b4 = *reinterpret_cast<const float4*>(Bm + (long)(col0 + r) * Kd + k0 + c);
            Bs[c + 0][r] = b4.x; Bs[c + 1][r] = b4.y;
            Bs[c + 2][r] = b4.z; Bs[c + 3][r] = b4.w;
        }
        __syncthreads();

#pragma unroll
        for (int kk = 0; kk < BK; kk++) {
            float ra[TM], rb[TN];
            *reinterpret_cast<float4*>(ra)     = *reinterpret_cast<const float4*>(&As[kk][tRow * TM]);
            *reinterpret_cast<float4*>(ra + 4) = *reinterpret_cast<const float4*>(&As[kk][tRow * TM + 4]);
            *reinterpret_cast<float4*>(rb)     = *reinterpret_cast<const float4*>(&Bs[kk][tCol * TN]);
            *reinterpret_cast<float4*>(rb + 4) = *reinterpret_cast<const float4*>(&Bs[kk][tCol * TN + 4]);
#pragma unroll
            for (int i = 0; i < TM; i++)
#pragma unroll
                for (int j = 0; j < TN; j++) acc[i][j] += ra[i] * rb[j];
        }
        __syncthreads();
    }

#pragma unroll
    for (int i = 0; i < TM; i++) {
        const int gr = row0 + tRow * TM + i;
#pragma unroll
        for (int j = 0; j < TN; j++) {
            const int gc = col0 + tCol * TN + j;
            const long idx = (long)gr * N + gc;
            const float vv = acc[i][j];
            if (EPI == EPI_STORE)      C[idx] = vv;
            else if (EPI == EPI_PHI)   C[idx] = (vv > 0.f) ? vv + 1.f : expf(vv);
            else if (EPI == EPI_MASKH)
                reinterpret_cast<unsigned short*>(C)[idx] =
                    __half_as_ushort(__float2half_rn((gc <= gr) ? vv * SCALE_ : 0.f));
            else if (EPI == EPI_ACC)   C[idx] += vv;
        }
    }
}

// -------------- fused INTER+RESID recurrence kernel (per chunk) -------------
__global__ __launch_bounds__(256) void k_ir(
    const float* __restrict__ qc, const float* __restrict__ kc,
    const float* __restrict__ Sst,
    float* __restrict__ ovc,
    const float* __restrict__ vc, float* __restrict__ U,
    const float* __restrict__ bypc, const float* __restrict__ Vb,
    const float* __restrict__ Stc)
{
    constexpr int BM = 128, BN = 128, BK = 8, TM = 8, TN = 8;
    __shared__ __align__(16) float As[BK][BM];
    __shared__ __align__(16) float Bs[BK][BN];

    const int zb   = blockIdx.z & 1;
    const int role = blockIdx.z >> 1;
    const float* A  = (role ? kc : qc) + (long)zb * S_ * K_;
    const float* Bm = Sst + (long)zb * K_ * D_;

    const int tid  = threadIdx.x;
    const int row0 = blockIdx.y * BM;
    const int col0 = blockIdx.x * BN;
    const int tRow = tid >> 4;
    const int tCol = tid & 15;

    float acc[TM][TN];
#pragma unroll
    for (int i = 0; i < TM; i++)
#pragma unroll
        for (int j = 0; j < TN; j++) acc[i][j] = 0.f;

    for (int k0 = 0; k0 < K_; k0 += BK) {
        {
            const int r = tid >> 1, c = (tid & 1) * 4;
            float4 a4 = *reinterpret_cast<const float4*>(A + (long)(row0 + r) * K_ + k0 + c);
            As[c + 0][r] = a4.x; As[c + 1][r] = a4.y;
            As[c + 2][r] = a4.z; As[c + 3][r] = a4.w;
        }
        {
            const int r = tid >> 5, c = (tid & 31) * 4;
            *reinterpret_cast<float4*>(&Bs[r][c]) =
                *reinterpret_cast<const float4*>(Bm + (long)(k0 + r) * D_ + col0 + c);
        }
        __syncthreads();
#pragma unroll
        for (int kk = 0; kk < BK; kk++) {
            float ra[TM], rb[TN];
            *reinterpret_cast<float4*>(ra)     = *reinterpret_cast<const float4*>(&As[kk][tRow * TM]);
            *reinterpret_cast<float4*>(ra + 4) = *reinterpret_cast<const float4*>(&As[kk][tRow * TM + 4]);
            *reinterpret_cast<float4*>(rb)     = *reinterpret_cast<const float4*>(&Bs[kk][tCol * TN]);
            *reinterpret_cast<float4*>(rb + 4) = *reinterpret_cast<const float4*>(&Bs[kk][tCol * TN + 4]);
#pragma unroll
            for (int i = 0; i < TM; i++)
#pragma unroll
                for (int j = 0; j < TN; j++) acc[i][j] += ra[i] * rb[j];
        }
        __syncthreads();
    }

    if (role == 0) {
        float addc[TN];
#pragma unroll
        for (int j = 0; j < TN; j++) {
            const int gc = col0 + tCol * TN + j;
            float bv = 0.f;
#pragma unroll
            for (int r = 0; r < KR_; r++) bv += bypc[zb * KR_ + r] * Vb[r * D_ + gc];
            addc[j] = bv + Stc[zb * D_ + gc];
        }
#pragma unroll
        for (int i = 0; i < TM; i++) {
            const int gr = row0 + tRow * TM + i;
#pragma unroll
            for (int j = 0; j < TN; j++) {
                const int gc = col0 + tCol * TN + j;
                const long o = (long)zb * S_ * D_ + (long)gr * D_ + gc;
                ovc[o] += acc[i][j] * SCALE_ + addc[j];
            }
        }
    } else {
#pragma unroll
        for (int i = 0; i < TM; i++) {
            const int gr = row0 + tRow * TM + i;
#pragma unroll
            for (int j = 0; j < TN; j++) {
                const int gc = col0 + tCol * TN + j;
                U[(long)zb * CH_ * D_ + (long)gr * D_ + gc] =
                    vc[(long)zb * S_ * D_ + (long)gr * D_ + gc] - acc[i][j] * SCALE_;
            }
        }
    }
}

// --------------------------- small kernels ---------------------------------
__global__ void k_zero(float* __restrict__ p, int n)
{
    const int i = blockIdx.x * blockDim.x + threadIdx.x;
    if (i < n) p[i] = 0.f;
}

__global__ void k_pack(const float* __restrict__ Wq, const float* __restrict__ Wk,
                       float* __restrict__ Wqk)
{
    const int i = blockIdx.x * 256 + threadIdx.x;
    Wqk[i] = Wq[i];
    Wqk[D_ * K_ + i] = Wk[i];
}

__global__ __launch_bounds__(256) void k_embed(const int* __restrict__ x,
    const float* __restrict__ emb, float* __restrict__ ctx,
    unsigned short* __restrict__ ctxh)
{
    const int row = blockIdx.x;
    const int b = row / S_, s = row % S_;
    const int tid = threadIdx.x;
    float acc[4] = {0.f, 0.f, 0.f, 0.f};
    for (int off = 0; off < LC_; off++) {
        const int sp = s - off;
        if (sp < 0) break;
        const float* er = emb + (long)x[b * S_ + sp] * D_;
#pragma unroll
        for (int j = 0; j < 4; j++) acc[j] += er[tid + j * 256];
    }
    float* cr = ctx + (long)row * D_;
    unsigned short* ch = ctxh + (long)row * D_;
#pragma unroll
    for (int j = 0; j < 4; j++) {
        cr[tid + j * 256] = acc[j];
        ch[tid + j * 256] = __half_as_ushort(__float2half_rn(acc[j]));
    }
}

__global__ __launch_bounds__(256) void k_xmean(const float* __restrict__ ctx,
                                               float* __restrict__ xm)
{
    const int b = blockIdx.x, c = blockIdx.y, seg = blockIdx.z;
    const int tid = threadIdx.x;
    const int d = seg * 128 + (tid & 127);
    const int half = tid >> 7;
    const float* base = ctx + ((long)b * S_ + (long)c * CH_ + half * 128) * D_;
    float s = 0.f;
    for (int i = 0; i < 128; i++) s += base[(long)i * D_ + d];
    __shared__ float red[256];
    red[tid] = s;
    __syncthreads();
    if (half == 0)
        xm[((long)b * NC_ + c) * D_ + d] = (red[tid] + red[tid + 128]) * (1.0f / CH_);
}

__global__ __launch_bounds__(256) void k_scan(const float* __restrict__ xm,
    const float* __restrict__ Ub, float* __restrict__ bypArr, float* __restrict__ StArr)
{
    const int b = blockIdx.x, tid = threadIdx.x;
    __shared__ float part[KR_ * 256];
    float stp[4] = {0.f, 0.f, 0.f, 0.f};
#pragma unroll
    for (int j = 0; j < 4; j++) StArr[(long)(0 * B_ + b) * D_ + tid + j * 256] = 0.f;
    if (tid < KR_) bypArr[(0 * B_ + b) * KR_ + tid] = 0.f;

    for (int c = 1; c < NC_; c++) {
        const float* xp = xm + ((long)b * NC_ + (c - 1)) * D_;
        float pr[KR_];
#pragma unroll
        for (int r = 0; r < KR_; r++) pr[r] = 0.f;
#pragma unroll
        for (int j = 0; j < 4; j++) {
            const int d = tid + j * 256;
            const float xv = xp[d];
            stp[j] = LAM_ * stp[j] + (1.f - LAM_) * xv;
            StArr[(long)(c * B_ + b) * D_ + d] = stp[j];
#pragma unroll
            for (int r = 0; r < KR_; r++) pr[r] += xv * Ub[d * KR_ + r];
        }
#pragma unroll
        for (int r = 0; r < KR_; r++) part[r * 256 + tid] = pr[r];
        __syncthreads();
        for (int st = 128; st > 0; st >>= 1) {
            if (tid < st)
#pragma unroll
                for (int r = 0; r < KR_; r++) part[r * 256 + tid] += part[r * 256 + tid + st];
            __syncthreads();
        }
        if (tid < KR_) bypArr[(c * B_ + b) * KR_ + tid] = part[tid * 256];
        __syncthreads();
    }
}

__global__ __launch_bounds__(256) void k_rowscale_h16(const float* __restrict__ ov,
    unsigned short* __restrict__ ovh, float* __restrict__ alpha)
{
    const int row = blockIdx.x, tid = threadIdx.x;
    const float* r = ov + (long)row * D_;
    float v[4]; float mx = 0.f;
#pragma unroll
    for (int j = 0; j < 4; j++) { v[j] = r[tid + j * 256]; mx = fmaxf(mx, fabsf(v[j])); }
    __shared__ float red[256];
    red[tid] = mx; __syncthreads();
    for (int st = 128; st > 0; st >>= 1) {
        if (tid < st) red[tid] = fmaxf(red[tid], red[tid + st]);
        __syncthreads();
    }
    const float a = fmaxf(red[0], 1e-30f);
    if (tid == 0) alpha[row] = a;
    const float inv = 1.0f / a;
    unsigned short* o = ovh + (long)row * D_;
#pragma unroll
    for (int j = 0; j < 4; j++)
        o[tid + j * 256] = __half_as_ushort(__float2half_rn(v[j] * inv));
}

// LayerNorm reconstructing reference overflow behavior (see R11 notes)
__global__ __launch_bounds__(256) void k_ln_alpha(const float* __restrict__ h,
    const float* __restrict__ alpha,
    const float* __restrict__ g, const float* __restrict__ bta,
    unsigned short* __restrict__ Aout)
{
    const int row = blockIdx.x, tid = threadIdx.x;
    const float a = alpha[row];
    const float* hr = h + (long)row * D_;
    float v[4]; float s = 0.f;
#pragma unroll
    for (int j = 0; j < 4; j++) { v[j] = hr[tid + j * 256]; s += v[j]; }
    __shared__ float red[256];
    red[tid] = s; __syncthreads();
    for (int st = 128; st > 0; st >>= 1) { if (tid < st) red[tid] += red[tid + st]; __syncthreads(); }
    const float mu = red[0] * (1.f / D_);
    __syncthreads();
    float dref[4]; float s2 = 0.f;
#pragma unroll
    for (int j = 0; j < 4; j++) {
        dref[j] = a * (v[j] - mu);
        s2 += dref[j] * dref[j];            // overflows to inf like the reference
    }
    red[tid] = s2; __syncthreads();
    for (int st = 128; st > 0; st >>= 1) { if (tid < st) red[tid] += red[tid + st]; __syncthreads(); }
    const float inv = rsqrtf(red[0] * (1.f / D_) + 1e-5f);
    unsigned short* ar = Aout + (long)row * KB_;
#pragma unroll
    for (int j = 0; j < 4; j++) {
        const int c = tid + j * 256;
        const float y = dref[j] * inv * g[c] + bta[c];
        ar[c] = __half_as_ushort(__float2half_rn(y));
    }
}

// ------------------------------- launch ------------------------------------
extern "C" void kernel_launch(void* const* d_in, const int* in_sizes, int n_in,
                              void* d_out, int out_size)
{
    (void)in_sizes; (void)n_in; (void)out_size;
    const int*   x    = (const int*)  d_in[0];
    const float* emb  = (const float*)d_in[1];
    const float* Wq   = (const float*)d_in[2];
    const float* Wk   = (const float*)d_in[3];
    const float* Wv   = (const float*)d_in[4];
    const float* Wo   = (const float*)d_in[5];
    const float* Ub   = (const float*)d_in[6];
    const float* Vb   = (const float*)d_in[7];
    const float* lng  = (const float*)d_in[8];
    const float* lnb  = (const float*)d_in[9];
    const float* Wout = (const float*)d_in[10];
    const float* bout = (const float*)d_in[11];
    float* outp = (float*)d_out;

    float *ctx, *qk, *v, *ov, *h, *Sst, *U, *xm, *bypArr, *StArr, *alpha, *Wqk;
    unsigned short *ctxh, *ovh, *Ahf, *Wvt, *Wot, *Bhf, *ath, *vhT;
    cudaGetSymbolAddress((void**)&ctx,    g_ctx);
    cudaGetSymbolAddress((void**)&qk,     g_qk);
    cudaGetSymbolAddress((void**)&v,      g_v);
    cudaGetSymbolAddress((void**)&ov,     g_out);
    cudaGetSymbolAddress((void**)&h,      g_h);
    cudaGetSymbolAddress((void**)&Sst,    g_Sst);
    cudaGetSymbolAddress((void**)&U,      g_U);
    cudaGetSymbolAddress((void**)&xm,     g_xm);
    cudaGetSymbolAddress((void**)&bypArr, g_bypArr);
    cudaGetSymbolAddress((void**)&StArr,  g_StArr);
    cudaGetSymbolAddress((void**)&alpha,  g_alpha);
    cudaGetSymbolAddress((void**)&Wqk,    g_Wqk);
    cudaGetSymbolAddress((void**)&ctxh,   g_ctxh);
    cudaGetSymbolAddress((void**)&ovh,    g_ovh);
    cudaGetSymbolAddress((void**)&Ahf,    g_Ahf);
    cudaGetSymbolAddress((void**)&Wvt,    g_Wvt);
    cudaGetSymbolAddress((void**)&Wot,    g_Wot);
    cudaGetSymbolAddress((void**)&Bhf,    g_Bhf);
    cudaGetSymbolAddress((void**)&ath,    g_ath);
    cudaGetSymbolAddress((void**)&vhT,    g_vhT);

    float* q = qk;
    float* k = qk + (long)R_ * K_;

    cudaFuncSetAttribute(hgemm<1024, true>,  cudaFuncAttributeMaxDynamicSharedMemorySize, GSM);
    cudaFuncSetAttribute(hgemm<1024, false>, cudaFuncAttributeMaxDynamicSharedMemorySize, GSM);
    cudaFuncSetAttribute(hgemm<256,  false>, cudaFuncAttributeMaxDynamicSharedMemorySize, GSM);

    // weight conversions (independent of the model chain)
    k_convB<<<dim3(V_ / 32, D_ / 32), 256>>>(Wout, Bhf, V_);
    k_convB<<<dim3(D_ / 32, D_ / 32), 256>>>(Wv, Wvt, D_);
    k_convB<<<dim3(D_ / 32, D_ / 32), 256>>>(Wo, Wot, D_);
    k_pack<<<D_ * K_ / 256, 256>>>(Wq, Wk, Wqk);

    k_zero<<<(B_ * K_ * D_ + 255) / 256, 256>>>(Sst, B_ * K_ * D_);

    // embedding + causal local-context sum (fp32 + fp16)
    k_embed<<<R_, 256>>>(x, emb, ctx, ctxh);

    // carry stats for all chunks
    k_xmean<<<dim3(B_, NC_, 8), 256>>>(ctx, xm);
    k_scan<<<B_, 256>>>(xm, Ub, bypArr, StArr);

    // projections: Q+K merged (fp32 SIMT, z=2); V fp16 tensor
    gemm128<0,0,EPI_PHI><<<dim3(1, R_ / 128, 2), 256>>>(
        ctx, Wqk, qk, R_, K_, D_, 0, (long)D_ * K_, (long)R_ * K_);
    hgemm<1024,false><<<dim3(R_ / GBM, D_ / GBN), 256, GSM>>>(
        ctxh, Wvt, nullptr, v, D_, 0, 0, 0);
    k_convVT<<<dim3(D_ / 32, CH_ / 32, B_ * NC_), 256>>>(v, vhT);

    // intra-chunk attention: masked QK^T -> fp16 'at', then fp16 at@v
    gemm128<0,1,EPI_MASKH><<<dim3(CH_ / 128, CH_ / 128, B_ * NC_), 256>>>(
        q, k, (float*)ath, CH_, CH_, K_,
        (long)CH_ * K_, (long)CH_ * K_, (long)(CH_ * CH_ / 2));
    hgemm<256,false><<<dim3(CH_ / GBM, D_ / GBN, B_ * NC_), 256, GSM>>>(
        ath, vhT, nullptr, ov, D_,
        (long)CH_ * CH_, (long)D_ * CH_, (long)CH_ * D_);

    // chunk 0: S=0 => skip k_ir; S-update uses U = v directly
    gemm128<1,0,EPI_ACC><<<dim3(D_ / 128, K_ / 128, B_), 256>>>(
        k, v, Sst, K_, D_, CH_, (long)S_ * K_, (long)S_ * D_, (long)K_ * D_);

    for (int c = 1; c < NC_; c++) {
        const float* qc = q + (long)c * CH_ * K_;
        const float* kc = k + (long)c * CH_ * K_;
        k_ir<<<dim3(D_ / 128, CH_ / 128, 2 * B_), 256>>>(
            qc, kc, Sst,
            ov + (long)c * CH_ * D_,
            v + (long)c * CH_ * D_, U,
            bypArr + (long)c * B_ * KR_, Vb, StArr + (long)c * B_ * D_);
        gemm128<1,0,EPI_ACC><<<dim3(D_ / 128, K_ / 128, B_), 256>>>(
            kc, U, Sst, K_, D_, CH_, (long)S_ * K_, (long)CH_ * D_, (long)K_ * D_);
    }

    // row-scale ov -> fp16 (+alpha), Wo (fp16), LN w/ saturation, vocab head
    k_rowscale_h16<<<R_, 256>>>(ov, ovh, alpha);
    hgemm<1024,false><<<dim3(R_ / GBM, D_ / GBN), 256, GSM>>>(
        ovh, Wot, nullptr, h, D_, 0, 0, 0);
    k_ln_alpha<<<R_, 256>>>(h, alpha, lng, lnb, Ahf);
    hgemm<1024,true><<<dim3(R_ / GBM, V_ / GBN), 256, GSM>>>(
        Ahf, Bhf, bout, outp, V_, 0, 0, 0);
}

// round 13
// speedup vs baseline: 5.4823x; 1.2228x over previous
#include <cuda_runtime.h>
#include <cuda_bf16.h>
#include <cuda_fp16.h>
#include <cstdint>

// ---------------------------------------------------------------------------
// DSRAModel forward. Round 13: recurrence de-serialized via linear scan:
// S_{c+1} = M_c S_c + T_c with M_c = I - s*kc^T kc, T_c = kc^T vc. M/T are
// batched GEMMs; one kernel scans S per 32-column slice (no grid sync);
// INTER for all 16 (b,c) pairs in one launch. R12 fp16 paths retained.
// ---------------------------------------------------------------------------

static constexpr int B_  = 2;
static constexpr int S_  = 2048;
static constexpr int D_  = 1024;
static constexpr int K_  = 128;
static constexpr int KR_ = 8;
static constexpr int CH_ = 256;
static constexpr int NC_ = 8;
static constexpr int V_  = 32000;
static constexpr int LC_ = 4;
static constexpr int R_  = B_ * S_;
static constexpr int Z_  = B_ * NC_;          // 16 (b,c) pairs; chunk offset = z*CH*stride
static constexpr float LAM_   = 0.9f;
static constexpr float SCALE_ = 0.08838834764831845f;

// ------------------------------ scratch ------------------------------------
__device__ float g_ctx [R_ * D_];
__device__ float g_qk  [2 * R_ * K_];
__device__ float g_v   [R_ * D_];
__device__ float g_out [R_ * D_];
__device__ float g_h   [R_ * D_];
__device__ float g_Mmat[Z_ * K_ * K_];        // I - s*k^T k  per (b,c)
__device__ float g_Tmat[Z_ * K_ * D_];        // k^T v        per (b,c)
__device__ float g_Sall[Z_ * K_ * D_];        // S_c (state BEFORE chunk c)
__device__ float g_xm     [B_ * NC_ * D_];
__device__ float g_bypArr [Z_ * KR_];
__device__ float g_StArr  [Z_ * D_];
__device__ float g_alpha  [R_];
__device__ float g_Wqk [2 * D_ * K_];
// fp16 operands
static constexpr int KB_ = D_;
__device__ unsigned short g_ctxh[R_ * D_];
__device__ unsigned short g_ovh [R_ * D_];
__device__ unsigned short g_Ahf [R_ * KB_];
__device__ unsigned short g_Wvt [D_ * D_];
__device__ unsigned short g_Wot [D_ * D_];
__device__ unsigned short g_Bhf [V_ * KB_];
__device__ unsigned short g_ath [Z_ * CH_ * CH_];
__device__ unsigned short g_vhT [Z_ * D_ * CH_];

// ------------------------ PTX helpers (sm_100-safe) ------------------------
__device__ __forceinline__ uint32_t smem_u32(const void* p) {
    uint32_t a;
    asm("{ .reg .u64 t; cvta.to.shared.u64 t, %1; cvt.u32.u64 %0, t; }" : "=r"(a) : "l"(p));
    return a;
}
#define CP16(dst, src)   asm volatile("cp.async.cg.shared.global [%0], [%1], 16;" :: "r"(dst), "l"(src))
#define CP_COMMIT()      asm volatile("cp.async.commit_group;" ::: "memory")
#define CP_WAIT(n)       asm volatile("cp.async.wait_group %0;" :: "n"(n) : "memory")
#define LDSM4(r, addr)                                                          \
    asm volatile("ldmatrix.sync.aligned.m8n8.x4.shared.b16 {%0,%1,%2,%3}, [%4];" \
        : "=r"((r)[0]), "=r"((r)[1]), "=r"((r)[2]), "=r"((r)[3]) : "r"(addr))
#define MMA16816(c, a, b0, b1)                                                  \
    asm volatile("mma.sync.aligned.m16n8k16.row.col.f32.f16.f16.f32 "           \
        "{%0,%1,%2,%3},{%4,%5,%6,%7},{%8,%9},{%0,%1,%2,%3};"                    \
        : "+f"((c)[0]), "+f"((c)[1]), "+f"((c)[2]), "+f"((c)[3])                \
        : "r"((a)[0]), "r"((a)[1]), "r"((a)[2]), "r"((a)[3]), "r"(b0), "r"(b1))

// ---------------- generalized fp16 GEMM (mma.sync, z-batched) ---------------
static constexpr int GBM = 128, GBN = 128, GBK = 32, NSTG = 3;
static constexpr int ROWB = 80;
static constexpr int ABYT = GBM * ROWB;
static constexpr int STG  = 2 * ABYT;
static constexpr int GSM  = NSTG * STG;          // 61440

template <int KDIM, bool BIAS>
__global__ __launch_bounds__(256, 2)
void hgemm(const unsigned short* __restrict__ A,
           const unsigned short* __restrict__ B,
           const float* __restrict__ bias, float* __restrict__ C, int Ncols,
           long sA, long sB, long sC)
{
    constexpr int KIT = KDIM / GBK;
    extern __shared__ char smem[];
    const uint32_t sb = smem_u32(smem);
    const int tid = threadIdx.x, wid = tid >> 5, lane = tid & 31;
    const int wm = wid >> 2, wn = wid & 3;
    const int z  = blockIdx.z;
    const int m0 = blockIdx.x * GBM;
    const int n0 = blockIdx.y * GBN;
    A += (long)z * sA; B += (long)z * sB; C += (long)z * sC;

    const unsigned short* Arow = A + (long)m0 * KDIM;
    const unsigned short* Brow = B + (long)n0 * KDIM;

    const int ldr = tid >> 1, ldc = (tid & 1) * 2;

    auto load_stage = [&](int it, int slot) {
        const int k0 = it * GBK;
        const uint32_t ab = sb + slot * STG;
        const uint32_t bb = ab + ABYT;
        const unsigned short* ga = Arow + (long)ldr * KDIM + k0 + ldc * 8;
        CP16(ab + ldr * ROWB + ldc * 16, ga);
        CP16(ab + ldr * ROWB + (ldc + 1) * 16, ga + 8);
        const unsigned short* gb = Brow + (long)ldr * KDIM + k0 + ldc * 8;
        CP16(bb + ldr * ROWB + ldc * 16, gb);
        CP16(bb + ldr * ROWB + (ldc + 1) * 16, gb + 8);
    };

    uint32_t aoff[4], boff[2];
#pragma unroll
    for (int mt = 0; mt < 4; mt++)
        aoff[mt] = (wm * 64 + mt * 16 + (lane & 15)) * ROWB + (lane >> 4) * 16;
#pragma unroll
    for (int nt2 = 0; nt2 < 2; nt2++)
        boff[nt2] = (wn * 32 + nt2 * 16 + (lane & 7) + ((lane >> 4) << 3)) * ROWB
                  + ((lane >> 3) & 1) * 16;

    float acc[4][4][4];
#pragma unroll
    for (int mt = 0; mt < 4; mt++)
#pragma unroll
        for (int nt = 0; nt < 4; nt++)
#pragma unroll
            for (int e = 0; e < 4; e++) acc[mt][nt][e] = 0.f;

#pragma unroll
    for (int s = 0; s < NSTG - 1; s++) { load_stage(s, s); CP_COMMIT(); }

    for (int i = 0; i < KIT; i++) {
        CP_WAIT(NSTG - 2);
        __syncthreads();
        const int slot = i % NSTG;
        const uint32_t ab = sb + slot * STG;
        const uint32_t bb = ab + ABYT;
#pragma unroll
        for (int ks = 0; ks < 2; ks++) {
            uint32_t af[4][4], bf[2][4];
#pragma unroll
            for (int mt = 0; mt < 4; mt++) LDSM4(af[mt], ab + aoff[mt] + ks * 32);
#pragma unroll
            for (int nt2 = 0; nt2 < 2; nt2++) LDSM4(bf[nt2], bb + boff[nt2] + ks * 32);
#pragma unroll
            for (int mt = 0; mt < 4; mt++)
#pragma unroll
                for (int nt = 0; nt < 4; nt++)
                    MMA16816(acc[mt][nt], af[mt], bf[nt >> 1][(nt & 1) * 2],
                             bf[nt >> 1][(nt & 1) * 2 + 1]);
        }
        __syncthreads();
        if (i + NSTG - 1 < KIT) load_stage(i + NSTG - 1, (i + NSTG - 1) % NSTG);
        CP_COMMIT();
    }

    const int r0 = lane >> 2, c2 = (lane & 3) * 2;
#pragma unroll
    for (int nt = 0; nt < 4; nt++) {
        const int gc = n0 + wn * 32 + nt * 8 + c2;
        float2 bv = {0.f, 0.f};
        if (BIAS) bv = *reinterpret_cast<const float2*>(bias + gc);
#pragma unroll
        for (int mt = 0; mt < 4; mt++) {
            const int gr = m0 + wm * 64 + mt * 16 + r0;
            float2 lo = { acc[mt][nt][0] + bv.x, acc[mt][nt][1] + bv.y };
            float2 hi = { acc[mt][nt][2] + bv.x, acc[mt][nt][3] + bv.y };
            *reinterpret_cast<float2*>(C + (long)gr * Ncols + gc) = lo;
            *reinterpret_cast<float2*>(C + (long)(gr + 8) * Ncols + gc) = hi;
        }
    }
}

// ----------------- weight transpose + fp16 convert -------------------------
__global__ __launch_bounds__(256) void k_convB(const float* __restrict__ W,
                                               unsigned short* __restrict__ Bt, int ncols)
{
    __shared__ float t[32][33];
    const int n0 = blockIdx.x * 32, k0 = blockIdx.y * 32;
    const int tx = threadIdx.x & 31, ty = threadIdx.x >> 5;
#pragma unroll
    for (int j = 0; j < 32; j += 8)
        t[ty + j][tx] = W[(long)(k0 + ty + j) * ncols + n0 + tx];
    __syncthreads();
#pragma unroll
    for (int j = 0; j < 32; j += 8) {
        const int n = ty + j;
        Bt[(long)(n0 + n) * KB_ + k0 + tx] =
            __half_as_ushort(__float2half_rn(t[tx][n]));
    }
}

// v [R,D] fp32 -> vhT [Z][D][CH] fp16
__global__ __launch_bounds__(256) void k_convVT(const float* __restrict__ v,
                                                unsigned short* __restrict__ vhT)
{
    __shared__ float sm[32][33];
    const int d0 = blockIdx.x * 32, t0 = blockIdx.y * 32, z = blockIdx.z;
    const int tx = threadIdx.x & 31, ty = threadIdx.x >> 5;
#pragma unroll
    for (int j = 0; j < 32; j += 8)
        sm[ty + j][tx] = v[((long)z * CH_ + t0 + ty + j) * D_ + d0 + tx];
    __syncthreads();
#pragma unroll
    for (int j = 0; j < 32; j += 8)
        vhT[((long)z * D_ + d0 + ty + j) * CH_ + t0 + tx] =
            __half_as_ushort(__float2half_rn(sm[tx][ty + j]));
}

// ------------------------------ SIMT GEMM ----------------------------------
enum { EPI_STORE = 0, EPI_PHI, EPI_MASKH, EPI_MI };

template <int TRA, int TRB, int EPI>
__global__ __launch_bounds__(256) void gemm128(
    const float* __restrict__ A, const float* __restrict__ Bm, float* __restrict__ C,
    int M, int N, int Kd, long sA, long sB, long sC)
{
    constexpr int BM = 128, BN = 128, BK = 8, TM = 8, TN = 8;
    __shared__ __align__(16) float As[BK][BM];
    __shared__ __align__(16) float Bs[BK][BN];

    const int z = blockIdx.z;
    A  += (long)z * sA;
    Bm += (long)z * sB;
    C  += (long)z * sC;   // EPI_MASKH: sC in FLOAT units

    const int tid  = threadIdx.x;
    const int row0 = blockIdx.y * BM;
    const int col0 = blockIdx.x * BN;
    const int tRow = tid >> 4;
    const int tCol = tid & 15;

    float acc[TM][TN];
#pragma unroll
    for (int i = 0; i < TM; i++)
#pragma unroll
        for (int j = 0; j < TN; j++) acc[i][j] = 0.f;

    for (int k0 = 0; k0 < Kd; k0 += BK) {
        if (TRA == 0) {
            const int r = tid >> 1, c = (tid & 1) * 4;
            float4 a4 = *reinterpret_cast<const float4*>(A + (long)(row0 + r) * Kd + k0 + c);
            As[c + 0][r] = a4.x; As[c + 1][r] = a4.y;
            As[c + 2][r] = a4.z; As[c + 3][r] = a4.w;
        } else {
            const int r = tid >> 5, c = (tid & 31) * 4;
            *reinterpret_cast<float4*>(&As[r][c]) =
                *reinterpret_cast<const float4*>(A + (long)(k0 + r) * M + row0 + c);
        }
        if (TRB == 0) {
            const int r = tid >> 5, c = (tid & 31) * 4;
            *reinterpret_cast<float4*>(&Bs[r][c]) =
                *reinterpret_cast<const float4*>(Bm + (long)(k0 + r) * N + col0 + c);
        } else {
            const int r = tid >> 1, c = (tid & 1) * 4;
            float4 b4 = *reinterpret_cast<const float4*>(Bm + (long)(col0 + r) * Kd + k0 + c);
            Bs[c + 0][r] = b4.x; Bs[c + 1][r] = b4.y;
            Bs[c + 2][r] = b4.z; Bs[c + 3][r] = b4.w;
        }
        __syncthreads();

#pragma unroll
        for (int kk = 0; kk < BK; kk++) {
            float ra[TM], rb[TN];
            *reinterpret_cast<float4*>(ra)     = *reinterpret_cast<const float4*>(&As[kk][tRow * TM]);
            *reinterpret_cast<float4*>(ra + 4) = *reinterpret_cast<const float4*>(&As[kk][tRow * TM + 4]);
            *reinterpret_cast<float4*>(rb)     = *reinterpret_cast<const float4*>(&Bs[kk][tCol * TN]);
            *reinterpret_cast<float4*>(rb + 4) = *reinterpret_cast<const float4*>(&Bs[kk][tCol * TN + 4]);
#pragma unroll
            for (int i = 0; i < TM; i++)
#pragma unroll
                for (int j = 0; j < TN; j++) acc[i][j] += ra[i] * rb[j];
        }
        __syncthreads();
    }

#pragma unroll
    for (int i = 0; i < TM; i++) {
        const int gr = row0 + tRow * TM + i;
#pragma unroll
        for (int j = 0; j < TN; j++) {
            const int gc = col0 + tCol * TN + j;
            const long idx = (long)gr * N + gc;
            const float vv = acc[i][j];
            if (EPI == EPI_STORE)      C[idx] = vv;
            else if (EPI == EPI_PHI)   C[idx] = (vv > 0.f) ? vv + 1.f : expf(vv);
            else if (EPI == EPI_MASKH)
                reinterpret_cast<unsigned short*>(C)[idx] =
                    __half_as_ushort(__float2half_rn((gc <= gr) ? vv * SCALE_ : 0.f));
            else if (EPI == EPI_MI)    C[idx] = ((gr == gc) ? 1.f : 0.f) - SCALE_ * vv;
        }
    }
}

// ---------------- state scan: S_{c+1} = M_c S_c + T_c ----------------------
// grid (D/32, B), 256 threads; each block owns a 32-column slice of S.
static constexpr int SREC_SM = (K_ * 129 + K_ * 32) * 4;  // MT + Sbuf = 82432 B
__global__ __launch_bounds__(256) void k_srec(
    const float* __restrict__ Mmat, const float* __restrict__ Tmat,
    float* __restrict__ Sall)
{
    extern __shared__ float sm[];
    float* MT = sm;              // [128][129], MT[k][i] = M[i][k]
    float* Sb = sm + K_ * 129;   // [128][32]
    const int tid = threadIdx.x;
    const int j = tid & 31, i0 = (tid >> 5) * 16;
    const int d0 = blockIdx.x * 32, b = blockIdx.y;

    for (int idx = tid; idx < K_ * 32; idx += 256) Sb[idx] = 0.f;
    __syncthreads();

    for (int c = 0; c < NC_; c++) {
        const long zoff = (long)(b * NC_ + c) * K_;
        // store S_c (state before chunk c)
        for (int r = tid >> 5; r < K_; r += 8)
            Sall[(zoff + r) * D_ + d0 + j] = Sb[r * 32 + j];
        if (c == NC_ - 1) break;
        __syncthreads();   // all reads of MT/Sb from prior iter complete
        const float* Mb = Mmat + zoff * K_;
        for (int idx = tid; idx < K_ * K_; idx += 256) {
            const int i = idx >> 7, kk = idx & 127;
            MT[kk * 129 + i] = Mb[idx];
        }
        __syncthreads();
        float sn[16];
        const float* Tb = Tmat + zoff * D_;
#pragma unroll
        for (int r = 0; r < 16; r++) sn[r] = Tb[(long)(i0 + r) * D_ + d0 + j];
        for (int kk = 0; kk < K_; kk++) {
            const float sv = Sb[kk * 32 + j];
            const float* mrow = MT + kk * 129 + i0;
#pragma unroll
            for (int r = 0; r < 16; r++) sn[r] += mrow[r] * sv;
        }
        __syncthreads();
#pragma unroll
        for (int r = 0; r < 16; r++) Sb[(i0 + r) * 32 + j] = sn[r];
        __syncthreads();
    }
}

// ---------------- batched INTER: ov += s*(q@S) + byp@Vb + St ----------------
__global__ __launch_bounds__(256) void k_inter(
    const float* __restrict__ q, const float* __restrict__ Sall,
    float* __restrict__ ov,
    const float* __restrict__ bypArr, const float* __restrict__ Vb,
    const float* __restrict__ StArr)
{
    constexpr int BM = 128, BN = 128, BK = 8, TM = 8, TN = 8;
    __shared__ __align__(16) float As[BK][BM];
    __shared__ __align__(16) float Bs[BK][BN];

    const int z = blockIdx.z;                  // b*NC + c
    const float* A  = q + (long)z * CH_ * K_;
    const float* Bm = Sall + (long)z * K_ * D_;
    float* C = ov + (long)z * CH_ * D_;

    const int tid  = threadIdx.x;
    const int row0 = blockIdx.y * BM;
    const int col0 = blockIdx.x * BN;
    const int tRow = tid >> 4;
    const int tCol = tid & 15;

    float acc[TM][TN];
#pragma unroll
    for (int i = 0; i < TM; i++)
#pragma unroll
        for (int j = 0; j < TN; j++) acc[i][j] = 0.f;

    for (int k0 = 0; k0 < K_; k0 += BK) {
        {
            const int r = tid >> 1, c = (tid & 1) * 4;
            float4 a4 = *reinterpret_cast<const float4*>(A + (long)(row0 + r) * K_ + k0 + c);
            As[c + 0][r] = a4.x; As[c + 1][r] = a4.y;
            As[c + 2][r] = a4.z; As[c + 3][r] = a4.w;
        }
        {
            const int r = tid >> 5, c = (tid & 31) * 4;
            *reinterpret_cast<float4*>(&Bs[r][c]) =
                *reinterpret_cast<const float4*>(Bm + (long)(k0 + r) * D_ + col0 + c);
        }
        __syncthreads();
#pragma unroll
        for (int kk = 0; kk < BK; kk++) {
            float ra[TM], rb[TN];
            *reinterpret_cast<float4*>(ra)     = *reinterpret_cast<const float4*>(&As[kk][tRow * TM]);
            *reinterpret_cast<float4*>(ra + 4) = *reinterpret_cast<const float4*>(&As[kk][tRow * TM + 4]);
            *reinterpret_cast<float4*>(rb)     = *reinterpret_cast<const float4*>(&Bs[kk][tCol * TN]);
            *reinterpret_cast<float4*>(rb + 4) = *reinterpret_cast<const float4*>(&Bs[kk][tCol * TN + 4]);
#pragma unroll
            for (int i = 0; i < TM; i++)
#pragma unroll
                for (int j = 0; j < TN; j++) acc[i][j] += ra[i] * rb[j];
        }
        __syncthreads();
    }

    float addc[TN];
#pragma unroll
    for (int j = 0; j < TN; j++) {
        const int gc = col0 + tCol * TN + j;
        float bv = 0.f;
#pragma unroll
        for (int r = 0; r < KR_; r++) bv += bypArr[z * KR_ + r] * Vb[r * D_ + gc];
        addc[j] = bv + StArr[(long)z * D_ + gc];
    }
#pragma unroll
    for (int i = 0; i < TM; i++) {
        const int gr = row0 + tRow * TM + i;
#pragma unroll
        for (int j = 0; j < TN; j++) {
            const int gc = col0 + tCol * TN + j;
            C[(long)gr * D_ + gc] += acc[i][j] * SCALE_ + addc[j];
        }
    }
}

// --------------------------- small kernels ---------------------------------
__global__ void k_pack(const float* __restrict__ Wq, const float* __restrict__ Wk,
                       float* __restrict__ Wqk)
{
    const int i = blockIdx.x * 256 + threadIdx.x;
    Wqk[i] = Wq[i];
    Wqk[D_ * K_ + i] = Wk[i];
}

__global__ __launch_bounds__(256) void k_embed(const int* __restrict__ x,
    const float* __restrict__ emb, float* __restrict__ ctx,
    unsigned short* __restrict__ ctxh)
{
    const int row = blockIdx.x;
    const int b = row / S_, s = row % S_;
    const int tid = threadIdx.x;
    float acc[4] = {0.f, 0.f, 0.f, 0.f};
    for (int off = 0; off < LC_; off++) {
        const int sp = s - off;
        if (sp < 0) break;
        const float* er = emb + (long)x[b * S_ + sp] * D_;
#pragma unroll
        for (int j = 0; j < 4; j++) acc[j] += er[tid + j * 256];
    }
    float* cr = ctx + (long)row * D_;
    unsigned short* ch = ctxh + (long)row * D_;
#pragma unroll
    for (int j = 0; j < 4; j++) {
        cr[tid + j * 256] = acc[j];
        ch[tid + j * 256] = __half_as_ushort(__float2half_rn(acc[j]));
    }
}

__global__ __launch_bounds__(256) void k_xmean(const float* __restrict__ ctx,
                                               float* __restrict__ xm)
{
    const int b = blockIdx.x, c = blockIdx.y, seg = blockIdx.z;
    const int tid = threadIdx.x;
    const int d = seg * 128 + (tid & 127);
    const int half = tid >> 7;
    const float* base = ctx + ((long)b * S_ + (long)c * CH_ + half * 128) * D_;
    float s = 0.f;
    for (int i = 0; i < 128; i++) s += base[(long)i * D_ + d];
    __shared__ float red[256];
    red[tid] = s;
    __syncthreads();
    if (half == 0)
        xm[((long)b * NC_ + c) * D_ + d] = (red[tid] + red[tid + 128]) * (1.0f / CH_);
}

// byp/St laid out by z = b*NC + c
__global__ __launch_bounds__(256) void k_scan(const float* __restrict__ xm,
    const float* __restrict__ Ub, float* __restrict__ bypArr, float* __restrict__ StArr)
{
    const int b = blockIdx.x, tid = threadIdx.x;
    __shared__ float part[KR_ * 256];
    float stp[4] = {0.f, 0.f, 0.f, 0.f};
#pragma unroll
    for (int j = 0; j < 4; j++) StArr[(long)(b * NC_) * D_ + tid + j * 256] = 0.f;
    if (tid < KR_) bypArr[(b * NC_) * KR_ + tid] = 0.f;

    for (int c = 1; c < NC_; c++) {
        const float* xp = xm + ((long)b * NC_ + (c - 1)) * D_;
        float pr[KR_];
#pragma unroll
        for (int r = 0; r < KR_; r++) pr[r] = 0.f;
#pragma unroll
        for (int j = 0; j < 4; j++) {
            const int d = tid + j * 256;
            const float xv = xp[d];
            stp[j] = LAM_ * stp[j] + (1.f - LAM_) * xv;
            StArr[(long)(b * NC_ + c) * D_ + d] = stp[j];
#pragma unroll
            for (int r = 0; r < KR_; r++) pr[r] += xv * Ub[d * KR_ + r];
        }
#pragma unroll
        for (int r = 0; r < KR_; r++) part[r * 256 + tid] = pr[r];
        __syncthreads();
        for (int st = 128; st > 0; st >>= 1) {
            if (tid < st)
#pragma unroll
                for (int r = 0; r < KR_; r++) part[r * 256 + tid] += part[r * 256 + tid + st];
            __syncthreads();
        }
        if (tid < KR_) bypArr[(b * NC_ + c) * KR_ + tid] = part[tid * 256];
        __syncthreads();
    }
}

__global__ __launch_bounds__(256) void k_rowscale_h16(const float* __restrict__ ov,
    unsigned short* __restrict__ ovh, float* __restrict__ alpha)
{
    const int row = blockIdx.x, tid = threadIdx.x;
    const float* r = ov + (long)row * D_;
    float v[4]; float mx = 0.f;
#pragma unroll
    for (int j = 0; j < 4; j++) { v[j] = r[tid + j * 256]; mx = fmaxf(mx, fabsf(v[j])); }
    __shared__ float red[256];
    red[tid] = mx; __syncthreads();
    for (int st = 128; st > 0; st >>= 1) {
        if (tid < st) red[tid] = fmaxf(red[tid], red[tid + st]);
        __syncthreads();
    }
    const float a = fmaxf(red[0], 1e-30f);
    if (tid == 0) alpha[row] = a;
    const float inv = 1.0f / a;
    unsigned short* o = ovh + (long)row * D_;
#pragma unroll
    for (int j = 0; j < 4; j++)
        o[tid + j * 256] = __half_as_ushort(__float2half_rn(v[j] * inv));
}

// LayerNorm reconstructing reference overflow behavior (R11 notes)
__global__ __launch_bounds__(256) void k_ln_alpha(const float* __restrict__ h,
    const float* __restrict__ alpha,
    const float* __restrict__ g, const float* __restrict__ bta,
    unsigned short* __restrict__ Aout)
{
    const int row = blockIdx.x, tid = threadIdx.x;
    const float a = alpha[row];
    const float* hr = h + (long)row * D_;
    float v[4]; float s = 0.f;
#pragma unroll
    for (int j = 0; j < 4; j++) { v[j] = hr[tid + j * 256]; s += v[j]; }
    __shared__ float red[256];
    red[tid] = s; __syncthreads();
    for (int st = 128; st > 0; st >>= 1) { if (tid < st) red[tid] += red[tid + st]; __syncthreads(); }
    const float mu = red[0] * (1.f / D_);
    __syncthreads();
    float dref[4]; float s2 = 0.f;
#pragma unroll
    for (int j = 0; j < 4; j++) {
        dref[j] = a * (v[j] - mu);
        s2 += dref[j] * dref[j];            // overflows to inf like the reference
    }
    red[tid] = s2; __syncthreads();
    for (int st = 128; st > 0; st >>= 1) { if (tid < st) red[tid] += red[tid + st]; __syncthreads(); }
    const float inv = rsqrtf(red[0] * (1.f / D_) + 1e-5f);
    unsigned short* ar = Aout + (long)row * KB_;
#pragma unroll
    for (int j = 0; j < 4; j++) {
        const int c = tid + j * 256;
        const float y = dref[j] * inv * g[c] + bta[c];
        ar[c] = __half_as_ushort(__float2half_rn(y));
    }
}

// ------------------------------- launch ------------------------------------
extern "C" void kernel_launch(void* const* d_in, const int* in_sizes, int n_in,
                              void* d_out, int out_size)
{
    (void)in_sizes; (void)n_in; (void)out_size;
    const int*   x    = (const int*)  d_in[0];
    const float* emb  = (const float*)d_in[1];
    const float* Wq   = (const float*)d_in[2];
    const float* Wk   = (const float*)d_in[3];
    const float* Wv   = (const float*)d_in[4];
    const float* Wo   = (const float*)d_in[5];
    const float* Ub   = (const float*)d_in[6];
    const float* Vb   = (const float*)d_in[7];
    const float* lng  = (const float*)d_in[8];
    const float* lnb  = (const float*)d_in[9];
    const float* Wout = (const float*)d_in[10];
    const float* bout = (const float*)d_in[11];
    float* outp = (float*)d_out;

    float *ctx, *qk, *v, *ov, *h, *Mm, *Tm, *Sall, *xm, *bypArr, *StArr, *alpha, *Wqk;
    unsigned short *ctxh, *ovh, *Ahf, *Wvt, *Wot, *Bhf, *ath, *vhT;
    cudaGetSymbolAddress((void**)&ctx,    g_ctx);
    cudaGetSymbolAddress((void**)&qk,     g_qk);
    cudaGetSymbolAddress((void**)&v,      g_v);
    cudaGetSymbolAddress((void**)&ov,     g_out);
    cudaGetSymbolAddress((void**)&h,      g_h);
    cudaGetSymbolAddress((void**)&Mm,     g_Mmat);
    cudaGetSymbolAddress((void**)&Tm,     g_Tmat);
    cudaGetSymbolAddress((void**)&Sall,   g_Sall);
    cudaGetSymbolAddress((void**)&xm,     g_xm);
    cudaGetSymbolAddress((void**)&bypArr, g_bypArr);
    cudaGetSymbolAddress((void**)&StArr,  g_StArr);
    cudaGetSymbolAddress((void**)&alpha,  g_alpha);
    cudaGetSymbolAddress((void**)&Wqk,    g_Wqk);
    cudaGetSymbolAddress((void**)&ctxh,   g_ctxh);
    cudaGetSymbolAddress((void**)&ovh,    g_ovh);
    cudaGetSymbolAddress((void**)&Ahf,    g_Ahf);
    cudaGetSymbolAddress((void**)&Wvt,    g_Wvt);
    cudaGetSymbolAddress((void**)&Wot,    g_Wot);
    cudaGetSymbolAddress((void**)&Bhf,    g_Bhf);
    cudaGetSymbolAddress((void**)&ath,    g_ath);
    cudaGetSymbolAddress((void**)&vhT,    g_vhT);

    float* q = qk;
    float* k = qk + (long)R_ * K_;

    cudaFuncSetAttribute(hgemm<1024, true>,  cudaFuncAttributeMaxDynamicSharedMemorySize, GSM);
    cudaFuncSetAttribute(hgemm<1024, false>, cudaFuncAttributeMaxDynamicSharedMemorySize, GSM);
    cudaFuncSetAttribute(hgemm<256,  false>, cudaFuncAttributeMaxDynamicSharedMemorySize, GSM);
    cudaFuncSetAttribute(k_srec, cudaFuncAttributeMaxDynamicSharedMemorySize, SREC_SM);

    // weight conversions (independent of the model chain)
    k_convB<<<dim3(V_ / 32, D_ / 32), 256>>>(Wout, Bhf, V_);
    k_convB<<<dim3(D_ / 32, D_ / 32), 256>>>(Wv, Wvt, D_);
    k_convB<<<dim3(D_ / 32, D_ / 32), 256>>>(Wo, Wot, D_);
    k_pack<<<D_ * K_ / 256, 256>>>(Wq, Wk, Wqk);

    // embedding + causal local-context sum (fp32 + fp16)
    k_embed<<<R_, 256>>>(x, emb, ctx, ctxh);

    // carry stats
    k_xmean<<<dim3(B_, NC_, 8), 256>>>(ctx, xm);
    k_scan<<<B_, 256>>>(xm, Ub, bypArr, StArr);

    // projections: Q+K merged (fp32, z=2); V fp16 tensor
    gemm128<0,0,EPI_PHI><<<dim3(1, R_ / 128, 2), 256>>>(
        ctx, Wqk, qk, R_, K_, D_, 0, (long)D_ * K_, (long)R_ * K_);
    hgemm<1024,false><<<dim3(R_ / GBM, D_ / GBN), 256, GSM>>>(
        ctxh, Wvt, nullptr, v, D_, 0, 0, 0);
    k_convVT<<<dim3(D_ / 32, CH_ / 32, Z_), 256>>>(v, vhT);

    // intra-chunk attention: masked QK^T (fp16 out), then fp16 at@v
    gemm128<0,1,EPI_MASKH><<<dim3(CH_ / 128, CH_ / 128, Z_), 256>>>(
        q, k, (float*)ath, CH_, CH_, K_,
        (long)CH_ * K_, (long)CH_ * K_, (long)(CH_ * CH_ / 2));
    hgemm<256,false><<<dim3(CH_ / GBM, D_ / GBN, Z_), 256, GSM>>>(
        ath, vhT, nullptr, ov, D_,
        (long)CH_ * CH_, (long)D_ * CH_, (long)CH_ * D_);

    // recurrence as linear scan: M_c = I - s*k^T k ; T_c = k^T v ; scan ; INTER
    gemm128<1,0,EPI_MI><<<dim3(1, 1, Z_), 256>>>(
        k, k, Mm, K_, K_, CH_, (long)CH_ * K_, (long)CH_ * K_, (long)K_ * K_);
    gemm128<1,0,EPI_STORE><<<dim3(D_ / 128, 1, Z_), 256>>>(
        k, v, Tm, K_, D_, CH_, (long)CH_ * K_, (long)CH_ * D_, (long)K_ * D_);
    k_srec<<<dim3(D_ / 32, B_), 256, SREC_SM>>>(Mm, Tm, Sall);
    k_inter<<<dim3(D_ / 128, CH_ / 128, Z_), 256>>>(q, Sall, ov, bypArr, Vb, StArr);

    // row-scale ov -> fp16 (+alpha), Wo (fp16), LN w/ saturation, vocab head
    k_rowscale_h16<<<R_, 256>>>(ov, ovh, alpha);
    hgemm<1024,false><<<dim3(R_ / GBM, D_ / GBN), 256, GSM>>>(
        ovh, Wot, nullptr, h, D_, 0, 0, 0);
    k_ln_alpha<<<R_, 256>>>(h, alpha, lng, lnb, Ahf);
    hgemm<1024,true><<<dim3(R_ / GBM, V_ / GBN), 256, GSM>>>(
        Ahf, Bhf, bout, outp, V_, 0, 0, 0);
}

// round 15
// speedup vs baseline: 5.9602x; 1.0872x over previous
#include <cuda_runtime.h>
#include <cuda_bf16.h>
#include <cuda_fp16.h>
#include <cstdint>

// ---------------------------------------------------------------------------
// DSRAModel forward. Round 15 (= Round 14 resubmit after infra failure):
// R13 + saturation skip: rows where the reference LN variance overflows
// (hn = lnb, constant) are flagged; vocab-GEMM blocks whose whole 128-row
// tile is saturated broadcast crow = lnb@Wout + bout instead of the GEMM.
// ---------------------------------------------------------------------------

static constexpr int B_  = 2;
static constexpr int S_  = 2048;
static constexpr int D_  = 1024;
static constexpr int K_  = 128;
static constexpr int KR_ = 8;
static constexpr int CH_ = 256;
static constexpr int NC_ = 8;
static constexpr int V_  = 32000;
static constexpr int LC_ = 4;
static constexpr int R_  = B_ * S_;
static constexpr int Z_  = B_ * NC_;
static constexpr float LAM_   = 0.9f;
static constexpr float SCALE_ = 0.08838834764831845f;

// ------------------------------ scratch ------------------------------------
__device__ float g_ctx [R_ * D_];
__device__ float g_qk  [2 * R_ * K_];
__device__ float g_v   [R_ * D_];
__device__ float g_out [R_ * D_];
__device__ float g_h   [R_ * D_];
__device__ float g_Mmat[Z_ * K_ * K_];
__device__ float g_Tmat[Z_ * K_ * D_];
__device__ float g_Sall[Z_ * K_ * D_];
__device__ float g_xm     [B_ * NC_ * D_];
__device__ float g_bypArr [Z_ * KR_];
__device__ float g_StArr  [Z_ * D_];
__device__ float g_alpha  [R_];
__device__ float g_crow   [V_];               // lnb@Wout + bout
__device__ int   g_sat    [R_];               // 1 = LN saturated (hn = lnb)
__device__ float g_Wqk [2 * D_ * K_];
// fp16 operands
static constexpr int KB_ = D_;
__device__ unsigned short g_ctxh[R_ * D_];
__device__ unsigned short g_ovh [R_ * D_];
__device__ unsigned short g_Ahf [R_ * KB_];
__device__ unsigned short g_Wvt [D_ * D_];
__device__ unsigned short g_Wot [D_ * D_];
__device__ unsigned short g_Bhf [V_ * KB_];
__device__ unsigned short g_ath [Z_ * CH_ * CH_];
__device__ unsigned short g_vhT [Z_ * D_ * CH_];

// ------------------------ PTX helpers (sm_100-safe) ------------------------
__device__ __forceinline__ uint32_t smem_u32(const void* p) {
    uint32_t a;
    asm("{ .reg .u64 t; cvta.to.shared.u64 t, %1; cvt.u32.u64 %0, t; }" : "=r"(a) : "l"(p));
    return a;
}
#define CP16(dst, src)   asm volatile("cp.async.cg.shared.global [%0], [%1], 16;" :: "r"(dst), "l"(src))
#define CP_COMMIT()      asm volatile("cp.async.commit_group;" ::: "memory")
#define CP_WAIT(n)       asm volatile("cp.async.wait_group %0;" :: "n"(n) : "memory")
#define LDSM4(r, addr)                                                          \
    asm volatile("ldmatrix.sync.aligned.m8n8.x4.shared.b16 {%0,%1,%2,%3}, [%4];" \
        : "=r"((r)[0]), "=r"((r)[1]), "=r"((r)[2]), "=r"((r)[3]) : "r"(addr))
#define MMA16816(c, a, b0, b1)                                                  \
    asm volatile("mma.sync.aligned.m16n8k16.row.col.f32.f16.f16.f32 "           \
        "{%0,%1,%2,%3},{%4,%5,%6,%7},{%8,%9},{%0,%1,%2,%3};"                    \
        : "+f"((c)[0]), "+f"((c)[1]), "+f"((c)[2]), "+f"((c)[3])                \
        : "r"((a)[0]), "r"((a)[1]), "r"((a)[2]), "r"((a)[3]), "r"(b0), "r"(b1))

// ---------------- generalized fp16 GEMM (mma.sync, z-batched) ---------------
static constexpr int GBM = 128, GBN = 128, GBK = 32, NSTG = 3;
static constexpr int ROWB = 80;
static constexpr int ABYT = GBM * ROWB;
static constexpr int STG  = 2 * ABYT;
static constexpr int GSM  = NSTG * STG;          // 61440

template <int KDIM, bool BIAS, bool SKIP>
__global__ __launch_bounds__(256, 2)
void hgemm(const unsigned short* __restrict__ A,
           const unsigned short* __restrict__ B,
           const float* __restrict__ bias, float* __restrict__ C, int Ncols,
           long sA, long sB, long sC,
           const int* __restrict__ sat, const float* __restrict__ crow)
{
    constexpr int KIT = KDIM / GBK;
    extern __shared__ char smem[];
    const uint32_t sb = smem_u32(smem);
    const int tid = threadIdx.x, wid = tid >> 5, lane = tid & 31;
    const int wm = wid >> 2, wn = wid & 3;
    const int z  = blockIdx.z;
    const int m0 = blockIdx.x * GBM;
    const int n0 = blockIdx.y * GBN;
    A += (long)z * sA; B += (long)z * sB; C += (long)z * sC;

    if (SKIP) {
        __shared__ int allsat;
        if (tid == 0) allsat = 1;
        __syncthreads();
        if (tid < GBM && !sat[m0 + tid]) allsat = 0;
        __syncthreads();
        if (allsat) {
            const float4 val = *reinterpret_cast<const float4*>(crow + n0 + (tid & 31) * 4);
            for (int r = tid >> 5; r < GBM; r += 8)
                *reinterpret_cast<float4*>(C + (long)(m0 + r) * Ncols + n0 + (tid & 31) * 4) = val;
            return;
        }
    }

    const unsigned short* Arow = A + (long)m0 * KDIM;
    const unsigned short* Brow = B + (long)n0 * KDIM;

    const int ldr = tid >> 1, ldc = (tid & 1) * 2;

    auto load_stage = [&](int it, int slot) {
        const int k0 = it * GBK;
        const uint32_t ab = sb + slot * STG;
        const uint32_t bb = ab + ABYT;
        const unsigned short* ga = Arow + (long)ldr * KDIM + k0 + ldc * 8;
        CP16(ab + ldr * ROWB + ldc * 16, ga);
        CP16(ab + ldr * ROWB + (ldc + 1) * 16, ga + 8);
        const unsigned short* gb = Brow + (long)ldr * KDIM + k0 + ldc * 8;
        CP16(bb + ldr * ROWB + ldc * 16, gb);
        CP16(bb + ldr * ROWB + (ldc + 1) * 16, gb + 8);
    };

    uint32_t aoff[4], boff[2];
#pragma unroll
    for (int mt = 0; mt < 4; mt++)
        aoff[mt] = (wm * 64 + mt * 16 + (lane & 15)) * ROWB + (lane >> 4) * 16;
#pragma unroll
    for (int nt2 = 0; nt2 < 2; nt2++)
        boff[nt2] = (wn * 32 + nt2 * 16 + (lane & 7) + ((lane >> 4) << 3)) * ROWB
                  + ((lane >> 3) & 1) * 16;

    float acc[4][4][4];
#pragma unroll
    for (int mt = 0; mt < 4; mt++)
#pragma unroll
        for (int nt = 0; nt < 4; nt++)
#pragma unroll
            for (int e = 0; e < 4; e++) acc[mt][nt][e] = 0.f;

#pragma unroll
    for (int s = 0; s < NSTG - 1; s++) { load_stage(s, s); CP_COMMIT(); }

    for (int i = 0; i < KIT; i++) {
        CP_WAIT(NSTG - 2);
        __syncthreads();
        const int slot = i % NSTG;
        const uint32_t ab = sb + slot * STG;
        const uint32_t bb = ab + ABYT;
#pragma unroll
        for (int ks = 0; ks < 2; ks++) {
            uint32_t af[4][4], bf[2][4];
#pragma unroll
            for (int mt = 0; mt < 4; mt++) LDSM4(af[mt], ab + aoff[mt] + ks * 32);
#pragma unroll
            for (int nt2 = 0; nt2 < 2; nt2++) LDSM4(bf[nt2], bb + boff[nt2] + ks * 32);
#pragma unroll
            for (int mt = 0; mt < 4; mt++)
#pragma unroll
                for (int nt = 0; nt < 4; nt++)
                    MMA16816(acc[mt][nt], af[mt], bf[nt >> 1][(nt & 1) * 2],
                             bf[nt >> 1][(nt & 1) * 2 + 1]);
        }
        __syncthreads();
        if (i + NSTG - 1 < KIT) load_stage(i + NSTG - 1, (i + NSTG - 1) % NSTG);
        CP_COMMIT();
    }

    const int r0 = lane >> 2, c2 = (lane & 3) * 2;
#pragma unroll
    for (int nt = 0; nt < 4; nt++) {
        const int gc = n0 + wn * 32 + nt * 8 + c2;
        float2 bv = {0.f, 0.f};
        if (BIAS) bv = *reinterpret_cast<const float2*>(bias + gc);
#pragma unroll
        for (int mt = 0; mt < 4; mt++) {
            const int gr = m0 + wm * 64 + mt * 16 + r0;
            float2 lo = { acc[mt][nt][0] + bv.x, acc[mt][nt][1] + bv.y };
            float2 hi = { acc[mt][nt][2] + bv.x, acc[mt][nt][3] + bv.y };
            *reinterpret_cast<float2*>(C + (long)gr * Ncols + gc) = lo;
            *reinterpret_cast<float2*>(C + (long)(gr + 8) * Ncols + gc) = hi;
        }
    }
}

// ----------------- weight transpose + fp16 convert -------------------------
__global__ __launch_bounds__(256) void k_convB(const float* __restrict__ W,
                                               unsigned short* __restrict__ Bt, int ncols)
{
    __shared__ float t[32][33];
    const int n0 = blockIdx.x * 32, k0 = blockIdx.y * 32;
    const int tx = threadIdx.x & 31, ty = threadIdx.x >> 5;
#pragma unroll
    for (int j = 0; j < 32; j += 8)
        t[ty + j][tx] = W[(long)(k0 + ty + j) * ncols + n0 + tx];
    __syncthreads();
#pragma unroll
    for (int j = 0; j < 32; j += 8) {
        const int n = ty + j;
        Bt[(long)(n0 + n) * KB_ + k0 + tx] =
            __half_as_ushort(__float2half_rn(t[tx][n]));
    }
}

// crow[n] = sum_d lnb[d]*Wout[d*V+n] + bout[n]
__global__ __launch_bounds__(256) void k_crow(const float* __restrict__ lnb,
    const float* __restrict__ Wout, const float* __restrict__ bout,
    float* __restrict__ crow)
{
    const int n = blockIdx.x * 256 + threadIdx.x;
    float acc = 0.f;
    for (int d = 0; d < D_; d++) acc += lnb[d] * Wout[(long)d * V_ + n];
    crow[n] = acc + bout[n];
}

// v [R,D] fp32 -> vhT [Z][D][CH] fp16
__global__ __launch_bounds__(256) void k_convVT(const float* __restrict__ v,
                                                unsigned short* __restrict__ vhT)
{
    __shared__ float sm[32][33];
    const int d0 = blockIdx.x * 32, t0 = blockIdx.y * 32, z = blockIdx.z;
    const int tx = threadIdx.x & 31, ty = threadIdx.x >> 5;
#pragma unroll
    for (int j = 0; j < 32; j += 8)
        sm[ty + j][tx] = v[((long)z * CH_ + t0 + ty + j) * D_ + d0 + tx];
    __syncthreads();
#pragma unroll
    for (int j = 0; j < 32; j += 8)
        vhT[((long)z * D_ + d0 + ty + j) * CH_ + t0 + tx] =
            __half_as_ushort(__float2half_rn(sm[tx][ty + j]));
}

// ------------------------------ SIMT GEMM ----------------------------------
enum { EPI_STORE = 0, EPI_PHI, EPI_MASKH, EPI_MI };

template <int TRA, int TRB, int EPI>
__global__ __launch_bounds__(256) void gemm128(
    const float* __restrict__ A, const float* __restrict__ Bm, float* __restrict__ C,
    int M, int N, int Kd, long sA, long sB, long sC)
{
    constexpr int BM = 128, BN = 128, BK = 8, TM = 8, TN = 8;
    __shared__ __align__(16) float As[BK][BM];
    __shared__ __align__(16) float Bs[BK][BN];

    const int z = blockIdx.z;
    A  += (long)z * sA;
    Bm += (long)z * sB;
    C  += (long)z * sC;   // EPI_MASKH: sC in FLOAT units

    const int tid  = threadIdx.x;
    const int row0 = blockIdx.y * BM;
    const int col0 = blockIdx.x * BN;
    const int tRow = tid >> 4;
    const int tCol = tid & 15;

    float acc[TM][TN];
#pragma unroll
    for (int i = 0; i < TM; i++)
#pragma unroll
        for (int j = 0; j < TN; j++) acc[i][j] = 0.f;

    for (int k0 = 0; k0 < Kd; k0 += BK) {
        if (TRA == 0) {
            const int r = tid >> 1, c = (tid & 1) * 4;
            float4 a4 = *reinterpret_cast<const float4*>(A + (long)(row0 + r) * Kd + k0 + c);
            As[c + 0][r] = a4.x; As[c + 1][r] = a4.y;
            As[c + 2][r] = a4.z; As[c + 3][r] = a4.w;
        } else {
            const int r = tid >> 5, c = (tid & 31) * 4;
            *reinterpret_cast<float4*>(&As[r][c]) =
                *reinterpret_cast<const float4*>(A + (long)(k0 + r) * M + row0 + c);
        }
        if (TRB == 0) {
            const int r = tid >> 5, c = (tid & 31) * 4;
            *reinterpret_cast<float4*>(&Bs[r][c]) =
                *reinterpret_cast<const float4*>(Bm + (long)(k0 + r) * N + col0 + c);
        } else {
            const int r = tid >> 1, c = (tid & 1) * 4;
            float4 b4 = *reinterpret_cast<const float4*>(Bm + (long)(col0 + r) * Kd + k0 + c);
            Bs[c + 0][r] = b4.x; Bs[c + 1][r] = b4.y;
            Bs[c + 2][r] = b4.z; Bs[c + 3][r] = b4.w;
        }
        __syncthreads();

#pragma unroll
        for (int kk = 0; kk < BK; kk++) {
            float ra[TM], rb[TN];
            *reinterpret_cast<float4*>(ra)     = *reinterpret_cast<const float4*>(&As[kk][tRow * TM]);
            *reinterpret_cast<float4*>(ra + 4) = *reinterpret_cast<const float4*>(&As[kk][tRow * TM + 4]);
            *reinterpret_cast<float4*>(rb)     = *reinterpret_cast<const float4*>(&Bs[kk][tCol * TN]);
            *reinterpret_cast<float4*>(rb + 4) = *reinterpret_cast<const float4*>(&Bs[kk][tCol * TN + 4]);
#pragma unroll
            for (int i = 0; i < TM; i++)
#pragma unroll
                for (int j = 0; j < TN; j++) acc[i][j] += ra[i] * rb[j];
        }
        __syncthreads();
    }

#pragma unroll
    for (int i = 0; i < TM; i++) {
        const int gr = row0 + tRow * TM + i;
#pragma unroll
        for (int j = 0; j < TN; j++) {
            const int gc = col0 + tCol * TN + j;
            const long idx = (long)gr * N + gc;
            const float vv = acc[i][j];
            if (EPI == EPI_STORE)      C[idx] = vv;
            else if (EPI == EPI_PHI)   C[idx] = (vv > 0.f) ? vv + 1.f : expf(vv);
            else if (EPI == EPI_MASKH)
                reinterpret_cast<unsigned short*>(C)[idx] =
                    __half_as_ushort(__float2half_rn((gc <= gr) ? vv * SCALE_ : 0.f));
            else if (EPI == EPI_MI)    C[idx] = ((gr == gc) ? 1.f : 0.f) - SCALE_ * vv;
        }
    }
}

// ---------------- state scan: S_{c+1} = M_c S_c + T_c ----------------------
static constexpr int SREC_SM = (K_ * 129 + K_ * 32) * 4;  // 82432 B
__global__ __launch_bounds__(256) void k_srec(
    const float* __restrict__ Mmat, const float* __restrict__ Tmat,
    float* __restrict__ Sall)
{
    extern __shared__ float sm[];
    float* MT = sm;              // [128][129], MT[k][i] = M[i][k]
    float* Sb = sm + K_ * 129;   // [128][32]
    const int tid = threadIdx.x;
    const int j = tid & 31, i0 = (tid >> 5) * 16;
    const int d0 = blockIdx.x * 32, b = blockIdx.y;

    for (int idx = tid; idx < K_ * 32; idx += 256) Sb[idx] = 0.f;
    __syncthreads();

    for (int c = 0; c < NC_; c++) {
        const long zoff = (long)(b * NC_ + c) * K_;
        for (int r = tid >> 5; r < K_; r += 8)
            Sall[(zoff + r) * D_ + d0 + j] = Sb[r * 32 + j];
        if (c == NC_ - 1) break;
        __syncthreads();
        const float* Mb = Mmat + zoff * K_;
        for (int idx = tid; idx < K_ * K_; idx += 256) {
            const int i = idx >> 7, kk = idx & 127;
            MT[kk * 129 + i] = Mb[idx];
        }
        __syncthreads();
        float sn[16];
        const float* Tb = Tmat + zoff * D_;
#pragma unroll
        for (int r = 0; r < 16; r++) sn[r] = Tb[(long)(i0 + r) * D_ + d0 + j];
        for (int kk = 0; kk < K_; kk++) {
            const float sv = Sb[kk * 32 + j];
            const float* mrow = MT + kk * 129 + i0;
#pragma unroll
            for (int r = 0; r < 16; r++) sn[r] += mrow[r] * sv;
        }
        __syncthreads();
#pragma unroll
        for (int r = 0; r < 16; r++) Sb[(i0 + r) * 32 + j] = sn[r];
        __syncthreads();
    }
}

// ---------------- batched INTER: ov += s*(q@S) + byp@Vb + St ----------------
__global__ __launch_bounds__(256) void k_inter(
    const float* __restrict__ q, const float* __restrict__ Sall,
    float* __restrict__ ov,
    const float* __restrict__ bypArr, const float* __restrict__ Vb,
    const float* __restrict__ StArr)
{
    constexpr int BM = 128, BN = 128, BK = 8, TM = 8, TN = 8;
    __shared__ __align__(16) float As[BK][BM];
    __shared__ __align__(16) float Bs[BK][BN];

    const int z = blockIdx.z;
    const float* A  = q + (long)z * CH_ * K_;
    const float* Bm = Sall + (long)z * K_ * D_;
    float* C = ov + (long)z * CH_ * D_;

    const int tid  = threadIdx.x;
    const int row0 = blockIdx.y * BM;
    const int col0 = blockIdx.x * BN;
    const int tRow = tid >> 4;
    const int tCol = tid & 15;

    float acc[TM][TN];
#pragma unroll
    for (int i = 0; i < TM; i++)
#pragma unroll
        for (int j = 0; j < TN; j++) acc[i][j] = 0.f;

    for (int k0 = 0; k0 < K_; k0 += BK) {
        {
            const int r = tid >> 1, c = (tid & 1) * 4;
            float4 a4 = *reinterpret_cast<const float4*>(A + (long)(row0 + r) * K_ + k0 + c);
            As[c + 0][r] = a4.x; As[c + 1][r] = a4.y;
            As[c + 2][r] = a4.z; As[c + 3][r] = a4.w;
        }
        {
            const int r = tid >> 5, c = (tid & 31) * 4;
            *reinterpret_cast<float4*>(&Bs[r][c]) =
                *reinterpret_cast<const float4*>(Bm + (long)(k0 + r) * D_ + col0 + c);
        }
        __syncthreads();
#pragma unroll
        for (int kk = 0; kk < BK; kk++) {
            float ra[TM], rb[TN];
            *reinterpret_cast<float4*>(ra)     = *reinterpret_cast<const float4*>(&As[kk][tRow * TM]);
            *reinterpret_cast<float4*>(ra + 4) = *reinterpret_cast<const float4*>(&As[kk][tRow * TM + 4]);
            *reinterpret_cast<float4*>(rb)     = *reinterpret_cast<const float4*>(&Bs[kk][tCol * TN]);
            *reinterpret_cast<float4*>(rb + 4) = *reinterpret_cast<const float4*>(&Bs[kk][tCol * TN + 4]);
#pragma unroll
            for (int i = 0; i < TM; i++)
#pragma unroll
                for (int j = 0; j < TN; j++) acc[i][j] += ra[i] * rb[j];
        }
        __syncthreads();
    }

    float addc[TN];
#pragma unroll
    for (int j = 0; j < TN; j++) {
        const int gc = col0 + tCol * TN + j;
        float bv = 0.f;
#pragma unroll
        for (int r = 0; r < KR_; r++) bv += bypArr[z * KR_ + r] * Vb[r * D_ + gc];
        addc[j] = bv + StArr[(long)z * D_ + gc];
    }
#pragma unroll
    for (int i = 0; i < TM; i++) {
        const int gr = row0 + tRow * TM + i;
#pragma unroll
        for (int j = 0; j < TN; j++) {
            const int gc = col0 + tCol * TN + j;
            C[(long)gr * D_ + gc] += acc[i][j] * SCALE_ + addc[j];
        }
    }
}

// --------------------------- small kernels ---------------------------------
__global__ void k_pack(const float* __restrict__ Wq, const float* __restrict__ Wk,
                       float* __restrict__ Wqk)
{
    const int i = blockIdx.x * 256 + threadIdx.x;
    Wqk[i] = Wq[i];
    Wqk[D_ * K_ + i] = Wk[i];
}

__global__ __launch_bounds__(256) void k_embed(const int* __restrict__ x,
    const float* __restrict__ emb, float* __restrict__ ctx,
    unsigned short* __restrict__ ctxh)
{
    const int row = blockIdx.x;
    const int b = row / S_, s = row % S_;
    const int tid = threadIdx.x;
    float acc[4] = {0.f, 0.f, 0.f, 0.f};
    for (int off = 0; off < LC_; off++) {
        const int sp = s - off;
        if (sp < 0) break;
        const float* er = emb + (long)x[b * S_ + sp] * D_;
#pragma unroll
        for (int j = 0; j < 4; j++) acc[j] += er[tid + j * 256];
    }
    float* cr = ctx + (long)row * D_;
    unsigned short* ch = ctxh + (long)row * D_;
#pragma unroll
    for (int j = 0; j < 4; j++) {
        cr[tid + j * 256] = acc[j];
        ch[tid + j * 256] = __half_as_ushort(__float2half_rn(acc[j]));
    }
}

__global__ __launch_bounds__(256) void k_xmean(const float* __restrict__ ctx,
                                               float* __restrict__ xm)
{
    const int b = blockIdx.x, c = blockIdx.y, seg = blockIdx.z;
    const int tid = threadIdx.x;
    const int d = seg * 128 + (tid & 127);
    const int half = tid >> 7;
    const float* base = ctx + ((long)b * S_ + (long)c * CH_ + half * 128) * D_;
    float s = 0.f;
    for (int i = 0; i < 128; i++) s += base[(long)i * D_ + d];
    __shared__ float red[256];
    red[tid] = s;
    __syncthreads();
    if (half == 0)
        xm[((long)b * NC_ + c) * D_ + d] = (red[tid] + red[tid + 128]) * (1.0f / CH_);
}

__global__ __launch_bounds__(256) void k_scan(const float* __restrict__ xm,
    const float* __restrict__ Ub, float* __restrict__ bypArr, float* __restrict__ StArr)
{
    const int b = blockIdx.x, tid = threadIdx.x;
    __shared__ float part[KR_ * 256];
    float stp[4] = {0.f, 0.f, 0.f, 0.f};
#pragma unroll
    for (int j = 0; j < 4; j++) StArr[(long)(b * NC_) * D_ + tid + j * 256] = 0.f;
    if (tid < KR_) bypArr[(b * NC_) * KR_ + tid] = 0.f;

    for (int c = 1; c < NC_; c++) {
        const float* xp = xm + ((long)b * NC_ + (c - 1)) * D_;
        float pr[KR_];
#pragma unroll
        for (int r = 0; r < KR_; r++) pr[r] = 0.f;
#pragma unroll
        for (int j = 0; j < 4; j++) {
            const int d = tid + j * 256;
            const float xv = xp[d];
            stp[j] = LAM_ * stp[j] + (1.f - LAM_) * xv;
            StArr[(long)(b * NC_ + c) * D_ + d] = stp[j];
#pragma unroll
            for (int r = 0; r < KR_; r++) pr[r] += xv * Ub[d * KR_ + r];
        }
#pragma unroll
        for (int r = 0; r < KR_; r++) part[r * 256 + tid] = pr[r];
        __syncthreads();
        for (int st = 128; st > 0; st >>= 1) {
            if (tid < st)
#pragma unroll
                for (int r = 0; r < KR_; r++) part[r * 256 + tid] += part[r * 256 + tid + st];
            __syncthreads();
        }
        if (tid < KR_) bypArr[(b * NC_ + c) * KR_ + tid] = part[tid * 256];
        __syncthreads();
    }
}

__global__ __launch_bounds__(256) void k_rowscale_h16(const float* __restrict__ ov,
    unsigned short* __restrict__ ovh, float* __restrict__ alpha)
{
    const int row = blockIdx.x, tid = threadIdx.x;
    const float* r = ov + (long)row * D_;
    float v[4]; float mx = 0.f;
#pragma unroll
    for (int j = 0; j < 4; j++) { v[j] = r[tid + j * 256]; mx = fmaxf(mx, fabsf(v[j])); }
    __shared__ float red[256];
    red[tid] = mx; __syncthreads();
    for (int st = 128; st > 0; st >>= 1) {
        if (tid < st) red[tid] = fmaxf(red[tid], red[tid + st]);
        __syncthreads();
    }
    const float a = fmaxf(red[0], 1e-30f);
    if (tid == 0) alpha[row] = a;
    const float inv = 1.0f / a;
    unsigned short* o = ovh + (long)row * D_;
#pragma unroll
    for (int j = 0; j < 4; j++)
        o[tid + j * 256] = __half_as_ushort(__float2half_rn(v[j] * inv));
}

// LayerNorm reconstructing reference overflow behavior; flags saturated rows
__global__ __launch_bounds__(256) void k_ln_alpha(const float* __restrict__ h,
    const float* __restrict__ alpha,
    const float* __restrict__ g, const float* __restrict__ bta,
    unsigned short* __restrict__ Aout, int* __restrict__ sat)
{
    const int row = blockIdx.x, tid = threadIdx.x;
    const float a = alpha[row];
    const float* hr = h + (long)row * D_;
    float v[4]; float s = 0.f;
#pragma unroll
    for (int j = 0; j < 4; j++) { v[j] = hr[tid + j * 256]; s += v[j]; }
    __shared__ float red[256];
    red[tid] = s; __syncthreads();
    for (int st = 128; st > 0; st >>= 1) { if (tid < st) red[tid] += red[tid + st]; __syncthreads(); }
    const float mu = red[0] * (1.f / D_);
    __syncthreads();
    float dref[4]; float s2 = 0.f;
#pragma unroll
    for (int j = 0; j < 4; j++) {
        dref[j] = a * (v[j] - mu);
        s2 += dref[j] * dref[j];            // overflows to inf like the reference
    }
    red[tid] = s2; __syncthreads();
    for (int st = 128; st > 0; st >>= 1) { if (tid < st) red[tid] += red[tid + st]; __syncthreads(); }
    const float inv = rsqrtf(red[0] * (1.f / D_) + 1e-5f);   // inf -> 0
    if (tid == 0) sat[row] = (inv == 0.f) ? 1 : 0;
    unsigned short* ar = Aout + (long)row * KB_;
#pragma unroll
    for (int j = 0; j < 4; j++) {
        const int c = tid + j * 256;
        const float y = dref[j] * inv * g[c] + bta[c];
        ar[c] = __half_as_ushort(__float2half_rn(y));
    }
}

// ------------------------------- launch ------------------------------------
extern "C" void kernel_launch(void* const* d_in, const int* in_sizes, int n_in,
                              void* d_out, int out_size)
{
    (void)in_sizes; (void)n_in; (void)out_size;
    const int*   x    = (const int*)  d_in[0];
    const float* emb  = (const float*)d_in[1];
    const float* Wq   = (const float*)d_in[2];
    const float* Wk   = (const float*)d_in[3];
    const float* Wv   = (const float*)d_in[4];
    const float* Wo   = (const float*)d_in[5];
    const float* Ub   = (const float*)d_in[6];
    const float* Vb   = (const float*)d_in[7];
    const float* lng  = (const float*)d_in[8];
    const float* lnb  = (const float*)d_in[9];
    const float* Wout = (const float*)d_in[10];
    const float* bout = (const float*)d_in[11];
    float* outp = (float*)d_out;

    float *ctx, *qk, *v, *ov, *h, *Mm, *Tm, *Sall, *xm, *bypArr, *StArr, *alpha, *crow, *Wqk;
    int* sat;
    unsigned short *ctxh, *ovh, *Ahf, *Wvt, *Wot, *Bhf, *ath, *vhT;
    cudaGetSymbolAddress((void**)&ctx,    g_ctx);
    cudaGetSymbolAddress((void**)&qk,     g_qk);
    cudaGetSymbolAddress((void**)&v,      g_v);
    cudaGetSymbolAddress((void**)&ov,     g_out);
    cudaGetSymbolAddress((void**)&h,      g_h);
    cudaGetSymbolAddress((void**)&Mm,     g_Mmat);
    cudaGetSymbolAddress((void**)&Tm,     g_Tmat);
    cudaGetSymbolAddress((void**)&Sall,   g_Sall);
    cudaGetSymbolAddress((void**)&xm,     g_xm);
    cudaGetSymbolAddress((void**)&bypArr, g_bypArr);
    cudaGetSymbolAddress((void**)&StArr,  g_StArr);
    cudaGetSymbolAddress((void**)&alpha,  g_alpha);
    cudaGetSymbolAddress((void**)&crow,   g_crow);
    cudaGetSymbolAddress((void**)&sat,    g_sat);
    cudaGetSymbolAddress((void**)&Wqk,    g_Wqk);
    cudaGetSymbolAddress((void**)&ctxh,   g_ctxh);
    cudaGetSymbolAddress((void**)&ovh,    g_ovh);
    cudaGetSymbolAddress((void**)&Ahf,    g_Ahf);
    cudaGetSymbolAddress((void**)&Wvt,    g_Wvt);
    cudaGetSymbolAddress((void**)&Wot,    g_Wot);
    cudaGetSymbolAddress((void**)&Bhf,    g_Bhf);
    cudaGetSymbolAddress((void**)&ath,    g_ath);
    cudaGetSymbolAddress((void**)&vhT,    g_vhT);

    float* q = qk;
    float* k = qk + (long)R_ * K_;

    cudaFuncSetAttribute(hgemm<1024, true, true>,
                         cudaFuncAttributeMaxDynamicSharedMemorySize, GSM);
    cudaFuncSetAttribute(hgemm<1024, false, false>,
                         cudaFuncAttributeMaxDynamicSharedMemorySize, GSM);
    cudaFuncSetAttribute(hgemm<256, false, false>,
                         cudaFuncAttributeMaxDynamicSharedMemorySize, GSM);
    cudaFuncSetAttribute(k_srec,
                         cudaFuncAttributeMaxDynamicSharedMemorySize, SREC_SM);

    // weight conversions + constant saturated-row logits (independent)
    k_convB<<<dim3(V_ / 32, D_ / 32), 256>>>(Wout, Bhf, V_);
    k_convB<<<dim3(D_ / 32, D_ / 32), 256>>>(Wv, Wvt, D_);
    k_convB<<<dim3(D_ / 32, D_ / 32), 256>>>(Wo, Wot, D_);
    k_pack<<<D_ * K_ / 256, 256>>>(Wq, Wk, Wqk);
    k_crow<<<V_ / 256, 256>>>(lnb, Wout, bout, crow);

    // embedding + causal local-context sum (fp32 + fp16)
    k_embed<<<R_, 256>>>(x, emb, ctx, ctxh);

    // carry stats
    k_xmean<<<dim3(B_, NC_, 8), 256>>>(ctx, xm);
    k_scan<<<B_, 256>>>(xm, Ub, bypArr, StArr);

    // projections: Q+K merged (fp32, z=2); V fp16 tensor
    gemm128<0,0,EPI_PHI><<<dim3(1, R_ / 128, 2), 256>>>(
        ctx, Wqk, qk, R_, K_, D_, 0, (long)D_ * K_, (long)R_ * K_);
    hgemm<1024,false,false><<<dim3(R_ / GBM, D_ / GBN), 256, GSM>>>(
        ctxh, Wvt, nullptr, v, D_, 0, 0, 0, nullptr, nullptr);
    k_convVT<<<dim3(D_ / 32, CH_ / 32, Z_), 256>>>(v, vhT);

    // intra-chunk attention: masked QK^T (fp16 out), then fp16 at@v
    gemm128<0,1,EPI_MASKH><<<dim3(CH_ / 128, CH_ / 128, Z_), 256>>>(
        q, k, (float*)ath, CH_, CH_, K_,
        (long)CH_ * K_, (long)CH_ * K_, (long)(CH_ * CH_ / 2));
    hgemm<256,false,false><<<dim3(CH_ / GBM, D_ / GBN, Z_), 256, GSM>>>(
        ath, vhT, nullptr, ov, D_,
        (long)CH_ * CH_, (long)D_ * CH_, (long)CH_ * D_, nullptr, nullptr);

    // recurrence as linear scan
    gemm128<1,0,EPI_MI><<<dim3(1, 1, Z_), 256>>>(
        k, k, Mm, K_, K_, CH_, (long)CH_ * K_, (long)CH_ * K_, (long)K_ * K_);
    gemm128<1,0,EPI_STORE><<<dim3(D_ / 128, 1, Z_), 256>>>(
        k, v, Tm, K_, D_, CH_, (long)CH_ * K_, (long)CH_ * D_, (long)K_ * D_);
    k_srec<<<dim3(D_ / 32, B_), 256, SREC_SM>>>(Mm, Tm, Sall);
    k_inter<<<dim3(D_ / 128, CH_ / 128, Z_), 256>>>(q, Sall, ov, bypArr, Vb, StArr);

    // row-scale ov -> fp16 (+alpha), Wo (fp16), LN w/ saturation+flags, vocab
    k_rowscale_h16<<<R_, 256>>>(ov, ovh, alpha);
    hgemm<1024,false,false><<<dim3(R_ / GBM, D_ / GBN), 256, GSM>>>(
        ovh, Wot, nullptr, h, D_, 0, 0, 0, nullptr, nullptr);
    k_ln_alpha<<<R_, 256>>>(h, alpha, lng, lnb, Ahf, sat);
    hgemm<1024,true,true><<<dim3(R_ / GBM, V_ / GBN), 256, GSM>>>(
        Ahf, Bhf, bout, outp, V_, 0, 0, 0, sat, crow);
}